// round 1
// baseline (speedup 1.0000x reference)
#include <cuda_runtime.h>
#include <math.h>

#define B_    2
#define S_    2048
#define HID   1024
#define NH    16
#define NKV   4
#define HD    64
#define REP   (NH / NKV)          // 4
#define THETA 100000.0

// ---------------------------------------------------------------------------
// Scratch (device globals — no allocation allowed in kernel_launch)
// ---------------------------------------------------------------------------
__device__ float g_q[(size_t)B_ * S_ * NH * HD];     // 16 MB  [b,s,h,d]
__device__ float g_k[(size_t)B_ * S_ * NKV * HD];    //  4 MB  [b,s,kh,d]
__device__ float g_v[(size_t)B_ * S_ * NKV * HD];    //  4 MB  [b,s,kh,d]
__device__ float g_attn[(size_t)B_ * S_ * NH * HD];  // 16 MB  [b,s,h,d]
__device__ float g_cos[S_ * 32];
__device__ float g_sin[S_ * 32];

// ---------------------------------------------------------------------------
// RoPE table: cos/sin(t * theta^(-j/32)), j = 0..31, computed in fp64 to
// match numpy's float64 outer-product before the float32 cast.
// ---------------------------------------------------------------------------
__global__ void rope_table_kernel() {
    int idx = blockIdx.x * blockDim.x + threadIdx.x;
    if (idx >= S_ * 32) return;
    int t = idx >> 5;
    int j = idx & 31;
    double inv = pow((double)THETA, -(double)j / 32.0);
    float ang = (float)((double)t * inv);   // ref casts f to float32 before cos
    g_cos[idx] = (float)cos((double)ang);
    g_sin[idx] = (float)sin((double)ang);
}

// ---------------------------------------------------------------------------
// RoPE apply (interleaved pairs, half-concat frequency indexing):
//   out[2i]   = x[2i]  *cos[(2i)%32]   - x[2i+1]*sin[(2i)%32]
//   out[2i+1] = x[2i+1]*cos[(2i+1)%32] + x[2i]  *sin[(2i+1)%32]
// ---------------------------------------------------------------------------
__global__ void rope_apply_kernel() {
    const int totq = B_ * S_ * NH * (HD / 2);
    const int totk = B_ * S_ * NKV * (HD / 2);
    int idx = blockIdx.x * blockDim.x + threadIdx.x;
    if (idx >= totq + totk) return;

    float* base;
    int pos, p;
    if (idx < totq) {
        p = idx & 31;
        int rem = idx >> 5;               // (b*S+s)*NH + h
        pos = (rem / NH) % S_;
        base = g_q + (size_t)rem * HD;
    } else {
        int idx2 = idx - totq;
        p = idx2 & 31;
        int rem = idx2 >> 5;              // (b*S+s)*NKV + kh
        pos = (rem / NKV) % S_;
        base = g_k + (size_t)rem * HD;
    }
    int d0 = 2 * p, d1 = 2 * p + 1;
    int j0 = d0 & 31, j1 = d1 & 31;
    float c0 = g_cos[pos * 32 + j0], s0 = g_sin[pos * 32 + j0];
    float c1 = g_cos[pos * 32 + j1], s1 = g_sin[pos * 32 + j1];
    float x0 = base[d0], x1 = base[d1];
    base[d0] = x0 * c0 - x1 * s0;
    base[d1] = x1 * c1 + x0 * s1;
}

// ---------------------------------------------------------------------------
// Tiled SGEMM: C[M,N] = A[M,K] @ B[K,N] + bias[N].
// 128x128 block tile, BK=8, 256 threads, 8x8 per-thread micro-tile.
// Assumes M%128==0, N%128==0, K%8==0 (true for all calls here).
// ---------------------------------------------------------------------------
__global__ __launch_bounds__(256) void sgemm_bias_kernel(
    const float* __restrict__ A, const float* __restrict__ Bm,
    const float* __restrict__ bias, float* __restrict__ C,
    int M, int N, int K)
{
    constexpr int BM = 128, BN = 128, BK = 8, TM = 8, TN = 8;
    __shared__ float As[BK][BM];
    __shared__ float Bs[BK][BN];

    const int tid = threadIdx.x;
    const int tr = tid / (BN / TN);       // 0..15
    const int tc = tid % (BN / TN);       // 0..15
    const int m0 = blockIdx.y * BM;
    const int n0 = blockIdx.x * BN;

    const int aRow = tid >> 1;            // 0..127
    const int aCol = (tid & 1) * 4;       // 0 or 4
    const int bRow = tid >> 5;            // 0..7
    const int bCol = (tid & 31) * 4;      // 0..124

    float acc[TM][TN];
    #pragma unroll
    for (int i = 0; i < TM; i++)
        #pragma unroll
        for (int j = 0; j < TN; j++) acc[i][j] = 0.f;

    for (int k0 = 0; k0 < K; k0 += BK) {
        float4 av = *reinterpret_cast<const float4*>(&A[(size_t)(m0 + aRow) * K + k0 + aCol]);
        As[aCol + 0][aRow] = av.x;
        As[aCol + 1][aRow] = av.y;
        As[aCol + 2][aRow] = av.z;
        As[aCol + 3][aRow] = av.w;
        float4 bv = *reinterpret_cast<const float4*>(&Bm[(size_t)(k0 + bRow) * N + n0 + bCol]);
        *reinterpret_cast<float4*>(&Bs[bRow][bCol]) = bv;
        __syncthreads();

        #pragma unroll
        for (int kk = 0; kk < BK; kk++) {
            float ra[TM], rb[TN];
            #pragma unroll
            for (int i = 0; i < TM; i += 4)
                *reinterpret_cast<float4*>(&ra[i]) =
                    *reinterpret_cast<const float4*>(&As[kk][tr * TM + i]);
            #pragma unroll
            for (int j = 0; j < TN; j += 4)
                *reinterpret_cast<float4*>(&rb[j]) =
                    *reinterpret_cast<const float4*>(&Bs[kk][tc * TN + j]);
            #pragma unroll
            for (int i = 0; i < TM; i++)
                #pragma unroll
                for (int j = 0; j < TN; j++)
                    acc[i][j] += ra[i] * rb[j];
        }
        __syncthreads();
    }

    #pragma unroll
    for (int i = 0; i < TM; i++) {
        #pragma unroll
        for (int j = 0; j < TN; j += 4) {
            int n = n0 + tc * TN + j;
            float4 o;
            o.x = acc[i][j + 0] + bias[n + 0];
            o.y = acc[i][j + 1] + bias[n + 1];
            o.z = acc[i][j + 2] + bias[n + 2];
            o.w = acc[i][j + 3] + bias[n + 3];
            *reinterpret_cast<float4*>(&C[(size_t)(m0 + tr * TM + i) * N + n]) = o;
        }
    }
}

// ---------------------------------------------------------------------------
// Flash-attention (fp32): one block per (q-tile of 64, head, batch).
// 256 threads, 16x16 layout; each thread owns a 4x4 score / output micro-tile.
// Online softmax; causal key tiles beyond the q-tile are skipped (their
// softmax weights are exactly 0 in the reference too).
// ---------------------------------------------------------------------------
__global__ __launch_bounds__(256) void attn_kernel(const int* __restrict__ amask) {
    extern __shared__ float sm[];
    float* Qs = sm;                 // 64 x 65
    float* Ks = Qs + 64 * 65;       // 64 x 65
    float* Vs = Ks + 64 * 65;       // 64 x 65
    float* Ps = Vs + 64 * 65;       // 64 x 65

    const int qi = blockIdx.x, h = blockIdx.y, b = blockIdx.z;
    const int tid = threadIdx.x;
    const int ty = tid >> 4, tx = tid & 15;
    const int r0 = ty * 4, c0 = tx * 4;
    const int q0 = qi * 64;
    const int kvh = h / REP;

    // Load Q tile
    const float* qbase = g_q + ((size_t)(b * S_ + q0) * NH + h) * HD;
    #pragma unroll
    for (int t = 0; t < 16; t++) {
        int idx = t * 256 + tid;
        int row = idx >> 6, col = idx & 63;
        Qs[row * 65 + col] = qbase[(size_t)row * NH * HD + col];
    }

    float m[4], l[4], acc[4][4];
    #pragma unroll
    for (int i = 0; i < 4; i++) {
        m[i] = -INFINITY; l[i] = 0.f;
        #pragma unroll
        for (int j = 0; j < 4; j++) acc[i][j] = 0.f;
    }
    __syncthreads();

    const int nkt = qi + 1;    // causal: only key tiles with k0 <= q_end
    for (int kt = 0; kt < nkt; kt++) {
        const int k0 = kt * 64;
        const float* kbase = g_k + ((size_t)(b * S_ + k0) * NKV + kvh) * HD;
        const float* vbase = g_v + ((size_t)(b * S_ + k0) * NKV + kvh) * HD;
        #pragma unroll
        for (int t = 0; t < 16; t++) {
            int idx = t * 256 + tid;
            int row = idx >> 6, col = idx & 63;
            Ks[row * 65 + col] = kbase[(size_t)row * NKV * HD + col];
            Vs[row * 65 + col] = vbase[(size_t)row * NKV * HD + col];
        }
        __syncthreads();

        // S = Q K^T (4x4 per thread)
        float s[4][4];
        #pragma unroll
        for (int i = 0; i < 4; i++)
            #pragma unroll
            for (int j = 0; j < 4; j++) s[i][j] = 0.f;
        for (int d = 0; d < 64; d++) {
            float qa[4], kb[4];
            #pragma unroll
            for (int i = 0; i < 4; i++) qa[i] = Qs[(r0 + i) * 65 + d];
            #pragma unroll
            for (int j = 0; j < 4; j++) kb[j] = Ks[(c0 + j) * 65 + d];
            #pragma unroll
            for (int i = 0; i < 4; i++)
                #pragma unroll
                for (int j = 0; j < 4; j++)
                    s[i][j] += qa[i] * kb[j];
        }

        // scale + causal + key mask
        #pragma unroll
        for (int j = 0; j < 4; j++) {
            int kg = k0 + c0 + j;
            bool kok = (amask[b * S_ + kg] != 0);
            #pragma unroll
            for (int i = 0; i < 4; i++) {
                int qg = q0 + r0 + i;
                float v = s[i][j] * 0.125f;
                if (kg > qg || !kok) v = -1e30f;
                s[i][j] = v;
            }
        }

        // row max over the key tile (reduce across the 16 lanes of the row)
        float tmax[4];
        #pragma unroll
        for (int i = 0; i < 4; i++)
            tmax[i] = fmaxf(fmaxf(s[i][0], s[i][1]), fmaxf(s[i][2], s[i][3]));
        #pragma unroll
        for (int off = 1; off < 16; off <<= 1)
            #pragma unroll
            for (int i = 0; i < 4; i++)
                tmax[i] = fmaxf(tmax[i], __shfl_xor_sync(0xffffffffu, tmax[i], off));

        float psum[4];
        #pragma unroll
        for (int i = 0; i < 4; i++) {
            float mn = fmaxf(m[i], tmax[i]);
            float corr = expf(m[i] - mn);
            psum[i] = 0.f;
            #pragma unroll
            for (int j = 0; j < 4; j++) {
                float p = expf(s[i][j] - mn);
                Ps[(r0 + i) * 65 + c0 + j] = p;
                psum[i] += p;
            }
            l[i] *= corr;
            #pragma unroll
            for (int j = 0; j < 4; j++) acc[i][j] *= corr;
            m[i] = mn;
        }
        #pragma unroll
        for (int off = 1; off < 16; off <<= 1)
            #pragma unroll
            for (int i = 0; i < 4; i++)
                psum[i] += __shfl_xor_sync(0xffffffffu, psum[i], off);
        #pragma unroll
        for (int i = 0; i < 4; i++) l[i] += psum[i];

        __syncthreads();

        // O += P V
        for (int k = 0; k < 64; k++) {
            float pv[4], vv[4];
            #pragma unroll
            for (int i = 0; i < 4; i++) pv[i] = Ps[(r0 + i) * 65 + k];
            #pragma unroll
            for (int j = 0; j < 4; j++) vv[j] = Vs[k * 65 + c0 + j];
            #pragma unroll
            for (int i = 0; i < 4; i++)
                #pragma unroll
                for (int j = 0; j < 4; j++)
                    acc[i][j] += pv[i] * vv[j];
        }
        __syncthreads();   // protect Ks/Vs/Ps before next tile's loads
    }

    float* obase = g_attn + ((size_t)(b * S_ + q0) * NH + h) * HD;
    #pragma unroll
    for (int i = 0; i < 4; i++) {
        float inv = 1.f / l[i];
        #pragma unroll
        for (int j = 0; j < 4; j++)
            obase[(size_t)(r0 + i) * NH * HD + c0 + j] = acc[i][j] * inv;
    }
}

// ---------------------------------------------------------------------------
// kernel_launch
// ---------------------------------------------------------------------------
extern "C" void kernel_launch(void* const* d_in, const int* in_sizes, int n_in,
                              void* d_out, int out_size)
{
    const float* hs    = (const float*)d_in[0];
    const int*   amask = (const int*)  d_in[1];
    const float* Wq    = (const float*)d_in[2];
    const float* bq    = (const float*)d_in[3];
    const float* Wk    = (const float*)d_in[4];
    const float* bk    = (const float*)d_in[5];
    const float* Wv    = (const float*)d_in[6];
    const float* bv    = (const float*)d_in[7];
    const float* Wo    = (const float*)d_in[8];
    const float* bo    = (const float*)d_in[9];
    float* out = (float*)d_out;

    float *qp, *kp, *vp, *ap;
    cudaGetSymbolAddress((void**)&qp, g_q);
    cudaGetSymbolAddress((void**)&kp, g_k);
    cudaGetSymbolAddress((void**)&vp, g_v);
    cudaGetSymbolAddress((void**)&ap, g_attn);

    const int M = B_ * S_;   // 4096
    dim3 blk(256);

    // QKV projections
    sgemm_bias_kernel<<<dim3(HID / 128, M / 128), blk>>>(hs, Wq, bq, qp, M, HID, HID);
    sgemm_bias_kernel<<<dim3((NKV * HD) / 128, M / 128), blk>>>(hs, Wk, bk, kp, M, NKV * HD, HID);
    sgemm_bias_kernel<<<dim3((NKV * HD) / 128, M / 128), blk>>>(hs, Wv, bv, vp, M, NKV * HD, HID);

    // RoPE
    rope_table_kernel<<<(S_ * 32 + 255) / 256, 256>>>();
    int tot = B_ * S_ * (NH + NKV) * (HD / 2);
    rope_apply_kernel<<<(tot + 255) / 256, 256>>>();

    // Attention
    size_t smem = 4 * 64 * 65 * sizeof(float);   // 66560 B
    cudaFuncSetAttribute(attn_kernel, cudaFuncAttributeMaxDynamicSharedMemorySize, (int)smem);
    attn_kernel<<<dim3(S_ / 64, NH, B_), 256, smem>>>(amask);

    // Output projection
    sgemm_bias_kernel<<<dim3(HID / 128, M / 128), blk>>>(ap, Wo, bo, out, M, HID, HID);
}

// round 3
// speedup vs baseline: 1.4415x; 1.4415x over previous
#include <cuda_runtime.h>
#include <cuda_bf16.h>
#include <cstdint>
#include <math.h>

#define B_    2
#define S_    2048
#define HID   1024
#define NH    16
#define NKV   4
#define HD    64
#define REP   (NH / NKV)
#define NCAT  1536            // 1024 (Q) + 256 (K) + 256 (V)
#define THETA 100000.0

// ---------------------------------------------------------------------------
// Scratch (device globals)
// ---------------------------------------------------------------------------
__device__ float g_qkv[(size_t)B_ * S_ * NCAT];      // [4096, 1536] q|k|v
__device__ float g_attn[(size_t)B_ * S_ * HID];      // [4096, 1024]
__device__ float g_cos[S_ * 32];
__device__ float g_sin[S_ * 32];
__device__ float g_bias[NCAT];

__device__ __nv_bfloat16 g_hs_hi[(size_t)B_ * S_ * HID];
__device__ __nv_bfloat16 g_hs_lo[(size_t)B_ * S_ * HID];
__device__ __nv_bfloat16 g_at_hi[(size_t)B_ * S_ * HID];
__device__ __nv_bfloat16 g_at_lo[(size_t)B_ * S_ * HID];
__device__ __nv_bfloat16 g_Wc_hi[NCAT * HID];        // [1536,1024] rows=out col
__device__ __nv_bfloat16 g_Wc_lo[NCAT * HID];
__device__ __nv_bfloat16 g_Wo_hi[HID * HID];
__device__ __nv_bfloat16 g_Wo_lo[HID * HID];

// ---------------------------------------------------------------------------
// helpers
// ---------------------------------------------------------------------------
__device__ __forceinline__ uint32_t smem_u32(const void* p) {
    uint32_t a;
    asm("{ .reg .u64 t; cvta.to.shared.u64 t, %1; cvt.u32.u64 %0, t; }" : "=r"(a) : "l"(p));
    return a;
}
#define LDSM_X4(r0, r1, r2, r3, addr) \
    asm volatile("ldmatrix.sync.aligned.m8n8.x4.shared.b16 {%0,%1,%2,%3}, [%4];" \
        : "=r"(r0), "=r"(r1), "=r"(r2), "=r"(r3) : "r"(addr))

__device__ __forceinline__ void mma_bf16(float* d, const uint32_t* a,
                                         uint32_t b0, uint32_t b1) {
    asm volatile(
        "mma.sync.aligned.m16n8k16.row.col.f32.bf16.bf16.f32 "
        "{%0,%1,%2,%3}, {%4,%5,%6,%7}, {%8,%9}, {%0,%1,%2,%3};"
        : "+f"(d[0]), "+f"(d[1]), "+f"(d[2]), "+f"(d[3])
        : "r"(a[0]), "r"(a[1]), "r"(a[2]), "r"(a[3]), "r"(b0), "r"(b1));
}

// ---------------------------------------------------------------------------
// Weight prep: transpose + hi/lo split.  z=0:Wq z=1:Wk z=2:Wv z=3:Wo.
// ---------------------------------------------------------------------------
__global__ void prep_weights_kernel(const float* __restrict__ Wq,
                                    const float* __restrict__ Wk,
                                    const float* __restrict__ Wv,
                                    const float* __restrict__ Wo) {
    __shared__ float t[32][33];
    int z = blockIdx.z;
    const float* W;
    __nv_bfloat16 *hi, *lo;
    int N, rowoff;
    if (z == 0)      { W = Wq; N = HID; rowoff = 0;    hi = g_Wc_hi; lo = g_Wc_lo; }
    else if (z == 1) { W = Wk; N = 256; rowoff = 1024; hi = g_Wc_hi; lo = g_Wc_lo; }
    else if (z == 2) { W = Wv; N = 256; rowoff = 1280; hi = g_Wc_hi; lo = g_Wc_lo; }
    else             { W = Wo; N = HID; rowoff = 0;    hi = g_Wo_hi; lo = g_Wo_lo; }

    int n0 = blockIdx.x * 32, k0 = blockIdx.y * 32;
    if (n0 >= N) return;
    int x = threadIdx.x, y = threadIdx.y;   // (32, 8)
    #pragma unroll
    for (int yy = y; yy < 32; yy += 8)
        t[yy][x] = W[(size_t)(k0 + yy) * N + n0 + x];
    __syncthreads();
    #pragma unroll
    for (int yy = y; yy < 32; yy += 8) {
        float v = t[x][yy];                 // W[k0+x][n0+yy]
        __nv_bfloat16 h = __float2bfloat16(v);
        size_t o = (size_t)(rowoff + n0 + yy) * HID + k0 + x;
        hi[o] = h;
        lo[o] = __float2bfloat16(v - __bfloat162float(h));
    }
}

// ---------------------------------------------------------------------------
// hi/lo split (elementwise)
// ---------------------------------------------------------------------------
__global__ void split_kernel(const float* __restrict__ in,
                             __nv_bfloat16* __restrict__ hi,
                             __nv_bfloat16* __restrict__ lo, int n) {
    int i = blockIdx.x * blockDim.x + threadIdx.x;
    if (i >= n) return;
    float v = in[i];
    __nv_bfloat16 h = __float2bfloat16(v);
    hi[i] = h;
    lo[i] = __float2bfloat16(v - __bfloat162float(h));
}

// ---------------------------------------------------------------------------
// RoPE table + bias concat
// ---------------------------------------------------------------------------
__global__ void rope_table_kernel(const float* __restrict__ bq,
                                  const float* __restrict__ bk,
                                  const float* __restrict__ bv) {
    int idx = blockIdx.x * blockDim.x + threadIdx.x;
    if (idx < NCAT)
        g_bias[idx] = (idx < 1024) ? bq[idx] : (idx < 1280) ? bk[idx - 1024] : bv[idx - 1280];
    if (idx >= S_ * 32) return;
    int t = idx >> 5, j = idx & 31;
    double inv = exp2(-(double)j * 0.5190512648261507);   // log2(1e5)/32
    float ang = (float)((double)t * inv);
    float s, c;
    sincosf(ang, &s, &c);
    g_cos[idx] = c;
    g_sin[idx] = s;
}

// ---------------------------------------------------------------------------
// GEMM via mma.sync (bf16 hi/lo x3 passes): C[M,Ngrid] = A @ W^T + bias.
// A: [M, K] bf16 hi/lo, W: [N, K] bf16 hi/lo (K-major rows).
// Block 128x128, BK=32, 256 thr (8 warps, 2x4, each 64x32), double-buffered.
// ---------------------------------------------------------------------------
#define GEMM_SMEM (2 * 40960)

__global__ __launch_bounds__(256, 1) void gemm_mma_kernel(
    const __nv_bfloat16* __restrict__ Ahi, const __nv_bfloat16* __restrict__ Alo,
    const __nv_bfloat16* __restrict__ Whi, const __nv_bfloat16* __restrict__ Wlo,
    const float* __restrict__ bias, float* __restrict__ C, int ldc, int K)
{
    extern __shared__ char smx[];
    const int tid = threadIdx.x, lane = tid & 31, wid = tid >> 5;
    const int wm = wid & 1, wn = wid >> 1;
    const int m0 = blockIdx.y * 128, n0 = blockIdx.x * 128;
    const uint32_t sbase = smem_u32(smx);

    float acc[4][4][4];
    #pragma unroll
    for (int a = 0; a < 4; a++)
        #pragma unroll
        for (int b = 0; b < 4; b++)
            #pragma unroll
            for (int c = 0; c < 4; c++) acc[a][b][c] = 0.f;

    // stage layout: Ahi(10240) Alo(10240) Whi(10240) Wlo(10240); row stride 80B
    auto load_stage = [&](int ch, int s) {
        char* base = smx + s * 40960;
        int k0 = ch * 32;
        #pragma unroll
        for (int mat = 0; mat < 4; ++mat) {
            const __nv_bfloat16* p = (mat == 0) ? Ahi : (mat == 1) ? Alo
                                   : (mat == 2) ? Whi : Wlo;
            int rb = (mat < 2) ? m0 : n0;
            #pragma unroll
            for (int it = 0; it < 2; ++it) {
                int i = it * 256 + tid;
                int row = i >> 2, seg = i & 3;
                *reinterpret_cast<uint4*>(base + mat * 10240 + row * 80 + seg * 16) =
                    *reinterpret_cast<const uint4*>(p + (size_t)(rb + row) * K + k0 + seg * 8);
            }
        }
    };

    load_stage(0, 0);
    __syncthreads();

    const int NCH = K / 32;
    for (int ch = 0; ch < NCH; ++ch) {
        const int s = ch & 1;
        if (ch + 1 < NCH) load_stage(ch + 1, s ^ 1);

        const uint32_t b = sbase + s * 40960;
        const uint32_t aAhi = b, aAlo = b + 10240, aWhi = b + 20480, aWlo = b + 30720;

        #pragma unroll
        for (int ks = 0; ks < 2; ++ks) {
            uint32_t ah[4][4], al[4][4], bh[2][4], bl[2][4];
            const uint32_t coff = ks * 32 + ((lane >> 4) << 4);
            #pragma unroll
            for (int mi = 0; mi < 4; ++mi) {
                uint32_t ro = (uint32_t)(wm * 64 + mi * 16 + (lane & 15)) * 80 + coff;
                LDSM_X4(ah[mi][0], ah[mi][1], ah[mi][2], ah[mi][3], aAhi + ro);
                LDSM_X4(al[mi][0], al[mi][1], al[mi][2], al[mi][3], aAlo + ro);
            }
            #pragma unroll
            for (int g = 0; g < 2; ++g) {
                uint32_t ro = (uint32_t)(wn * 32 + g * 16 + (lane & 15)) * 80 + coff;
                LDSM_X4(bh[g][0], bh[g][1], bh[g][2], bh[g][3], aWhi + ro);
                LDSM_X4(bl[g][0], bl[g][1], bl[g][2], bl[g][3], aWlo + ro);
            }
            #pragma unroll
            for (int mi = 0; mi < 4; ++mi) {
                #pragma unroll
                for (int j = 0; j < 4; ++j) {
                    const int g = j >> 1, p = j & 1;
                    mma_bf16(acc[mi][j], ah[mi], bh[g][p], bh[g][p + 2]);
                    mma_bf16(acc[mi][j], ah[mi], bl[g][p], bl[g][p + 2]);
                    mma_bf16(acc[mi][j], al[mi], bh[g][p], bh[g][p + 2]);
                }
            }
        }
        __syncthreads();
    }

    // epilogue
    #pragma unroll
    for (int mi = 0; mi < 4; ++mi) {
        const int r = m0 + wm * 64 + mi * 16 + (lane >> 2);
        #pragma unroll
        for (int j = 0; j < 4; ++j) {
            const int col = n0 + wn * 32 + j * 8 + (lane & 3) * 2;
            const float b0 = bias[col], b1 = bias[col + 1];
            float2 v0 = make_float2(acc[mi][j][0] + b0, acc[mi][j][1] + b1);
            float2 v1 = make_float2(acc[mi][j][2] + b0, acc[mi][j][3] + b1);
            *reinterpret_cast<float2*>(C + (size_t)r * ldc + col) = v0;
            *reinterpret_cast<float2*>(C + (size_t)(r + 8) * ldc + col) = v1;
        }
    }
}

// ---------------------------------------------------------------------------
// RoPE apply on g_qkv (q cols 0-1023, k cols 1024-1279)
// ---------------------------------------------------------------------------
__global__ void rope_apply_kernel() {
    const int totq = B_ * S_ * NH * (HD / 2);
    const int totk = B_ * S_ * NKV * (HD / 2);
    int idx = blockIdx.x * blockDim.x + threadIdx.x;
    if (idx >= totq + totk) return;

    float* base;
    int pos, p;
    if (idx < totq) {
        p = idx & 31;
        int rem = idx >> 5;                  // (b*S+s)*NH + h
        int row = rem / NH, h = rem % NH;
        pos = row % S_;
        base = g_qkv + (size_t)row * NCAT + h * HD;
    } else {
        int idx2 = idx - totq;
        p = idx2 & 31;
        int rem = idx2 >> 5;                 // (b*S+s)*NKV + kh
        int row = rem / NKV, kh = rem % NKV;
        pos = row % S_;
        base = g_qkv + (size_t)row * NCAT + 1024 + kh * HD;
    }
    int d0 = 2 * p, d1 = 2 * p + 1;
    int j0 = d0 & 31, j1 = d1 & 31;
    float c0 = g_cos[pos * 32 + j0], s0 = g_sin[pos * 32 + j0];
    float c1 = g_cos[pos * 32 + j1], s1 = g_sin[pos * 32 + j1];
    float x0 = base[d0], x1 = base[d1];
    base[d0] = x0 * c0 - x1 * s0;
    base[d1] = x1 * c1 + x0 * s1;
}

// ---------------------------------------------------------------------------
// Flash-attention (fp32 scalar) reading strided q/k/v from g_qkv
// ---------------------------------------------------------------------------
__global__ __launch_bounds__(256) void attn_kernel(const int* __restrict__ amask) {
    extern __shared__ float sm[];
    float* Qs = sm;
    float* Ks = Qs + 64 * 65;
    float* Vs = Ks + 64 * 65;
    float* Ps = Vs + 64 * 65;

    const int qi = blockIdx.x, h = blockIdx.y, b = blockIdx.z;
    const int tid = threadIdx.x;
    const int ty = tid >> 4, tx = tid & 15;
    const int r0 = ty * 4, c0 = tx * 4;
    const int q0 = qi * 64;
    const int kvh = h / REP;

    const float* qbase = g_qkv + (size_t)(b * S_ + q0) * NCAT + h * HD;
    #pragma unroll
    for (int t = 0; t < 16; t++) {
        int idx = t * 256 + tid;
        int row = idx >> 6, col = idx & 63;
        Qs[row * 65 + col] = qbase[(size_t)row * NCAT + col];
    }

    float m[4], l[4], acc[4][4];
    #pragma unroll
    for (int i = 0; i < 4; i++) {
        m[i] = -INFINITY; l[i] = 0.f;
        #pragma unroll
        for (int j = 0; j < 4; j++) acc[i][j] = 0.f;
    }
    __syncthreads();

    const int nkt = qi + 1;
    for (int kt = 0; kt < nkt; kt++) {
        const int k0 = kt * 64;
        const float* kbase = g_qkv + (size_t)(b * S_ + k0) * NCAT + 1024 + kvh * HD;
        const float* vbase = g_qkv + (size_t)(b * S_ + k0) * NCAT + 1280 + kvh * HD;
        #pragma unroll
        for (int t = 0; t < 16; t++) {
            int idx = t * 256 + tid;
            int row = idx >> 6, col = idx & 63;
            Ks[row * 65 + col] = kbase[(size_t)row * NCAT + col];
            Vs[row * 65 + col] = vbase[(size_t)row * NCAT + col];
        }
        __syncthreads();

        float s[4][4];
        #pragma unroll
        for (int i = 0; i < 4; i++)
            #pragma unroll
            for (int j = 0; j < 4; j++) s[i][j] = 0.f;
        for (int d = 0; d < 64; d++) {
            float qa[4], kb[4];
            #pragma unroll
            for (int i = 0; i < 4; i++) qa[i] = Qs[(r0 + i) * 65 + d];
            #pragma unroll
            for (int j = 0; j < 4; j++) kb[j] = Ks[(c0 + j) * 65 + d];
            #pragma unroll
            for (int i = 0; i < 4; i++)
                #pragma unroll
                for (int j = 0; j < 4; j++)
                    s[i][j] += qa[i] * kb[j];
        }

        #pragma unroll
        for (int j = 0; j < 4; j++) {
            int kg = k0 + c0 + j;
            bool kok = (amask[b * S_ + kg] != 0);
            #pragma unroll
            for (int i = 0; i < 4; i++) {
                int qg = q0 + r0 + i;
                float v = s[i][j] * 0.125f;
                if (kg > qg || !kok) v = -1e30f;
                s[i][j] = v;
            }
        }

        float tmax[4];
        #pragma unroll
        for (int i = 0; i < 4; i++)
            tmax[i] = fmaxf(fmaxf(s[i][0], s[i][1]), fmaxf(s[i][2], s[i][3]));
        #pragma unroll
        for (int off = 1; off < 16; off <<= 1)
            #pragma unroll
            for (int i = 0; i < 4; i++)
                tmax[i] = fmaxf(tmax[i], __shfl_xor_sync(0xffffffffu, tmax[i], off));

        float psum[4];
        #pragma unroll
        for (int i = 0; i < 4; i++) {
            float mn = fmaxf(m[i], tmax[i]);
            float corr = expf(m[i] - mn);
            psum[i] = 0.f;
            #pragma unroll
            for (int j = 0; j < 4; j++) {
                float p = expf(s[i][j] - mn);
                Ps[(r0 + i) * 65 + c0 + j] = p;
                psum[i] += p;
            }
            l[i] *= corr;
            #pragma unroll
            for (int j = 0; j < 4; j++) acc[i][j] *= corr;
            m[i] = mn;
        }
        #pragma unroll
        for (int off = 1; off < 16; off <<= 1)
            #pragma unroll
            for (int i = 0; i < 4; i++)
                psum[i] += __shfl_xor_sync(0xffffffffu, psum[i], off);
        #pragma unroll
        for (int i = 0; i < 4; i++) l[i] += psum[i];

        __syncthreads();

        for (int k = 0; k < 64; k++) {
            float pv[4], vv[4];
            #pragma unroll
            for (int i = 0; i < 4; i++) pv[i] = Ps[(r0 + i) * 65 + k];
            #pragma unroll
            for (int j = 0; j < 4; j++) vv[j] = Vs[k * 65 + c0 + j];
            #pragma unroll
            for (int i = 0; i < 4; i++)
                #pragma unroll
                for (int j = 0; j < 4; j++)
                    acc[i][j] += pv[i] * vv[j];
        }
        __syncthreads();
    }

    float* obase = g_attn + ((size_t)(b * S_ + q0) * NH + h) * HD;
    #pragma unroll
    for (int i = 0; i < 4; i++) {
        float inv = 1.f / l[i];
        #pragma unroll
        for (int j = 0; j < 4; j++)
            obase[(size_t)(r0 + i) * NH * HD + c0 + j] = acc[i][j] * inv;
    }
}

// ---------------------------------------------------------------------------
// kernel_launch
// ---------------------------------------------------------------------------
extern "C" void kernel_launch(void* const* d_in, const int* in_sizes, int n_in,
                              void* d_out, int out_size)
{
    const float* hs    = (const float*)d_in[0];
    const int*   amask = (const int*)  d_in[1];
    const float* Wq    = (const float*)d_in[2];
    const float* bq    = (const float*)d_in[3];
    const float* Wk    = (const float*)d_in[4];
    const float* bk    = (const float*)d_in[5];
    const float* Wv    = (const float*)d_in[6];
    const float* bv    = (const float*)d_in[7];
    const float* Wo    = (const float*)d_in[8];
    const float* bo    = (const float*)d_in[9];
    float* out = (float*)d_out;

    float *qkvp, *ap, *biasp;
    cudaGetSymbolAddress((void**)&qkvp, g_qkv);
    cudaGetSymbolAddress((void**)&ap, g_attn);
    cudaGetSymbolAddress((void**)&biasp, g_bias);
    __nv_bfloat16 *hshi, *hslo, *athi, *atlo, *wch, *wcl, *woh, *wol;
    cudaGetSymbolAddress((void**)&hshi, g_hs_hi);
    cudaGetSymbolAddress((void**)&hslo, g_hs_lo);
    cudaGetSymbolAddress((void**)&athi, g_at_hi);
    cudaGetSymbolAddress((void**)&atlo, g_at_lo);
    cudaGetSymbolAddress((void**)&wch, g_Wc_hi);
    cudaGetSymbolAddress((void**)&wcl, g_Wc_lo);
    cudaGetSymbolAddress((void**)&woh, g_Wo_hi);
    cudaGetSymbolAddress((void**)&wol, g_Wo_lo);

    cudaFuncSetAttribute(gemm_mma_kernel,
                         cudaFuncAttributeMaxDynamicSharedMemorySize, GEMM_SMEM);
    size_t asmem = 4 * 64 * 65 * sizeof(float);
    cudaFuncSetAttribute(attn_kernel,
                         cudaFuncAttributeMaxDynamicSharedMemorySize, (int)asmem);

    const int M = B_ * S_;   // 4096
    const int nhs = M * HID;

    // 1. weight transpose + split
    prep_weights_kernel<<<dim3(32, 32, 4), dim3(32, 8)>>>(Wq, Wk, Wv, Wo);
    // 2. hidden states split
    split_kernel<<<(nhs + 255) / 256, 256>>>(hs, hshi, hslo, nhs);
    // 3. rope table + bias concat
    rope_table_kernel<<<(S_ * 32 + 255) / 256, 256>>>(bq, bk, bv);
    // 4. fused QKV projection  (C = g_qkv [4096,1536])
    gemm_mma_kernel<<<dim3(NCAT / 128, M / 128), 256, GEMM_SMEM>>>(
        hshi, hslo, wch, wcl, biasp, qkvp, NCAT, HID);
    // 5. RoPE
    int tot = B_ * S_ * (NH + NKV) * (HD / 2);
    rope_apply_kernel<<<(tot + 255) / 256, 256>>>();
    // 6. attention  (profiled launch)
    attn_kernel<<<dim3(S_ / 64, NH, B_), 256, asmem>>>(amask);
    // 7. attention output split
    split_kernel<<<(nhs + 255) / 256, 256>>>(ap, athi, atlo, nhs);
    // 8. output projection
    gemm_mma_kernel<<<dim3(HID / 128, M / 128), 256, GEMM_SMEM>>>(
        athi, atlo, woh, wol, bo, out, HID, HID);
}

// round 4
// speedup vs baseline: 2.4062x; 1.6693x over previous
#include <cuda_runtime.h>
#include <cuda_bf16.h>
#include <cstdint>
#include <math.h>

#define B_    2
#define S_    2048
#define HID   1024
#define NH    16
#define NKV   4
#define HD    64
#define REP   (NH / NKV)
#define NCAT  1536            // 1024 (Q) + 256 (K) + 256 (V)

// ---------------------------------------------------------------------------
// Scratch (device globals)
// ---------------------------------------------------------------------------
__device__ float g_qkv[(size_t)B_ * S_ * NCAT];      // [4096, 1536] q|k|v
__device__ float g_cos[S_ * 32];
__device__ float g_sin[S_ * 32];
__device__ float g_bias[NCAT];

__device__ __nv_bfloat16 g_hs_hi[(size_t)B_ * S_ * HID];
__device__ __nv_bfloat16 g_hs_lo[(size_t)B_ * S_ * HID];
__device__ __nv_bfloat16 g_at_hi[(size_t)B_ * S_ * HID];   // written by attention
__device__ __nv_bfloat16 g_at_lo[(size_t)B_ * S_ * HID];
__device__ __nv_bfloat16 g_Wc_hi[NCAT * HID];        // [1536,1024], K-major rows
__device__ __nv_bfloat16 g_Wc_lo[NCAT * HID];
__device__ __nv_bfloat16 g_Wo_hi[HID * HID];
__device__ __nv_bfloat16 g_Wo_lo[HID * HID];

// ---------------------------------------------------------------------------
// helpers
// ---------------------------------------------------------------------------
__device__ __forceinline__ uint32_t smem_u32(const void* p) {
    uint32_t a;
    asm("{ .reg .u64 t; cvta.to.shared.u64 t, %1; cvt.u32.u64 %0, t; }" : "=r"(a) : "l"(p));
    return a;
}
#define LDSM_X4(r0, r1, r2, r3, addr) \
    asm volatile("ldmatrix.sync.aligned.m8n8.x4.shared.b16 {%0,%1,%2,%3}, [%4];" \
        : "=r"(r0), "=r"(r1), "=r"(r2), "=r"(r3) : "r"(addr))

__device__ __forceinline__ void mma_bf16(float* d, const uint32_t* a,
                                         uint32_t b0, uint32_t b1) {
    asm volatile(
        "mma.sync.aligned.m16n8k16.row.col.f32.bf16.bf16.f32 "
        "{%0,%1,%2,%3}, {%4,%5,%6,%7}, {%8,%9}, {%0,%1,%2,%3};"
        : "+f"(d[0]), "+f"(d[1]), "+f"(d[2]), "+f"(d[3])
        : "r"(a[0]), "r"(a[1]), "r"(a[2]), "r"(a[3]), "r"(b0), "r"(b1));
}

// split two floats into packed bf16x2 hi + lo words (x -> low half)
__device__ __forceinline__ void split2(float x, float y, uint32_t& h, uint32_t& l) {
    __nv_bfloat162 hh = __floats2bfloat162_rn(x, y);
    float rx = x - __bfloat162float(hh.x);
    float ry = y - __bfloat162float(hh.y);
    __nv_bfloat162 ll = __floats2bfloat162_rn(rx, ry);
    h = *reinterpret_cast<uint32_t*>(&hh);
    l = *reinterpret_cast<uint32_t*>(&ll);
}

// ---------------------------------------------------------------------------
// Weight prep: transpose + hi/lo split.  z=0:Wq z=1:Wk z=2:Wv z=3:Wo.
// ---------------------------------------------------------------------------
__global__ void prep_weights_kernel(const float* __restrict__ Wq,
                                    const float* __restrict__ Wk,
                                    const float* __restrict__ Wv,
                                    const float* __restrict__ Wo) {
    __shared__ float t[32][33];
    int z = blockIdx.z;
    const float* W;
    __nv_bfloat16 *hi, *lo;
    int N, rowoff;
    if (z == 0)      { W = Wq; N = HID; rowoff = 0;    hi = g_Wc_hi; lo = g_Wc_lo; }
    else if (z == 1) { W = Wk; N = 256; rowoff = 1024; hi = g_Wc_hi; lo = g_Wc_lo; }
    else if (z == 2) { W = Wv; N = 256; rowoff = 1280; hi = g_Wc_hi; lo = g_Wc_lo; }
    else             { W = Wo; N = HID; rowoff = 0;    hi = g_Wo_hi; lo = g_Wo_lo; }

    int n0 = blockIdx.x * 32, k0 = blockIdx.y * 32;
    if (n0 >= N) return;
    int x = threadIdx.x, y = threadIdx.y;   // (32, 8)
    #pragma unroll
    for (int yy = y; yy < 32; yy += 8)
        t[yy][x] = W[(size_t)(k0 + yy) * N + n0 + x];
    __syncthreads();
    #pragma unroll
    for (int yy = y; yy < 32; yy += 8) {
        float v = t[x][yy];                 // W[k0+x][n0+yy]
        __nv_bfloat16 h = __float2bfloat16(v);
        size_t o = (size_t)(rowoff + n0 + yy) * HID + k0 + x;
        hi[o] = h;
        lo[o] = __float2bfloat16(v - __bfloat162float(h));
    }
}

__global__ void split_kernel(const float* __restrict__ in,
                             __nv_bfloat16* __restrict__ hi,
                             __nv_bfloat16* __restrict__ lo, int n) {
    int i = blockIdx.x * blockDim.x + threadIdx.x;
    if (i >= n) return;
    float v = in[i];
    __nv_bfloat16 h = __float2bfloat16(v);
    hi[i] = h;
    lo[i] = __float2bfloat16(v - __bfloat162float(h));
}

// ---------------------------------------------------------------------------
// RoPE table + bias concat
// ---------------------------------------------------------------------------
__global__ void rope_table_kernel(const float* __restrict__ bq,
                                  const float* __restrict__ bk,
                                  const float* __restrict__ bv) {
    int idx = blockIdx.x * blockDim.x + threadIdx.x;
    if (idx < NCAT)
        g_bias[idx] = (idx < 1024) ? bq[idx] : (idx < 1280) ? bk[idx - 1024] : bv[idx - 1280];
    if (idx >= S_ * 32) return;
    int t = idx >> 5, j = idx & 31;
    double inv = exp2(-(double)j * 0.5190512648261507);   // log2(1e5)/32
    float ang = (float)((double)t * inv);
    float s, c;
    sincosf(ang, &s, &c);
    g_cos[idx] = c;
    g_sin[idx] = s;
}

// ---------------------------------------------------------------------------
// GEMM via mma.sync (bf16 hi/lo x3 passes): C[M,*] = A @ W^T + bias
// ---------------------------------------------------------------------------
#define GEMM_SMEM (2 * 40960)

__global__ __launch_bounds__(256, 1) void gemm_mma_kernel(
    const __nv_bfloat16* __restrict__ Ahi, const __nv_bfloat16* __restrict__ Alo,
    const __nv_bfloat16* __restrict__ Whi, const __nv_bfloat16* __restrict__ Wlo,
    const float* __restrict__ bias, float* __restrict__ C, int ldc, int K)
{
    extern __shared__ char smx[];
    const int tid = threadIdx.x, lane = tid & 31, wid = tid >> 5;
    const int wm = wid & 1, wn = wid >> 1;
    const int m0 = blockIdx.y * 128, n0 = blockIdx.x * 128;
    const uint32_t sbase = smem_u32(smx);

    float acc[4][4][4];
    #pragma unroll
    for (int a = 0; a < 4; a++)
        #pragma unroll
        for (int b = 0; b < 4; b++)
            #pragma unroll
            for (int c = 0; c < 4; c++) acc[a][b][c] = 0.f;

    auto load_stage = [&](int ch, int s) {
        char* base = smx + s * 40960;
        int k0 = ch * 32;
        #pragma unroll
        for (int mat = 0; mat < 4; ++mat) {
            const __nv_bfloat16* p = (mat == 0) ? Ahi : (mat == 1) ? Alo
                                   : (mat == 2) ? Whi : Wlo;
            int rb = (mat < 2) ? m0 : n0;
            #pragma unroll
            for (int it = 0; it < 2; ++it) {
                int i = it * 256 + tid;
                int row = i >> 2, seg = i & 3;
                *reinterpret_cast<uint4*>(base + mat * 10240 + row * 80 + seg * 16) =
                    *reinterpret_cast<const uint4*>(p + (size_t)(rb + row) * K + k0 + seg * 8);
            }
        }
    };

    load_stage(0, 0);
    __syncthreads();

    const int NCH = K / 32;
    for (int ch = 0; ch < NCH; ++ch) {
        const int s = ch & 1;
        if (ch + 1 < NCH) load_stage(ch + 1, s ^ 1);

        const uint32_t b = sbase + s * 40960;
        const uint32_t aAhi = b, aAlo = b + 10240, aWhi = b + 20480, aWlo = b + 30720;

        #pragma unroll
        for (int ks = 0; ks < 2; ++ks) {
            uint32_t ah[4][4], al[4][4], bh[2][4], bl[2][4];
            const uint32_t coff = ks * 32 + ((lane >> 4) << 4);
            #pragma unroll
            for (int mi = 0; mi < 4; ++mi) {
                uint32_t ro = (uint32_t)(wm * 64 + mi * 16 + (lane & 15)) * 80 + coff;
                LDSM_X4(ah[mi][0], ah[mi][1], ah[mi][2], ah[mi][3], aAhi + ro);
                LDSM_X4(al[mi][0], al[mi][1], al[mi][2], al[mi][3], aAlo + ro);
            }
            #pragma unroll
            for (int g = 0; g < 2; ++g) {
                uint32_t ro = (uint32_t)(wn * 32 + g * 16 + (lane & 15)) * 80 + coff;
                LDSM_X4(bh[g][0], bh[g][1], bh[g][2], bh[g][3], aWhi + ro);
                LDSM_X4(bl[g][0], bl[g][1], bl[g][2], bl[g][3], aWlo + ro);
            }
            #pragma unroll
            for (int mi = 0; mi < 4; ++mi) {
                #pragma unroll
                for (int j = 0; j < 4; ++j) {
                    const int g = j >> 1, p = j & 1;
                    mma_bf16(acc[mi][j], ah[mi], bh[g][p], bh[g][p + 2]);
                    mma_bf16(acc[mi][j], ah[mi], bl[g][p], bl[g][p + 2]);
                    mma_bf16(acc[mi][j], al[mi], bh[g][p], bh[g][p + 2]);
                }
            }
        }
        __syncthreads();
    }

    #pragma unroll
    for (int mi = 0; mi < 4; ++mi) {
        const int r = m0 + wm * 64 + mi * 16 + (lane >> 2);
        #pragma unroll
        for (int j = 0; j < 4; ++j) {
            const int col = n0 + wn * 32 + j * 8 + (lane & 3) * 2;
            const float b0 = bias[col], b1 = bias[col + 1];
            float2 v0 = make_float2(acc[mi][j][0] + b0, acc[mi][j][1] + b1);
            float2 v1 = make_float2(acc[mi][j][2] + b0, acc[mi][j][3] + b1);
            *reinterpret_cast<float2*>(C + (size_t)r * ldc + col) = v0;
            *reinterpret_cast<float2*>(C + (size_t)(r + 8) * ldc + col) = v1;
        }
    }
}

// ---------------------------------------------------------------------------
// RoPE apply on g_qkv
// ---------------------------------------------------------------------------
__global__ void rope_apply_kernel() {
    const int totq = B_ * S_ * NH * (HD / 2);
    const int totk = B_ * S_ * NKV * (HD / 2);
    int idx = blockIdx.x * blockDim.x + threadIdx.x;
    if (idx >= totq + totk) return;

    float* base;
    int pos, p;
    if (idx < totq) {
        p = idx & 31;
        int rem = idx >> 5;
        int row = rem / NH, h = rem % NH;
        pos = row % S_;
        base = g_qkv + (size_t)row * NCAT + h * HD;
    } else {
        int idx2 = idx - totq;
        p = idx2 & 31;
        int rem = idx2 >> 5;
        int row = rem / NKV, kh = rem % NKV;
        pos = row % S_;
        base = g_qkv + (size_t)row * NCAT + 1024 + kh * HD;
    }
    int d0 = 2 * p, d1 = 2 * p + 1;
    int j0 = d0 & 31, j1 = d1 & 31;
    float c0 = g_cos[pos * 32 + j0], s0 = g_sin[pos * 32 + j0];
    float c1 = g_cos[pos * 32 + j1], s1 = g_sin[pos * 32 + j1];
    float x0 = base[d0], x1 = base[d1];
    base[d0] = x0 * c0 - x1 * s0;
    base[d1] = x1 * c1 + x0 * s1;
}

// ---------------------------------------------------------------------------
// Flash attention on mma.sync: CTA = (64 q rows, head, batch), 4 warps.
// Q/K hi-lo bf16 in smem (144B padded rows), V transposed [d][key].
// S = QK^T 3-pass; softmax in regs; P->A fragment via register repack;
// O += P V 3-pass. Writes bf16 hi/lo attention output directly.
// ---------------------------------------------------------------------------
#define QH_OFF 0
#define QL_OFF 9216
#define KH_OFF 18432
#define KL_OFF 27648
#define VH_OFF 36864
#define VL_OFF 46080
#define KM_OFF 55296
#define ATTN_SMEM (55296 + 256)

__global__ __launch_bounds__(128) void attn_mma_kernel(
    const int* __restrict__ amask,
    __nv_bfloat16* __restrict__ athi, __nv_bfloat16* __restrict__ atlo)
{
    extern __shared__ char sm[];
    const uint32_t sb = smem_u32(sm);
    int* km = reinterpret_cast<int*>(sm + KM_OFF);

    const int tid = threadIdx.x, lane = tid & 31, w = tid >> 5;
    const int qi = blockIdx.x, h = blockIdx.y, b = blockIdx.z;
    const int q0 = qi * 64, kvh = h >> 2;

    // ---- load Q tile (64x64) -> hi/lo bf16, padded rows ----
    const float* qbase = g_qkv + (size_t)(b * S_ + q0) * NCAT + h * HD;
    #pragma unroll
    for (int it = 0; it < 16; ++it) {
        int i = it * 128 + tid;
        int row = i >> 5, cp = i & 31;
        float2 v = *reinterpret_cast<const float2*>(qbase + (size_t)row * NCAT + cp * 2);
        uint32_t hh, ll;
        split2(v.x, v.y, hh, ll);
        *reinterpret_cast<uint32_t*>(sm + QH_OFF + row * 144 + cp * 4) = hh;
        *reinterpret_cast<uint32_t*>(sm + QL_OFF + row * 144 + cp * 4) = ll;
    }
    __syncthreads();

    // preload Q A-fragments (held for the whole kernel)
    uint32_t qh[4][4], ql[4][4];
    #pragma unroll
    for (int ks = 0; ks < 4; ++ks) {
        uint32_t ro = (uint32_t)((w * 16 + (lane & 15)) * 144 + ks * 32 + ((lane >> 4) << 4));
        LDSM_X4(qh[ks][0], qh[ks][1], qh[ks][2], qh[ks][3], sb + QH_OFF + ro);
        LDSM_X4(ql[ks][0], ql[ks][1], ql[ks][2], ql[ks][3], sb + QL_OFF + ro);
    }

    float acc[8][4];
    #pragma unroll
    for (int nt = 0; nt < 8; ++nt)
        #pragma unroll
        for (int c = 0; c < 4; ++c) acc[nt][c] = 0.f;
    float m0 = -1e30f, m1 = -1e30f, l0 = 0.f, l1 = 0.f;
    const int row0g = q0 + w * 16 + (lane >> 2);
    const int row1g = row0g + 8;

    const int nkt = qi + 1;
    for (int kt = 0; kt < nkt; ++kt) {
        const int k0 = kt * 64;
        const float* kb = g_qkv + (size_t)(b * S_ + k0) * NCAT + 1024 + kvh * HD;
        const float* vb = g_qkv + (size_t)(b * S_ + k0) * NCAT + 1280 + kvh * HD;

        // K tile (64x64) hi/lo
        #pragma unroll
        for (int it = 0; it < 16; ++it) {
            int i = it * 128 + tid;
            int row = i >> 5, cp = i & 31;
            float2 v = *reinterpret_cast<const float2*>(kb + (size_t)row * NCAT + cp * 2);
            uint32_t hh, ll;
            split2(v.x, v.y, hh, ll);
            *reinterpret_cast<uint32_t*>(sm + KH_OFF + row * 144 + cp * 4) = hh;
            *reinterpret_cast<uint32_t*>(sm + KL_OFF + row * 144 + cp * 4) = ll;
        }
        // V tile transposed: Vt[d][key]
        #pragma unroll
        for (int it = 0; it < 32; ++it) {
            int i = it * 128 + tid;
            int key = i >> 6, d = i & 63;
            float v = vb[(size_t)key * NCAT + d];
            __nv_bfloat16 hv = __float2bfloat16(v);
            *reinterpret_cast<__nv_bfloat16*>(sm + VH_OFF + d * 144 + key * 2) = hv;
            *reinterpret_cast<__nv_bfloat16*>(sm + VL_OFF + d * 144 + key * 2) =
                __float2bfloat16(v - __bfloat162float(hv));
        }
        if (tid < 64) km[tid] = amask[b * S_ + k0 + tid];
        __syncthreads();

        // ---- S = Q K^T (3-pass) ----
        float s[8][4];
        #pragma unroll
        for (int nt = 0; nt < 8; ++nt)
            #pragma unroll
            for (int c = 0; c < 4; ++c) s[nt][c] = 0.f;

        #pragma unroll
        for (int ks = 0; ks < 4; ++ks) {
            uint32_t bh[4][4], bl[4][4];
            #pragma unroll
            for (int g = 0; g < 4; ++g) {
                uint32_t ro = (uint32_t)((g * 16 + (lane & 15)) * 144 + ks * 32 + ((lane >> 4) << 4));
                LDSM_X4(bh[g][0], bh[g][1], bh[g][2], bh[g][3], sb + KH_OFF + ro);
                LDSM_X4(bl[g][0], bl[g][1], bl[g][2], bl[g][3], sb + KL_OFF + ro);
            }
            #pragma unroll
            for (int g = 0; g < 4; ++g) {
                #pragma unroll
                for (int p = 0; p < 2; ++p) {
                    int nt = g * 2 + p;
                    mma_bf16(s[nt], qh[ks], bh[g][p], bh[g][p + 2]);
                    mma_bf16(s[nt], qh[ks], bl[g][p], bl[g][p + 2]);
                    mma_bf16(s[nt], ql[ks], bh[g][p], bh[g][p + 2]);
                }
            }
        }

        // ---- scale + causal + key mask, online softmax ----
        float mt0 = -1e30f, mt1 = -1e30f;
        #pragma unroll
        for (int nt = 0; nt < 8; ++nt) {
            int cl = nt * 8 + (lane & 3) * 2;
            int cg0 = k0 + cl, cg1 = cg0 + 1;
            bool ok0 = km[cl] != 0, ok1 = km[cl + 1] != 0;
            s[nt][0] = (ok0 && cg0 <= row0g) ? s[nt][0] * 0.125f : -1e30f;
            s[nt][1] = (ok1 && cg1 <= row0g) ? s[nt][1] * 0.125f : -1e30f;
            s[nt][2] = (ok0 && cg0 <= row1g) ? s[nt][2] * 0.125f : -1e30f;
            s[nt][3] = (ok1 && cg1 <= row1g) ? s[nt][3] * 0.125f : -1e30f;
            mt0 = fmaxf(mt0, fmaxf(s[nt][0], s[nt][1]));
            mt1 = fmaxf(mt1, fmaxf(s[nt][2], s[nt][3]));
        }
        mt0 = fmaxf(mt0, __shfl_xor_sync(0xffffffffu, mt0, 1));
        mt0 = fmaxf(mt0, __shfl_xor_sync(0xffffffffu, mt0, 2));
        mt1 = fmaxf(mt1, __shfl_xor_sync(0xffffffffu, mt1, 1));
        mt1 = fmaxf(mt1, __shfl_xor_sync(0xffffffffu, mt1, 2));

        float mn0 = fmaxf(m0, mt0), mn1 = fmaxf(m1, mt1);
        float corr0 = __expf(m0 - mn0), corr1 = __expf(m1 - mn1);
        float ps0 = 0.f, ps1 = 0.f;
        uint32_t pah[4][4], pal[4][4];
        #pragma unroll
        for (int nt = 0; nt < 8; ++nt) {
            float p0 = __expf(s[nt][0] - mn0);
            float p1 = __expf(s[nt][1] - mn0);
            float p2 = __expf(s[nt][2] - mn1);
            float p3 = __expf(s[nt][3] - mn1);
            ps0 += p0 + p1;
            ps1 += p2 + p3;
            int t = nt >> 1, q = nt & 1;
            split2(p0, p1, pah[t][q * 2 + 0], pal[t][q * 2 + 0]);
            split2(p2, p3, pah[t][q * 2 + 1], pal[t][q * 2 + 1]);
        }
        ps0 += __shfl_xor_sync(0xffffffffu, ps0, 1);
        ps0 += __shfl_xor_sync(0xffffffffu, ps0, 2);
        ps1 += __shfl_xor_sync(0xffffffffu, ps1, 1);
        ps1 += __shfl_xor_sync(0xffffffffu, ps1, 2);
        l0 = l0 * corr0 + ps0;
        l1 = l1 * corr1 + ps1;
        m0 = mn0; m1 = mn1;
        #pragma unroll
        for (int nt = 0; nt < 8; ++nt) {
            acc[nt][0] *= corr0; acc[nt][1] *= corr0;
            acc[nt][2] *= corr1; acc[nt][3] *= corr1;
        }

        // ---- O += P V (3-pass) ----
        #pragma unroll
        for (int ks = 0; ks < 4; ++ks) {
            uint32_t vh[4][4], vl[4][4];
            #pragma unroll
            for (int g = 0; g < 4; ++g) {
                uint32_t ro = (uint32_t)((g * 16 + (lane & 15)) * 144 + ks * 32 + ((lane >> 4) << 4));
                LDSM_X4(vh[g][0], vh[g][1], vh[g][2], vh[g][3], sb + VH_OFF + ro);
                LDSM_X4(vl[g][0], vl[g][1], vl[g][2], vl[g][3], sb + VL_OFF + ro);
            }
            #pragma unroll
            for (int g = 0; g < 4; ++g) {
                #pragma unroll
                for (int p = 0; p < 2; ++p) {
                    int nt = g * 2 + p;
                    mma_bf16(acc[nt], pah[ks], vh[g][p], vh[g][p + 2]);
                    mma_bf16(acc[nt], pah[ks], vl[g][p], vl[g][p + 2]);
                    mma_bf16(acc[nt], pal[ks], vh[g][p], vh[g][p + 2]);
                }
            }
        }
        __syncthreads();
    }

    // ---- epilogue: o = acc / l, write bf16 hi/lo directly ----
    float inv0 = 1.f / l0, inv1 = 1.f / l1;
    size_t r0o = (size_t)(b * S_ + row0g) * HID + h * HD;
    size_t r1o = r0o + (size_t)8 * HID;
    #pragma unroll
    for (int nt = 0; nt < 8; ++nt) {
        int d = nt * 8 + (lane & 3) * 2;
        uint32_t hh, ll;
        split2(acc[nt][0] * inv0, acc[nt][1] * inv0, hh, ll);
        *reinterpret_cast<uint32_t*>(athi + r0o + d) = hh;
        *reinterpret_cast<uint32_t*>(atlo + r0o + d) = ll;
        split2(acc[nt][2] * inv1, acc[nt][3] * inv1, hh, ll);
        *reinterpret_cast<uint32_t*>(athi + r1o + d) = hh;
        *reinterpret_cast<uint32_t*>(atlo + r1o + d) = ll;
    }
}

// ---------------------------------------------------------------------------
// kernel_launch
// ---------------------------------------------------------------------------
extern "C" void kernel_launch(void* const* d_in, const int* in_sizes, int n_in,
                              void* d_out, int out_size)
{
    const float* hs    = (const float*)d_in[0];
    const int*   amask = (const int*)  d_in[1];
    const float* Wq    = (const float*)d_in[2];
    const float* bq    = (const float*)d_in[3];
    const float* Wk    = (const float*)d_in[4];
    const float* bk    = (const float*)d_in[5];
    const float* Wv    = (const float*)d_in[6];
    const float* bv    = (const float*)d_in[7];
    const float* Wo    = (const float*)d_in[8];
    const float* bo    = (const float*)d_in[9];
    float* out = (float*)d_out;

    float *qkvp, *biasp;
    cudaGetSymbolAddress((void**)&qkvp, g_qkv);
    cudaGetSymbolAddress((void**)&biasp, g_bias);
    __nv_bfloat16 *hshi, *hslo, *athi, *atlo, *wch, *wcl, *woh, *wol;
    cudaGetSymbolAddress((void**)&hshi, g_hs_hi);
    cudaGetSymbolAddress((void**)&hslo, g_hs_lo);
    cudaGetSymbolAddress((void**)&athi, g_at_hi);
    cudaGetSymbolAddress((void**)&atlo, g_at_lo);
    cudaGetSymbolAddress((void**)&wch, g_Wc_hi);
    cudaGetSymbolAddress((void**)&wcl, g_Wc_lo);
    cudaGetSymbolAddress((void**)&woh, g_Wo_hi);
    cudaGetSymbolAddress((void**)&wol, g_Wo_lo);

    cudaFuncSetAttribute(gemm_mma_kernel,
                         cudaFuncAttributeMaxDynamicSharedMemorySize, GEMM_SMEM);
    cudaFuncSetAttribute(attn_mma_kernel,
                         cudaFuncAttributeMaxDynamicSharedMemorySize, ATTN_SMEM);

    const int M = B_ * S_;   // 4096
    const int nhs = M * HID;

    // 0. weight transpose + split
    prep_weights_kernel<<<dim3(32, 32, 4), dim3(32, 8)>>>(Wq, Wk, Wv, Wo);
    // 1. hidden states split
    split_kernel<<<(nhs + 255) / 256, 256>>>(hs, hshi, hslo, nhs);
    // 2. rope table + bias concat
    rope_table_kernel<<<(S_ * 32 + 255) / 256, 256>>>(bq, bk, bv);
    // 3. fused QKV projection
    gemm_mma_kernel<<<dim3(NCAT / 128, M / 128), 256, GEMM_SMEM>>>(
        hshi, hslo, wch, wcl, biasp, qkvp, NCAT, HID);
    // 4. RoPE
    int tot = B_ * S_ * (NH + NKV) * (HD / 2);
    rope_apply_kernel<<<(tot + 255) / 256, 256>>>();
    // 5. attention (profiled launch)
    attn_mma_kernel<<<dim3(S_ / 64, NH, B_), 128, ATTN_SMEM>>>(amask, athi, atlo);
    // 6. output projection
    gemm_mma_kernel<<<dim3(HID / 128, M / 128), 256, GEMM_SMEM>>>(
        athi, atlo, woh, wol, bo, out, HID, HID);
}

// round 5
// speedup vs baseline: 2.8105x; 1.1680x over previous
#include <cuda_runtime.h>
#include <cuda_bf16.h>
#include <cstdint>
#include <math.h>

#define B_    2
#define S_    2048
#define HID   1024
#define NH    16
#define NKV   4
#define HD    64
#define NCAT  1536            // 1024 (Q) + 256 (K) + 256 (V)

// ---------------------------------------------------------------------------
// Scratch (device globals)
// ---------------------------------------------------------------------------
__device__ float g_qkv[(size_t)B_ * S_ * NCAT];      // [4096, 1536] q|k|v fp32
__device__ float g_cos[S_ * 32];
__device__ float g_sin[S_ * 32];
__device__ float g_bias[NCAT];

__device__ __nv_bfloat16 g_hs_hi[(size_t)B_ * S_ * HID];
__device__ __nv_bfloat16 g_hs_lo[(size_t)B_ * S_ * HID];
__device__ __nv_bfloat16 g_at_hi[(size_t)B_ * S_ * HID];
__device__ __nv_bfloat16 g_at_lo[(size_t)B_ * S_ * HID];
__device__ __nv_bfloat16 g_Wc_hi[NCAT * HID];
__device__ __nv_bfloat16 g_Wc_lo[NCAT * HID];
__device__ __nv_bfloat16 g_Wo_hi[HID * HID];
__device__ __nv_bfloat16 g_Wo_lo[HID * HID];

// post-rope bf16 hi/lo tensors for attention
__device__ __nv_bfloat16 g_Qh[(size_t)B_ * S_ * HID];        // [4096,1024]
__device__ __nv_bfloat16 g_Ql[(size_t)B_ * S_ * HID];
__device__ __nv_bfloat16 g_Kh[(size_t)B_ * S_ * NKV * HD];   // [4096,256]
__device__ __nv_bfloat16 g_Kl[(size_t)B_ * S_ * NKV * HD];
__device__ __nv_bfloat16 g_Vth[(size_t)B_ * NKV * HD * S_];  // [b,kvh,d,s]
__device__ __nv_bfloat16 g_Vtl[(size_t)B_ * NKV * HD * S_];

// ---------------------------------------------------------------------------
// helpers
// ---------------------------------------------------------------------------
__device__ __forceinline__ uint32_t smem_u32(const void* p) {
    uint32_t a;
    asm("{ .reg .u64 t; cvta.to.shared.u64 t, %1; cvt.u32.u64 %0, t; }" : "=r"(a) : "l"(p));
    return a;
}
#define LDSM_X4(r0, r1, r2, r3, addr) \
    asm volatile("ldmatrix.sync.aligned.m8n8.x4.shared.b16 {%0,%1,%2,%3}, [%4];" \
        : "=r"(r0), "=r"(r1), "=r"(r2), "=r"(r3) : "r"(addr))
#define CP_A16(dst, src) \
    asm volatile("cp.async.cg.shared.global [%0], [%1], 16;" :: "r"(dst), "l"(src))
#define CP_COMMIT() asm volatile("cp.async.commit_group;" ::: "memory")
#define CP_WAIT0()  asm volatile("cp.async.wait_group 0;" ::: "memory")
#define CP_WAIT1()  asm volatile("cp.async.wait_group 1;" ::: "memory")

__device__ __forceinline__ void mma_bf16(float* d, const uint32_t* a,
                                         uint32_t b0, uint32_t b1) {
    asm volatile(
        "mma.sync.aligned.m16n8k16.row.col.f32.bf16.bf16.f32 "
        "{%0,%1,%2,%3}, {%4,%5,%6,%7}, {%8,%9}, {%0,%1,%2,%3};"
        : "+f"(d[0]), "+f"(d[1]), "+f"(d[2]), "+f"(d[3])
        : "r"(a[0]), "r"(a[1]), "r"(a[2]), "r"(a[3]), "r"(b0), "r"(b1));
}

__device__ __forceinline__ void split2(float x, float y, uint32_t& h, uint32_t& l) {
    __nv_bfloat162 hh = __floats2bfloat162_rn(x, y);
    float rx = x - __bfloat162float(hh.x);
    float ry = y - __bfloat162float(hh.y);
    __nv_bfloat162 ll = __floats2bfloat162_rn(rx, ry);
    h = *reinterpret_cast<uint32_t*>(&hh);
    l = *reinterpret_cast<uint32_t*>(&ll);
}

// ---------------------------------------------------------------------------
// Weight prep: transpose + hi/lo split.  z=0:Wq z=1:Wk z=2:Wv z=3:Wo.
// ---------------------------------------------------------------------------
__global__ void prep_weights_kernel(const float* __restrict__ Wq,
                                    const float* __restrict__ Wk,
                                    const float* __restrict__ Wv,
                                    const float* __restrict__ Wo) {
    __shared__ float t[32][33];
    int z = blockIdx.z;
    const float* W;
    __nv_bfloat16 *hi, *lo;
    int N, rowoff;
    if (z == 0)      { W = Wq; N = HID; rowoff = 0;    hi = g_Wc_hi; lo = g_Wc_lo; }
    else if (z == 1) { W = Wk; N = 256; rowoff = 1024; hi = g_Wc_hi; lo = g_Wc_lo; }
    else if (z == 2) { W = Wv; N = 256; rowoff = 1280; hi = g_Wc_hi; lo = g_Wc_lo; }
    else             { W = Wo; N = HID; rowoff = 0;    hi = g_Wo_hi; lo = g_Wo_lo; }

    int n0 = blockIdx.x * 32, k0 = blockIdx.y * 32;
    if (n0 >= N) return;
    int x = threadIdx.x, y = threadIdx.y;
    #pragma unroll
    for (int yy = y; yy < 32; yy += 8)
        t[yy][x] = W[(size_t)(k0 + yy) * N + n0 + x];
    __syncthreads();
    #pragma unroll
    for (int yy = y; yy < 32; yy += 8) {
        float v = t[x][yy];
        __nv_bfloat16 h = __float2bfloat16(v);
        size_t o = (size_t)(rowoff + n0 + yy) * HID + k0 + x;
        hi[o] = h;
        lo[o] = __float2bfloat16(v - __bfloat162float(h));
    }
}

__global__ void split_kernel(const float* __restrict__ in,
                             __nv_bfloat16* __restrict__ hi,
                             __nv_bfloat16* __restrict__ lo, int n) {
    int i = blockIdx.x * blockDim.x + threadIdx.x;
    if (i >= n) return;
    float v = in[i];
    __nv_bfloat16 h = __float2bfloat16(v);
    hi[i] = h;
    lo[i] = __float2bfloat16(v - __bfloat162float(h));
}

// ---------------------------------------------------------------------------
// RoPE table + bias concat
// ---------------------------------------------------------------------------
__global__ void rope_table_kernel(const float* __restrict__ bq,
                                  const float* __restrict__ bk,
                                  const float* __restrict__ bv) {
    int idx = blockIdx.x * blockDim.x + threadIdx.x;
    if (idx < NCAT)
        g_bias[idx] = (idx < 1024) ? bq[idx] : (idx < 1280) ? bk[idx - 1024] : bv[idx - 1280];
    if (idx >= S_ * 32) return;
    int t = idx >> 5, j = idx & 31;
    double inv = exp2(-(double)j * 0.5190512648261507);
    float ang = (float)((double)t * inv);
    float s, c;
    sincosf(ang, &s, &c);
    g_cos[idx] = c;
    g_sin[idx] = s;
}

// ---------------------------------------------------------------------------
// GEMM via mma.sync, cp.async double-buffered (bf16 hi/lo x3 passes)
// ---------------------------------------------------------------------------
#define GEMM_SMEM (2 * 40960)

__global__ __launch_bounds__(256, 2) void gemm_mma_kernel(
    const __nv_bfloat16* __restrict__ Ahi, const __nv_bfloat16* __restrict__ Alo,
    const __nv_bfloat16* __restrict__ Whi, const __nv_bfloat16* __restrict__ Wlo,
    const float* __restrict__ bias, float* __restrict__ C, int ldc, int K)
{
    extern __shared__ char smx[];
    const int tid = threadIdx.x, lane = tid & 31, wid = tid >> 5;
    const int wm = wid & 1, wn = wid >> 1;
    const int m0 = blockIdx.y * 128, n0 = blockIdx.x * 128;
    const uint32_t sbase = smem_u32(smx);

    float acc[4][4][4];
    #pragma unroll
    for (int a = 0; a < 4; a++)
        #pragma unroll
        for (int bb = 0; bb < 4; bb++)
            #pragma unroll
            for (int c = 0; c < 4; c++) acc[a][bb][c] = 0.f;

    auto load_stage = [&](int ch, int st) {
        const uint32_t base = sbase + (uint32_t)st * 40960u;
        const int k0 = ch * 32;
        #pragma unroll
        for (int mat = 0; mat < 4; ++mat) {
            const __nv_bfloat16* p = (mat == 0) ? Ahi : (mat == 1) ? Alo
                                   : (mat == 2) ? Whi : Wlo;
            const int rb = (mat < 2) ? m0 : n0;
            #pragma unroll
            for (int it = 0; it < 2; ++it) {
                int i = it * 256 + tid;
                int row = i >> 2, seg = i & 3;
                CP_A16(base + mat * 10240u + (uint32_t)(row * 80 + seg * 16),
                       p + (size_t)(rb + row) * K + k0 + seg * 8);
            }
        }
    };

    const int NCH = K / 32;
    load_stage(0, 0);
    CP_COMMIT();

    for (int ch = 0; ch < NCH; ++ch) {
        if (ch + 1 < NCH) { load_stage(ch + 1, (ch + 1) & 1); CP_COMMIT(); CP_WAIT1(); }
        else              { CP_WAIT0(); }
        __syncthreads();

        const uint32_t sbuf = sbase + (uint32_t)(ch & 1) * 40960u;
        const uint32_t aAhi = sbuf, aAlo = sbuf + 10240, aWhi = sbuf + 20480, aWlo = sbuf + 30720;

        #pragma unroll
        for (int ks = 0; ks < 2; ++ks) {
            uint32_t ah[4][4], al[4][4], bh[2][4], bl[2][4];
            const uint32_t coff = ks * 32 + ((lane >> 4) << 4);
            #pragma unroll
            for (int mi = 0; mi < 4; ++mi) {
                uint32_t ro = (uint32_t)(wm * 64 + mi * 16 + (lane & 15)) * 80 + coff;
                LDSM_X4(ah[mi][0], ah[mi][1], ah[mi][2], ah[mi][3], aAhi + ro);
                LDSM_X4(al[mi][0], al[mi][1], al[mi][2], al[mi][3], aAlo + ro);
            }
            #pragma unroll
            for (int g = 0; g < 2; ++g) {
                uint32_t ro = (uint32_t)(wn * 32 + g * 16 + (lane & 15)) * 80 + coff;
                LDSM_X4(bh[g][0], bh[g][1], bh[g][2], bh[g][3], aWhi + ro);
                LDSM_X4(bl[g][0], bl[g][1], bl[g][2], bl[g][3], aWlo + ro);
            }
            #pragma unroll
            for (int mi = 0; mi < 4; ++mi) {
                #pragma unroll
                for (int j = 0; j < 4; ++j) {
                    const int g = j >> 1, p = j & 1;
                    mma_bf16(acc[mi][j], ah[mi], bh[g][p], bh[g][p + 2]);
                    mma_bf16(acc[mi][j], ah[mi], bl[g][p], bl[g][p + 2]);
                    mma_bf16(acc[mi][j], al[mi], bh[g][p], bh[g][p + 2]);
                }
            }
        }
        __syncthreads();
    }

    #pragma unroll
    for (int mi = 0; mi < 4; ++mi) {
        const int r = m0 + wm * 64 + mi * 16 + (lane >> 2);
        #pragma unroll
        for (int j = 0; j < 4; ++j) {
            const int col = n0 + wn * 32 + j * 8 + (lane & 3) * 2;
            const float b0 = bias[col], b1 = bias[col + 1];
            float2 v0 = make_float2(acc[mi][j][0] + b0, acc[mi][j][1] + b1);
            float2 v1 = make_float2(acc[mi][j][2] + b0, acc[mi][j][3] + b1);
            *reinterpret_cast<float2*>(C + (size_t)r * ldc + col) = v0;
            *reinterpret_cast<float2*>(C + (size_t)(r + 8) * ldc + col) = v1;
        }
    }
}

// ---------------------------------------------------------------------------
// RoPE apply: read fp32 g_qkv, write packed bf16 hi/lo Q and K
// ---------------------------------------------------------------------------
__global__ void rope_apply_kernel() {
    const int totq = B_ * S_ * NH * (HD / 2);
    const int totk = B_ * S_ * NKV * (HD / 2);
    int idx = blockIdx.x * blockDim.x + threadIdx.x;
    if (idx >= totq + totk) return;

    const float* base;
    uint32_t *outh, *outl;
    size_t oidx;
    int pos, p;
    if (idx < totq) {
        p = idx & 31;
        int rem = idx >> 5;
        int row = rem / NH, h = rem % NH;
        pos = row % S_;
        base = g_qkv + (size_t)row * NCAT + h * HD;
        outh = reinterpret_cast<uint32_t*>(g_Qh);
        outl = reinterpret_cast<uint32_t*>(g_Ql);
        oidx = (size_t)row * 512 + h * 32 + p;
    } else {
        int idx2 = idx - totq;
        p = idx2 & 31;
        int rem = idx2 >> 5;
        int row = rem / NKV, kh = rem % NKV;
        pos = row % S_;
        base = g_qkv + (size_t)row * NCAT + 1024 + kh * HD;
        outh = reinterpret_cast<uint32_t*>(g_Kh);
        outl = reinterpret_cast<uint32_t*>(g_Kl);
        oidx = (size_t)row * 128 + kh * 32 + p;
    }
    int d0 = 2 * p, d1 = 2 * p + 1;
    int j0 = d0 & 31, j1 = d1 & 31;
    float c0 = g_cos[pos * 32 + j0], s0 = g_sin[pos * 32 + j0];
    float c1 = g_cos[pos * 32 + j1], s1 = g_sin[pos * 32 + j1];
    float x0 = base[d0], x1 = base[d1];
    float y0 = x0 * c0 - x1 * s0;
    float y1 = x1 * c1 + x0 * s1;
    uint32_t hh, ll;
    split2(y0, y1, hh, ll);
    outh[oidx] = hh;
    outl[oidx] = ll;
}

// ---------------------------------------------------------------------------
// V transpose + split: g_qkv V cols -> Vt[b][kvh][d][s] bf16 hi/lo
// ---------------------------------------------------------------------------
__global__ void v_transpose_kernel() {
    __shared__ float t[64][65];
    const int s0 = blockIdx.x * 64, kvh = blockIdx.y, b = blockIdx.z;
    const int tid = threadIdx.x;
    #pragma unroll
    for (int it = 0; it < 16; ++it) {
        int i = it * 256 + tid;
        int sl = i >> 6, d = i & 63;
        t[sl][d] = g_qkv[(size_t)(b * S_ + s0 + sl) * NCAT + 1280 + kvh * HD + d];
    }
    __syncthreads();
    #pragma unroll
    for (int it = 0; it < 16; ++it) {
        int i = it * 256 + tid;
        int d = i >> 6, sl = i & 63;
        float v = t[sl][d];
        __nv_bfloat16 h = __float2bfloat16(v);
        size_t o = ((size_t)(b * NKV + kvh) * HD + d) * S_ + s0 + sl;
        g_Vth[o] = h;
        g_Vtl[o] = __float2bfloat16(v - __bfloat162float(h));
    }
}

// ---------------------------------------------------------------------------
// Flash attention: bf16 tiles loaded via cp.async, double-buffered K/V.
// CTA = (64 queries, head, batch), 4 warps.
// ---------------------------------------------------------------------------
#define QH_OFF 0
#define QL_OFF 9216
#define ST_OFF 18432           // two stages of 36864 (KH,KL,VH,VL @ 9216 each)
#define AM_OFF (18432 + 2 * 36864)
#define ATTN_SMEM (AM_OFF + S_ * 4 + 128)

__global__ __launch_bounds__(128) void attn_mma_kernel(
    const int* __restrict__ amask,
    __nv_bfloat16* __restrict__ athi, __nv_bfloat16* __restrict__ atlo)
{
    extern __shared__ char sm[];
    const uint32_t sb = smem_u32(sm);
    int* am = reinterpret_cast<int*>(sm + AM_OFF);

    const int tid = threadIdx.x, lane = tid & 31, w = tid >> 5;
    const int qi = blockIdx.x, h = blockIdx.y, b = blockIdx.z;
    const int q0 = qi * 64, kvh = h >> 2;
    const int nkt = qi + 1;

    // mask row for this batch
    #pragma unroll
    for (int it = 0; it < 16; ++it)
        am[it * 128 + tid] = amask[b * S_ + it * 128 + tid];

    // Q tile cp.async (hi + lo)
    {
        const __nv_bfloat16* qh = g_Qh + (size_t)(b * S_ + q0) * HID + h * HD;
        const __nv_bfloat16* ql = g_Ql + (size_t)(b * S_ + q0) * HID + h * HD;
        #pragma unroll
        for (int it = 0; it < 4; ++it) {
            int i = it * 128 + tid;
            int row = i >> 3, seg = i & 7;
            uint32_t so = (uint32_t)(row * 144 + seg * 16);
            CP_A16(sb + QH_OFF + so, qh + (size_t)row * HID + seg * 8);
            CP_A16(sb + QL_OFF + so, ql + (size_t)row * HID + seg * 8);
        }
        CP_COMMIT();
    }

    auto prefetch_kv = [&](int kt, int st) {
        const int k0 = kt * 64;
        const uint32_t base = sb + ST_OFF + (uint32_t)st * 36864u;
        const __nv_bfloat16* kh = g_Kh + (size_t)(b * S_ + k0) * (NKV * HD) + kvh * HD;
        const __nv_bfloat16* kl = g_Kl + (size_t)(b * S_ + k0) * (NKV * HD) + kvh * HD;
        const __nv_bfloat16* vh = g_Vth + (size_t)(b * NKV + kvh) * HD * S_ + k0;
        const __nv_bfloat16* vl = g_Vtl + (size_t)(b * NKV + kvh) * HD * S_ + k0;
        #pragma unroll
        for (int it = 0; it < 4; ++it) {
            int i = it * 128 + tid;
            int row = i >> 3, seg = i & 7;
            uint32_t so = (uint32_t)(row * 144 + seg * 16);
            CP_A16(base +         so, kh + (size_t)row * (NKV * HD) + seg * 8);
            CP_A16(base + 9216u + so, kl + (size_t)row * (NKV * HD) + seg * 8);
            CP_A16(base + 18432u + so, vh + (size_t)row * S_ + seg * 8);
            CP_A16(base + 27648u + so, vl + (size_t)row * S_ + seg * 8);
        }
    };

    prefetch_kv(0, 0);
    CP_COMMIT();
    if (nkt > 1) { prefetch_kv(1, 1); CP_COMMIT(); CP_WAIT1(); }
    else         { CP_WAIT0(); }
    __syncthreads();

    // preload Q fragments for the whole kernel
    uint32_t qfh[4][4], qfl[4][4];
    #pragma unroll
    for (int ks = 0; ks < 4; ++ks) {
        uint32_t ro = (uint32_t)((w * 16 + (lane & 15)) * 144 + ks * 32 + ((lane >> 4) << 4));
        LDSM_X4(qfh[ks][0], qfh[ks][1], qfh[ks][2], qfh[ks][3], sb + QH_OFF + ro);
        LDSM_X4(qfl[ks][0], qfl[ks][1], qfl[ks][2], qfl[ks][3], sb + QL_OFF + ro);
    }

    float acc[8][4];
    #pragma unroll
    for (int nt = 0; nt < 8; ++nt)
        #pragma unroll
        for (int c = 0; c < 4; ++c) acc[nt][c] = 0.f;
    float m0 = -1e30f, m1 = -1e30f, l0 = 0.f, l1 = 0.f;
    const int row0g = q0 + w * 16 + (lane >> 2);
    const int row1g = row0g + 8;

    for (int kt = 0; kt < nkt; ++kt) {
        const int k0 = kt * 64;
        const uint32_t stage = sb + ST_OFF + (uint32_t)(kt & 1) * 36864u;
        const uint32_t aKH = stage, aKL = stage + 9216, aVH = stage + 18432, aVL = stage + 27648;

        // ---- S = Q K^T (3-pass) ----
        float s[8][4];
        #pragma unroll
        for (int nt = 0; nt < 8; ++nt)
            #pragma unroll
            for (int c = 0; c < 4; ++c) s[nt][c] = 0.f;

        #pragma unroll
        for (int ks = 0; ks < 4; ++ks) {
            uint32_t bh[4][4], bl[4][4];
            #pragma unroll
            for (int g = 0; g < 4; ++g) {
                uint32_t ro = (uint32_t)((g * 16 + (lane & 15)) * 144 + ks * 32 + ((lane >> 4) << 4));
                LDSM_X4(bh[g][0], bh[g][1], bh[g][2], bh[g][3], aKH + ro);
                LDSM_X4(bl[g][0], bl[g][1], bl[g][2], bl[g][3], aKL + ro);
            }
            #pragma unroll
            for (int g = 0; g < 4; ++g) {
                #pragma unroll
                for (int p = 0; p < 2; ++p) {
                    int nt = g * 2 + p;
                    mma_bf16(s[nt], qfh[ks], bh[g][p], bh[g][p + 2]);
                    mma_bf16(s[nt], qfh[ks], bl[g][p], bl[g][p + 2]);
                    mma_bf16(s[nt], qfl[ks], bh[g][p], bh[g][p + 2]);
                }
            }
        }

        // ---- scale + causal + key mask, online softmax ----
        float mt0 = -1e30f, mt1 = -1e30f;
        #pragma unroll
        for (int nt = 0; nt < 8; ++nt) {
            int cl = nt * 8 + (lane & 3) * 2;
            int cg0 = k0 + cl, cg1 = cg0 + 1;
            bool ok0 = am[cg0] != 0, ok1 = am[cg1] != 0;
            s[nt][0] = (ok0 && cg0 <= row0g) ? s[nt][0] * 0.125f : -1e30f;
            s[nt][1] = (ok1 && cg1 <= row0g) ? s[nt][1] * 0.125f : -1e30f;
            s[nt][2] = (ok0 && cg0 <= row1g) ? s[nt][2] * 0.125f : -1e30f;
            s[nt][3] = (ok1 && cg1 <= row1g) ? s[nt][3] * 0.125f : -1e30f;
            mt0 = fmaxf(mt0, fmaxf(s[nt][0], s[nt][1]));
            mt1 = fmaxf(mt1, fmaxf(s[nt][2], s[nt][3]));
        }
        mt0 = fmaxf(mt0, __shfl_xor_sync(0xffffffffu, mt0, 1));
        mt0 = fmaxf(mt0, __shfl_xor_sync(0xffffffffu, mt0, 2));
        mt1 = fmaxf(mt1, __shfl_xor_sync(0xffffffffu, mt1, 1));
        mt1 = fmaxf(mt1, __shfl_xor_sync(0xffffffffu, mt1, 2));

        float mn0 = fmaxf(m0, mt0), mn1 = fmaxf(m1, mt1);
        float corr0 = __expf(m0 - mn0), corr1 = __expf(m1 - mn1);
        float ps0 = 0.f, ps1 = 0.f;
        uint32_t pah[4][4], pal[4][4];
        #pragma unroll
        for (int nt = 0; nt < 8; ++nt) {
            float p0 = __expf(s[nt][0] - mn0);
            float p1 = __expf(s[nt][1] - mn0);
            float p2 = __expf(s[nt][2] - mn1);
            float p3 = __expf(s[nt][3] - mn1);
            ps0 += p0 + p1;
            ps1 += p2 + p3;
            int t = nt >> 1, q = nt & 1;
            split2(p0, p1, pah[t][q * 2 + 0], pal[t][q * 2 + 0]);
            split2(p2, p3, pah[t][q * 2 + 1], pal[t][q * 2 + 1]);
        }
        ps0 += __shfl_xor_sync(0xffffffffu, ps0, 1);
        ps0 += __shfl_xor_sync(0xffffffffu, ps0, 2);
        ps1 += __shfl_xor_sync(0xffffffffu, ps1, 1);
        ps1 += __shfl_xor_sync(0xffffffffu, ps1, 2);
        l0 = l0 * corr0 + ps0;
        l1 = l1 * corr1 + ps1;
        m0 = mn0; m1 = mn1;
        #pragma unroll
        for (int nt = 0; nt < 8; ++nt) {
            acc[nt][0] *= corr0; acc[nt][1] *= corr0;
            acc[nt][2] *= corr1; acc[nt][3] *= corr1;
        }

        // ---- O += P V (3-pass) ----
        #pragma unroll
        for (int ks = 0; ks < 4; ++ks) {
            uint32_t vh[4][4], vl[4][4];
            #pragma unroll
            for (int g = 0; g < 4; ++g) {
                uint32_t ro = (uint32_t)((g * 16 + (lane & 15)) * 144 + ks * 32 + ((lane >> 4) << 4));
                LDSM_X4(vh[g][0], vh[g][1], vh[g][2], vh[g][3], aVH + ro);
                LDSM_X4(vl[g][0], vl[g][1], vl[g][2], vl[g][3], aVL + ro);
            }
            #pragma unroll
            for (int g = 0; g < 4; ++g) {
                #pragma unroll
                for (int p = 0; p < 2; ++p) {
                    int nt = g * 2 + p;
                    mma_bf16(acc[nt], pah[ks], vh[g][p], vh[g][p + 2]);
                    mma_bf16(acc[nt], pah[ks], vl[g][p], vl[g][p + 2]);
                    mma_bf16(acc[nt], pal[ks], vh[g][p], vh[g][p + 2]);
                }
            }
        }

        __syncthreads();      // all reads of this stage done
        if (kt + 1 < nkt) {
            if (kt + 2 < nkt) { prefetch_kv(kt + 2, kt & 1); CP_COMMIT(); CP_WAIT1(); }
            else              { CP_WAIT0(); }
            __syncthreads();
        }
    }

    // ---- epilogue ----
    float inv0 = 1.f / l0, inv1 = 1.f / l1;
    size_t r0o = (size_t)(b * S_ + row0g) * HID + h * HD;
    size_t r1o = r0o + (size_t)8 * HID;
    #pragma unroll
    for (int nt = 0; nt < 8; ++nt) {
        int d = nt * 8 + (lane & 3) * 2;
        uint32_t hh, ll;
        split2(acc[nt][0] * inv0, acc[nt][1] * inv0, hh, ll);
        *reinterpret_cast<uint32_t*>(athi + r0o + d) = hh;
        *reinterpret_cast<uint32_t*>(atlo + r0o + d) = ll;
        split2(acc[nt][2] * inv1, acc[nt][3] * inv1, hh, ll);
        *reinterpret_cast<uint32_t*>(athi + r1o + d) = hh;
        *reinterpret_cast<uint32_t*>(atlo + r1o + d) = ll;
    }
}

// ---------------------------------------------------------------------------
// kernel_launch
// ---------------------------------------------------------------------------
extern "C" void kernel_launch(void* const* d_in, const int* in_sizes, int n_in,
                              void* d_out, int out_size)
{
    const float* hs    = (const float*)d_in[0];
    const int*   amask = (const int*)  d_in[1];
    const float* Wq    = (const float*)d_in[2];
    const float* bq    = (const float*)d_in[3];
    const float* Wk    = (const float*)d_in[4];
    const float* bk    = (const float*)d_in[5];
    const float* Wv    = (const float*)d_in[6];
    const float* bv    = (const float*)d_in[7];
    const float* Wo    = (const float*)d_in[8];
    const float* bo    = (const float*)d_in[9];
    float* out = (float*)d_out;

    float *qkvp, *biasp;
    cudaGetSymbolAddress((void**)&qkvp, g_qkv);
    cudaGetSymbolAddress((void**)&biasp, g_bias);
    __nv_bfloat16 *hshi, *hslo, *athi, *atlo, *wch, *wcl, *woh, *wol;
    cudaGetSymbolAddress((void**)&hshi, g_hs_hi);
    cudaGetSymbolAddress((void**)&hslo, g_hs_lo);
    cudaGetSymbolAddress((void**)&athi, g_at_hi);
    cudaGetSymbolAddress((void**)&atlo, g_at_lo);
    cudaGetSymbolAddress((void**)&wch, g_Wc_hi);
    cudaGetSymbolAddress((void**)&wcl, g_Wc_lo);
    cudaGetSymbolAddress((void**)&woh, g_Wo_hi);
    cudaGetSymbolAddress((void**)&wol, g_Wo_lo);

    cudaFuncSetAttribute(gemm_mma_kernel,
                         cudaFuncAttributeMaxDynamicSharedMemorySize, GEMM_SMEM);
    cudaFuncSetAttribute(attn_mma_kernel,
                         cudaFuncAttributeMaxDynamicSharedMemorySize, ATTN_SMEM);

    const int M = B_ * S_;
    const int nhs = M * HID;

    prep_weights_kernel<<<dim3(32, 32, 4), dim3(32, 8)>>>(Wq, Wk, Wv, Wo);
    split_kernel<<<(nhs + 255) / 256, 256>>>(hs, hshi, hslo, nhs);
    rope_table_kernel<<<(S_ * 32 + 255) / 256, 256>>>(bq, bk, bv);

    // fused QKV projection
    gemm_mma_kernel<<<dim3(NCAT / 128, M / 128), 256, GEMM_SMEM>>>(
        hshi, hslo, wch, wcl, biasp, qkvp, NCAT, HID);

    // RoPE -> bf16 hi/lo Q,K ; V transpose -> bf16 hi/lo
    int tot = B_ * S_ * (NH + NKV) * (HD / 2);
    rope_apply_kernel<<<(tot + 255) / 256, 256>>>();
    v_transpose_kernel<<<dim3(S_ / 64, NKV, B_), 256>>>();

    // attention (profiled launch)
    attn_mma_kernel<<<dim3(S_ / 64, NH, B_), 128, ATTN_SMEM>>>(amask, athi, atlo);

    // output projection
    gemm_mma_kernel<<<dim3(HID / 128, M / 128), 256, GEMM_SMEM>>>(
        athi, atlo, woh, wol, bo, out, HID, HID);
}

// round 6
// speedup vs baseline: 2.8327x; 1.0079x over previous
#include <cuda_runtime.h>
#include <cuda_bf16.h>
#include <cstdint>
#include <math.h>

#define B_    2
#define S_    2048
#define HID   1024
#define NH    16
#define NKV   4
#define HD    64
#define NCAT  1536            // 1024 (Q) + 256 (K) + 256 (V)

// ---------------------------------------------------------------------------
// Scratch (device globals)
// ---------------------------------------------------------------------------
__device__ float g_qkv[(size_t)B_ * S_ * NCAT];      // only V cols used now
__device__ float g_cos[S_ * 32];
__device__ float g_sin[S_ * 32];
__device__ float g_bias[NCAT];

__device__ __nv_bfloat16 g_hs_hi[(size_t)B_ * S_ * HID];
__device__ __nv_bfloat16 g_hs_lo[(size_t)B_ * S_ * HID];
__device__ __nv_bfloat16 g_at_hi[(size_t)B_ * S_ * HID];
__device__ __nv_bfloat16 g_at_lo[(size_t)B_ * S_ * HID];
__device__ __nv_bfloat16 g_Wc_hi[NCAT * HID];
__device__ __nv_bfloat16 g_Wc_lo[NCAT * HID];
__device__ __nv_bfloat16 g_Wo_hi[HID * HID];
__device__ __nv_bfloat16 g_Wo_lo[HID * HID];

// post-rope bf16 hi/lo tensors for attention
__device__ __nv_bfloat16 g_Qh[(size_t)B_ * S_ * HID];        // [4096,1024]
__device__ __nv_bfloat16 g_Ql[(size_t)B_ * S_ * HID];
__device__ __nv_bfloat16 g_Kh[(size_t)B_ * S_ * NKV * HD];   // [4096,256]
__device__ __nv_bfloat16 g_Kl[(size_t)B_ * S_ * NKV * HD];
__device__ __nv_bfloat16 g_Vth[(size_t)B_ * NKV * HD * S_];  // [b,kvh,d,s]
__device__ __nv_bfloat16 g_Vtl[(size_t)B_ * NKV * HD * S_];

// ---------------------------------------------------------------------------
// helpers
// ---------------------------------------------------------------------------
__device__ __forceinline__ uint32_t smem_u32(const void* p) {
    uint32_t a;
    asm("{ .reg .u64 t; cvta.to.shared.u64 t, %1; cvt.u32.u64 %0, t; }" : "=r"(a) : "l"(p));
    return a;
}
#define LDSM_X4(r0, r1, r2, r3, addr) \
    asm volatile("ldmatrix.sync.aligned.m8n8.x4.shared.b16 {%0,%1,%2,%3}, [%4];" \
        : "=r"(r0), "=r"(r1), "=r"(r2), "=r"(r3) : "r"(addr))
#define CP_A16(dst, src) \
    asm volatile("cp.async.cg.shared.global [%0], [%1], 16;" :: "r"(dst), "l"(src))
#define CP_COMMIT() asm volatile("cp.async.commit_group;" ::: "memory")
#define CP_WAIT0()  asm volatile("cp.async.wait_group 0;" ::: "memory")
#define CP_WAIT1()  asm volatile("cp.async.wait_group 1;" ::: "memory")
#define CP_WAIT2()  asm volatile("cp.async.wait_group 2;" ::: "memory")

__device__ __forceinline__ void mma_bf16(float* d, const uint32_t* a,
                                         uint32_t b0, uint32_t b1) {
    asm volatile(
        "mma.sync.aligned.m16n8k16.row.col.f32.bf16.bf16.f32 "
        "{%0,%1,%2,%3}, {%4,%5,%6,%7}, {%8,%9}, {%0,%1,%2,%3};"
        : "+f"(d[0]), "+f"(d[1]), "+f"(d[2]), "+f"(d[3])
        : "r"(a[0]), "r"(a[1]), "r"(a[2]), "r"(a[3]), "r"(b0), "r"(b1));
}

__device__ __forceinline__ void split2(float x, float y, uint32_t& h, uint32_t& l) {
    __nv_bfloat162 hh = __floats2bfloat162_rn(x, y);
    float rx = x - __bfloat162float(hh.x);
    float ry = y - __bfloat162float(hh.y);
    __nv_bfloat162 ll = __floats2bfloat162_rn(rx, ry);
    h = *reinterpret_cast<uint32_t*>(&hh);
    l = *reinterpret_cast<uint32_t*>(&ll);
}

// ---------------------------------------------------------------------------
// Weight prep: transpose + hi/lo split.  z=0:Wq z=1:Wk z=2:Wv z=3:Wo.
// ---------------------------------------------------------------------------
__global__ void prep_weights_kernel(const float* __restrict__ Wq,
                                    const float* __restrict__ Wk,
                                    const float* __restrict__ Wv,
                                    const float* __restrict__ Wo) {
    __shared__ float t[32][33];
    int z = blockIdx.z;
    const float* W;
    __nv_bfloat16 *hi, *lo;
    int N, rowoff;
    if (z == 0)      { W = Wq; N = HID; rowoff = 0;    hi = g_Wc_hi; lo = g_Wc_lo; }
    else if (z == 1) { W = Wk; N = 256; rowoff = 1024; hi = g_Wc_hi; lo = g_Wc_lo; }
    else if (z == 2) { W = Wv; N = 256; rowoff = 1280; hi = g_Wc_hi; lo = g_Wc_lo; }
    else             { W = Wo; N = HID; rowoff = 0;    hi = g_Wo_hi; lo = g_Wo_lo; }

    int n0 = blockIdx.x * 32, k0 = blockIdx.y * 32;
    if (n0 >= N) return;
    int x = threadIdx.x, y = threadIdx.y;
    #pragma unroll
    for (int yy = y; yy < 32; yy += 8)
        t[yy][x] = W[(size_t)(k0 + yy) * N + n0 + x];
    __syncthreads();
    #pragma unroll
    for (int yy = y; yy < 32; yy += 8) {
        float v = t[x][yy];
        __nv_bfloat16 h = __float2bfloat16(v);
        size_t o = (size_t)(rowoff + n0 + yy) * HID + k0 + x;
        hi[o] = h;
        lo[o] = __float2bfloat16(v - __bfloat162float(h));
    }
}

__global__ void split_kernel(const float* __restrict__ in,
                             __nv_bfloat16* __restrict__ hi,
                             __nv_bfloat16* __restrict__ lo, int n) {
    int i = blockIdx.x * blockDim.x + threadIdx.x;
    if (i >= n) return;
    float v = in[i];
    __nv_bfloat16 h = __float2bfloat16(v);
    hi[i] = h;
    lo[i] = __float2bfloat16(v - __bfloat162float(h));
}

// ---------------------------------------------------------------------------
// RoPE table + bias concat
// ---------------------------------------------------------------------------
__global__ void rope_table_kernel(const float* __restrict__ bq,
                                  const float* __restrict__ bk,
                                  const float* __restrict__ bv) {
    int idx = blockIdx.x * blockDim.x + threadIdx.x;
    if (idx < NCAT)
        g_bias[idx] = (idx < 1024) ? bq[idx] : (idx < 1280) ? bk[idx - 1024] : bv[idx - 1280];
    if (idx >= S_ * 32) return;
    int t = idx >> 5, j = idx & 31;
    double inv = exp2(-(double)j * 0.5190512648261507);
    float ang = (float)((double)t * inv);
    float s, c;
    sincosf(ang, &s, &c);
    g_cos[idx] = c;
    g_sin[idx] = s;
}

// ---------------------------------------------------------------------------
// GEMM via mma.sync, 3-stage cp.async, hi|lo packed 128B swizzled rows.
// MODE 0: C = A@W^T + bias (fp32). MODE 1: fused RoPE epilogue -> Qh/Ql/Kh/Kl
// bf16 for cols<1280, fp32 g_qkv for V cols.
// ---------------------------------------------------------------------------
#define GEMM_SMEM (3 * 32768)

template <int MODE>
__global__ __launch_bounds__(256, 2) void gemm_mma_kernel(
    const __nv_bfloat16* __restrict__ Ahi, const __nv_bfloat16* __restrict__ Alo,
    const __nv_bfloat16* __restrict__ Whi, const __nv_bfloat16* __restrict__ Wlo,
    const float* __restrict__ bias, float* __restrict__ C, int ldc, int K)
{
    extern __shared__ char smx[];
    const int tid = threadIdx.x, lane = tid & 31, wid = tid >> 5;
    const int wm = wid & 1, wn = wid >> 1;
    const int m0 = blockIdx.y * 128, n0 = blockIdx.x * 128;
    const uint32_t sbase = smem_u32(smx);

    float acc[4][4][4];
    #pragma unroll
    for (int a = 0; a < 4; a++)
        #pragma unroll
        for (int bb = 0; bb < 4; bb++)
            #pragma unroll
            for (int c = 0; c < 4; c++) acc[a][bb][c] = 0.f;

    // stage: A (128 rows x 128B [hi|lo]) @ +0, W @ +16384
    auto load_stage = [&](int ch, int st) {
        const uint32_t base = sbase + (uint32_t)st * 32768u;
        const int k0 = ch * 32;
        #pragma unroll
        for (int it = 0; it < 4; ++it) {
            int i = it * 256 + tid;
            int row = i >> 3, seg = i & 7;
            uint32_t so = (uint32_t)(row * 128 + ((seg ^ (row & 7)) << 4));
            const __nv_bfloat16* pa = (seg < 4) ? Ahi : Alo;
            const __nv_bfloat16* pw = (seg < 4) ? Whi : Wlo;
            CP_A16(base + so,          pa + (size_t)(m0 + row) * K + k0 + (seg & 3) * 8);
            CP_A16(base + 16384u + so, pw + (size_t)(n0 + row) * K + k0 + (seg & 3) * 8);
        }
    };

    const int NCH = K / 32;
    load_stage(0, 0); CP_COMMIT();
    if (NCH > 1) { load_stage(1, 1); CP_COMMIT(); }
    if (NCH > 2) { load_stage(2, 2); CP_COMMIT(); }

    int st = 0;
    for (int ch = 0; ch < NCH; ++ch) {
        const int rem = NCH - 1 - ch;
        if (rem >= 2) CP_WAIT2(); else if (rem == 1) CP_WAIT1(); else CP_WAIT0();
        __syncthreads();

        const uint32_t sA = sbase + (uint32_t)st * 32768u;
        const uint32_t sW = sA + 16384u;

        #pragma unroll
        for (int ks = 0; ks < 2; ++ks) {
            const int colh = ks * 2 + (lane >> 4);
            const int coll = colh + 4;
            uint32_t ah[4][4], al[4][4], bh[2][4], bl[2][4];
            #pragma unroll
            for (int mi = 0; mi < 4; ++mi) {
                int row = wm * 64 + mi * 16 + (lane & 15);
                uint32_t rb = sA + row * 128;
                LDSM_X4(ah[mi][0], ah[mi][1], ah[mi][2], ah[mi][3], rb + ((colh ^ (row & 7)) << 4));
                LDSM_X4(al[mi][0], al[mi][1], al[mi][2], al[mi][3], rb + ((coll ^ (row & 7)) << 4));
            }
            #pragma unroll
            for (int g = 0; g < 2; ++g) {
                int row = wn * 32 + g * 16 + (lane & 15);
                uint32_t rb = sW + row * 128;
                LDSM_X4(bh[g][0], bh[g][1], bh[g][2], bh[g][3], rb + ((colh ^ (row & 7)) << 4));
                LDSM_X4(bl[g][0], bl[g][1], bl[g][2], bl[g][3], rb + ((coll ^ (row & 7)) << 4));
            }
            #pragma unroll
            for (int mi = 0; mi < 4; ++mi) {
                #pragma unroll
                for (int j = 0; j < 4; ++j) {
                    const int g = j >> 1, p = j & 1;
                    mma_bf16(acc[mi][j], ah[mi], bh[g][p], bh[g][p + 2]);
                    mma_bf16(acc[mi][j], ah[mi], bl[g][p], bl[g][p + 2]);
                    mma_bf16(acc[mi][j], al[mi], bh[g][p], bh[g][p + 2]);
                }
            }
        }
        __syncthreads();
        if (ch + 3 < NCH) { load_stage(ch + 3, st); CP_COMMIT(); }
        st = (st == 2) ? 0 : st + 1;
    }

    // epilogue
    #pragma unroll
    for (int mi = 0; mi < 4; ++mi) {
        const int r = m0 + wm * 64 + mi * 16 + (lane >> 2);
        #pragma unroll
        for (int j = 0; j < 4; ++j) {
            const int col = n0 + wn * 32 + j * 8 + (lane & 3) * 2;
            const float b0 = bias[col], b1 = bias[col + 1];
            float x0 = acc[mi][j][0] + b0, x1 = acc[mi][j][1] + b1;
            float x2 = acc[mi][j][2] + b0, x3 = acc[mi][j][3] + b1;
            if (MODE == 0) {
                *reinterpret_cast<float2*>(C + (size_t)r * ldc + col) = make_float2(x0, x1);
                *reinterpret_cast<float2*>(C + (size_t)(r + 8) * ldc + col) = make_float2(x2, x3);
            } else {
                if (col < 1280) {
                    const int pos0 = r & (S_ - 1), pos1 = (r + 8) & (S_ - 1);
                    const int j0 = col & 31;
                    float2 cc0 = *reinterpret_cast<const float2*>(&g_cos[pos0 * 32 + j0]);
                    float2 ss0 = *reinterpret_cast<const float2*>(&g_sin[pos0 * 32 + j0]);
                    float2 cc1 = *reinterpret_cast<const float2*>(&g_cos[pos1 * 32 + j0]);
                    float2 ss1 = *reinterpret_cast<const float2*>(&g_sin[pos1 * 32 + j0]);
                    float y0 = x0 * cc0.x - x1 * ss0.x;
                    float y1 = x1 * cc0.y + x0 * ss0.y;
                    float y2 = x2 * cc1.x - x3 * ss1.x;
                    float y3 = x3 * cc1.y + x2 * ss1.y;
                    uint32_t hh, ll;
                    if (col < 1024) {
                        uint32_t* oh = reinterpret_cast<uint32_t*>(g_Qh);
                        uint32_t* ol = reinterpret_cast<uint32_t*>(g_Ql);
                        size_t w0 = (size_t)r * 512 + (col >> 1);
                        size_t w1 = (size_t)(r + 8) * 512 + (col >> 1);
                        split2(y0, y1, hh, ll); oh[w0] = hh; ol[w0] = ll;
                        split2(y2, y3, hh, ll); oh[w1] = hh; ol[w1] = ll;
                    } else {
                        uint32_t* oh = reinterpret_cast<uint32_t*>(g_Kh);
                        uint32_t* ol = reinterpret_cast<uint32_t*>(g_Kl);
                        size_t w0 = (size_t)r * 128 + ((col - 1024) >> 1);
                        size_t w1 = (size_t)(r + 8) * 128 + ((col - 1024) >> 1);
                        split2(y0, y1, hh, ll); oh[w0] = hh; ol[w0] = ll;
                        split2(y2, y3, hh, ll); oh[w1] = hh; ol[w1] = ll;
                    }
                } else {
                    *reinterpret_cast<float2*>(&g_qkv[(size_t)r * NCAT + col]) = make_float2(x0, x1);
                    *reinterpret_cast<float2*>(&g_qkv[(size_t)(r + 8) * NCAT + col]) = make_float2(x2, x3);
                }
            }
        }
    }
}

// ---------------------------------------------------------------------------
// V transpose + split: g_qkv V cols -> Vt[b][kvh][d][s] bf16 hi/lo
// ---------------------------------------------------------------------------
__global__ void v_transpose_kernel() {
    __shared__ float t[64][65];
    const int s0 = blockIdx.x * 64, kvh = blockIdx.y, b = blockIdx.z;
    const int tid = threadIdx.x;
    #pragma unroll
    for (int it = 0; it < 16; ++it) {
        int i = it * 256 + tid;
        int sl = i >> 6, d = i & 63;
        t[sl][d] = g_qkv[(size_t)(b * S_ + s0 + sl) * NCAT + 1280 + kvh * HD + d];
    }
    __syncthreads();
    #pragma unroll
    for (int it = 0; it < 16; ++it) {
        int i = it * 256 + tid;
        int d = i >> 6, sl = i & 63;
        float v = t[sl][d];
        __nv_bfloat16 h = __float2bfloat16(v);
        size_t o = ((size_t)(b * NKV + kvh) * HD + d) * S_ + s0 + sl;
        g_Vth[o] = h;
        g_Vtl[o] = __float2bfloat16(v - __bfloat162float(h));
    }
}

// ---------------------------------------------------------------------------
// Flash attention: 128-query CTA, 8 warps, hi|lo packed 256B swizzled rows,
// 2-stage cp.async K/V pipeline.
// ---------------------------------------------------------------------------
#define AQ_OFF  0                         // 128 rows x 256B = 32768
#define AST_OFF 32768                     // 2 stages x (K 16384 + V 16384)
#define AAM_OFF (32768 + 2 * 32768)       // mask 8192
#define ATTN_SMEM (AAM_OFF + S_ * 4)

__global__ __launch_bounds__(256, 2) void attn_mma_kernel(
    const int* __restrict__ amask,
    __nv_bfloat16* __restrict__ athi, __nv_bfloat16* __restrict__ atlo)
{
    extern __shared__ char sm[];
    const uint32_t sb = smem_u32(sm);
    int* am = reinterpret_cast<int*>(sm + AAM_OFF);

    const int tid = threadIdx.x, lane = tid & 31, w = tid >> 5;
    const int qi = blockIdx.x, h = blockIdx.y, b = blockIdx.z;
    const int q0 = qi * 128, kvh = h >> 2;
    const int nkt = 2 * qi + 2;

    // mask row for this batch
    #pragma unroll
    for (int it = 0; it < 8; ++it)
        am[it * 256 + tid] = amask[b * S_ + it * 256 + tid];

    // Q tile: 128 rows x 16 segs (hi segs 0-7, lo segs 8-15)
    {
        const __nv_bfloat16* qh = g_Qh + (size_t)(b * S_ + q0) * HID + h * HD;
        const __nv_bfloat16* ql = g_Ql + (size_t)(b * S_ + q0) * HID + h * HD;
        #pragma unroll
        for (int it = 0; it < 8; ++it) {
            int i = it * 256 + tid;
            int row = i >> 4, seg = i & 15;
            uint32_t so = (uint32_t)(row * 256 + ((seg ^ (row & 7)) << 4));
            const __nv_bfloat16* p = (seg < 8) ? qh : ql;
            CP_A16(sb + AQ_OFF + so, p + (size_t)row * HID + (seg & 7) * 8);
        }
        CP_COMMIT();
    }

    auto prefetch_kv = [&](int kt, int st) {
        const int k0 = kt * 64;
        const uint32_t base = sb + AST_OFF + (uint32_t)st * 32768u;
        const __nv_bfloat16* kh = g_Kh + (size_t)(b * S_ + k0) * (NKV * HD) + kvh * HD;
        const __nv_bfloat16* kl = g_Kl + (size_t)(b * S_ + k0) * (NKV * HD) + kvh * HD;
        const __nv_bfloat16* vh = g_Vth + ((size_t)(b * NKV + kvh) * HD) * S_ + k0;
        const __nv_bfloat16* vl = g_Vtl + ((size_t)(b * NKV + kvh) * HD) * S_ + k0;
        #pragma unroll
        for (int it = 0; it < 4; ++it) {
            int i = it * 256 + tid;
            int row = i >> 4, seg = i & 15;
            uint32_t so = (uint32_t)(row * 256 + ((seg ^ (row & 7)) << 4));
            const __nv_bfloat16* pk = (seg < 8) ? kh : kl;
            const __nv_bfloat16* pv = (seg < 8) ? vh : vl;
            CP_A16(base + so,           pk + (size_t)row * (NKV * HD) + (seg & 7) * 8);
            CP_A16(base + 16384u + so,  pv + (size_t)row * S_ + (seg & 7) * 8);
        }
    };

    prefetch_kv(0, 0); CP_COMMIT();
    if (nkt > 1) { prefetch_kv(1, 1); CP_COMMIT(); CP_WAIT1(); }
    else         { CP_WAIT0(); }
    __syncthreads();

    // preload Q fragments (whole kernel)
    uint32_t qfh[4][4], qfl[4][4];
    {
        int row = w * 16 + (lane & 15);
        uint32_t rb = sb + AQ_OFF + row * 256;
        #pragma unroll
        for (int ks = 0; ks < 4; ++ks) {
            int colh = ks * 2 + (lane >> 4);
            LDSM_X4(qfh[ks][0], qfh[ks][1], qfh[ks][2], qfh[ks][3], rb + ((colh ^ (row & 7)) << 4));
            LDSM_X4(qfl[ks][0], qfl[ks][1], qfl[ks][2], qfl[ks][3], rb + (((colh + 8) ^ (row & 7)) << 4));
        }
    }

    float acc[8][4];
    #pragma unroll
    for (int nt = 0; nt < 8; ++nt)
        #pragma unroll
        for (int c = 0; c < 4; ++c) acc[nt][c] = 0.f;
    float m0 = -1e30f, m1 = -1e30f, l0 = 0.f, l1 = 0.f;
    const int row0g = q0 + w * 16 + (lane >> 2);
    const int row1g = row0g + 8;

    for (int kt = 0; kt < nkt; ++kt) {
        const int k0 = kt * 64;
        const uint32_t stage = sb + AST_OFF + (uint32_t)(kt & 1) * 32768u;

        // ---- S = Q K^T (3-pass) ----
        float s[8][4];
        #pragma unroll
        for (int nt = 0; nt < 8; ++nt)
            #pragma unroll
            for (int c = 0; c < 4; ++c) s[nt][c] = 0.f;

        #pragma unroll
        for (int ks = 0; ks < 4; ++ks) {
            const int colh = ks * 2 + (lane >> 4);
            uint32_t bh[4][4], bl[4][4];
            #pragma unroll
            for (int g = 0; g < 4; ++g) {
                int row = g * 16 + (lane & 15);
                uint32_t rb = stage + row * 256;
                LDSM_X4(bh[g][0], bh[g][1], bh[g][2], bh[g][3], rb + ((colh ^ (row & 7)) << 4));
                LDSM_X4(bl[g][0], bl[g][1], bl[g][2], bl[g][3], rb + (((colh + 8) ^ (row & 7)) << 4));
            }
            #pragma unroll
            for (int g = 0; g < 4; ++g) {
                #pragma unroll
                for (int p = 0; p < 2; ++p) {
                    int nt = g * 2 + p;
                    mma_bf16(s[nt], qfh[ks], bh[g][p], bh[g][p + 2]);
                    mma_bf16(s[nt], qfh[ks], bl[g][p], bl[g][p + 2]);
                    mma_bf16(s[nt], qfl[ks], bh[g][p], bh[g][p + 2]);
                }
            }
        }

        // ---- scale + causal + key mask, online softmax ----
        float mt0 = -1e30f, mt1 = -1e30f;
        #pragma unroll
        for (int nt = 0; nt < 8; ++nt) {
            int cl = nt * 8 + (lane & 3) * 2;
            int cg0 = k0 + cl, cg1 = cg0 + 1;
            bool ok0 = am[cg0] != 0, ok1 = am[cg1] != 0;
            s[nt][0] = (ok0 && cg0 <= row0g) ? s[nt][0] * 0.125f : -1e30f;
            s[nt][1] = (ok1 && cg1 <= row0g) ? s[nt][1] * 0.125f : -1e30f;
            s[nt][2] = (ok0 && cg0 <= row1g) ? s[nt][2] * 0.125f : -1e30f;
            s[nt][3] = (ok1 && cg1 <= row1g) ? s[nt][3] * 0.125f : -1e30f;
            mt0 = fmaxf(mt0, fmaxf(s[nt][0], s[nt][1]));
            mt1 = fmaxf(mt1, fmaxf(s[nt][2], s[nt][3]));
        }
        mt0 = fmaxf(mt0, __shfl_xor_sync(0xffffffffu, mt0, 1));
        mt0 = fmaxf(mt0, __shfl_xor_sync(0xffffffffu, mt0, 2));
        mt1 = fmaxf(mt1, __shfl_xor_sync(0xffffffffu, mt1, 1));
        mt1 = fmaxf(mt1, __shfl_xor_sync(0xffffffffu, mt1, 2));

        float mn0 = fmaxf(m0, mt0), mn1 = fmaxf(m1, mt1);
        float corr0 = __expf(m0 - mn0), corr1 = __expf(m1 - mn1);
        float ps0 = 0.f, ps1 = 0.f;
        uint32_t pah[4][4], pal[4][4];
        #pragma unroll
        for (int nt = 0; nt < 8; ++nt) {
            float p0 = __expf(s[nt][0] - mn0);
            float p1 = __expf(s[nt][1] - mn0);
            float p2 = __expf(s[nt][2] - mn1);
            float p3 = __expf(s[nt][3] - mn1);
            ps0 += p0 + p1;
            ps1 += p2 + p3;
            int t = nt >> 1, q = nt & 1;
            split2(p0, p1, pah[t][q * 2 + 0], pal[t][q * 2 + 0]);
            split2(p2, p3, pah[t][q * 2 + 1], pal[t][q * 2 + 1]);
        }
        ps0 += __shfl_xor_sync(0xffffffffu, ps0, 1);
        ps0 += __shfl_xor_sync(0xffffffffu, ps0, 2);
        ps1 += __shfl_xor_sync(0xffffffffu, ps1, 1);
        ps1 += __shfl_xor_sync(0xffffffffu, ps1, 2);
        l0 = l0 * corr0 + ps0;
        l1 = l1 * corr1 + ps1;
        m0 = mn0; m1 = mn1;
        #pragma unroll
        for (int nt = 0; nt < 8; ++nt) {
            acc[nt][0] *= corr0; acc[nt][1] *= corr0;
            acc[nt][2] *= corr1; acc[nt][3] *= corr1;
        }

        // ---- O += P V (3-pass), V rows are d with keys packed hi|lo ----
        const uint32_t vstage = stage + 16384u;
        #pragma unroll
        for (int ks = 0; ks < 4; ++ks) {
            const int colh = ks * 2 + (lane >> 4);
            uint32_t vh[4][4], vl[4][4];
            #pragma unroll
            for (int g = 0; g < 4; ++g) {
                int row = g * 16 + (lane & 15);
                uint32_t rb = vstage + row * 256;
                LDSM_X4(vh[g][0], vh[g][1], vh[g][2], vh[g][3], rb + ((colh ^ (row & 7)) << 4));
                LDSM_X4(vl[g][0], vl[g][1], vl[g][2], vl[g][3], rb + (((colh + 8) ^ (row & 7)) << 4));
            }
            #pragma unroll
            for (int g = 0; g < 4; ++g) {
                #pragma unroll
                for (int p = 0; p < 2; ++p) {
                    int nt = g * 2 + p;
                    mma_bf16(acc[nt], pah[ks], vh[g][p], vh[g][p + 2]);
                    mma_bf16(acc[nt], pah[ks], vl[g][p], vl[g][p + 2]);
                    mma_bf16(acc[nt], pal[ks], vh[g][p], vh[g][p + 2]);
                }
            }
        }

        __syncthreads();
        if (kt + 1 < nkt) {
            if (kt + 2 < nkt) { prefetch_kv(kt + 2, kt & 1); CP_COMMIT(); CP_WAIT1(); }
            else              { CP_WAIT0(); }
            __syncthreads();
        }
    }

    // ---- epilogue ----
    float inv0 = 1.f / l0, inv1 = 1.f / l1;
    size_t r0o = (size_t)(b * S_ + row0g) * HID + h * HD;
    size_t r1o = r0o + (size_t)8 * HID;
    #pragma unroll
    for (int nt = 0; nt < 8; ++nt) {
        int d = nt * 8 + (lane & 3) * 2;
        uint32_t hh, ll;
        split2(acc[nt][0] * inv0, acc[nt][1] * inv0, hh, ll);
        *reinterpret_cast<uint32_t*>(athi + r0o + d) = hh;
        *reinterpret_cast<uint32_t*>(atlo + r0o + d) = ll;
        split2(acc[nt][2] * inv1, acc[nt][3] * inv1, hh, ll);
        *reinterpret_cast<uint32_t*>(athi + r1o + d) = hh;
        *reinterpret_cast<uint32_t*>(atlo + r1o + d) = ll;
    }
}

// ---------------------------------------------------------------------------
// kernel_launch
// ---------------------------------------------------------------------------
extern "C" void kernel_launch(void* const* d_in, const int* in_sizes, int n_in,
                              void* d_out, int out_size)
{
    const float* hs    = (const float*)d_in[0];
    const int*   amask = (const int*)  d_in[1];
    const float* Wq    = (const float*)d_in[2];
    const float* bq    = (const float*)d_in[3];
    const float* Wk    = (const float*)d_in[4];
    const float* bk    = (const float*)d_in[5];
    const float* Wv    = (const float*)d_in[6];
    const float* bv    = (const float*)d_in[7];
    const float* Wo    = (const float*)d_in[8];
    const float* bo    = (const float*)d_in[9];
    float* out = (float*)d_out;

    float *qkvp, *biasp;
    cudaGetSymbolAddress((void**)&qkvp, g_qkv);
    cudaGetSymbolAddress((void**)&biasp, g_bias);
    __nv_bfloat16 *hshi, *hslo, *athi, *atlo, *wch, *wcl, *woh, *wol;
    cudaGetSymbolAddress((void**)&hshi, g_hs_hi);
    cudaGetSymbolAddress((void**)&hslo, g_hs_lo);
    cudaGetSymbolAddress((void**)&athi, g_at_hi);
    cudaGetSymbolAddress((void**)&atlo, g_at_lo);
    cudaGetSymbolAddress((void**)&wch, g_Wc_hi);
    cudaGetSymbolAddress((void**)&wcl, g_Wc_lo);
    cudaGetSymbolAddress((void**)&woh, g_Wo_hi);
    cudaGetSymbolAddress((void**)&wol, g_Wo_lo);

    cudaFuncSetAttribute(gemm_mma_kernel<0>,
                         cudaFuncAttributeMaxDynamicSharedMemorySize, GEMM_SMEM);
    cudaFuncSetAttribute(gemm_mma_kernel<1>,
                         cudaFuncAttributeMaxDynamicSharedMemorySize, GEMM_SMEM);
    cudaFuncSetAttribute(attn_mma_kernel,
                         cudaFuncAttributeMaxDynamicSharedMemorySize, ATTN_SMEM);

    const int M = B_ * S_;
    const int nhs = M * HID;

    prep_weights_kernel<<<dim3(32, 32, 4), dim3(32, 8)>>>(Wq, Wk, Wv, Wo);
    split_kernel<<<(nhs + 255) / 256, 256>>>(hs, hshi, hslo, nhs);
    rope_table_kernel<<<(S_ * 32 + 255) / 256, 256>>>(bq, bk, bv);

    // fused QKV projection + RoPE + bf16 split (Q,K) / fp32 (V)
    gemm_mma_kernel<1><<<dim3(NCAT / 128, M / 128), 256, GEMM_SMEM>>>(
        hshi, hslo, wch, wcl, biasp, qkvp, NCAT, HID);

    // V transpose -> bf16 hi/lo
    v_transpose_kernel<<<dim3(S_ / 64, NKV, B_), 256>>>();

    // attention (profiled launch)
    attn_mma_kernel<<<dim3(S_ / 128, NH, B_), 256, ATTN_SMEM>>>(amask, athi, atlo);

    // output projection
    gemm_mma_kernel<0><<<dim3(HID / 128, M / 128), 256, GEMM_SMEM>>>(
        athi, atlo, woh, wol, bo, out, HID, HID);
}

// round 7
// speedup vs baseline: 3.1490x; 1.1117x over previous
#include <cuda_runtime.h>
#include <cuda_bf16.h>
#include <cstdint>
#include <math.h>

#define B_    2
#define S_    2048
#define HID   1024
#define NH    16
#define NKV   4
#define HD    64
#define NCAT  1536            // 1024 (Q) + 256 (K) + 256 (V)

// ---------------------------------------------------------------------------
// Scratch (device globals)
// ---------------------------------------------------------------------------
__device__ float g_qkv[(size_t)B_ * S_ * NCAT];      // only V cols used now
__device__ float g_cos[S_ * 32];
__device__ float g_sin[S_ * 32];
__device__ float g_bias[NCAT];

__device__ __nv_bfloat16 g_hs_hi[(size_t)B_ * S_ * HID];
__device__ __nv_bfloat16 g_hs_lo[(size_t)B_ * S_ * HID];
__device__ __nv_bfloat16 g_at_hi[(size_t)B_ * S_ * HID];
__device__ __nv_bfloat16 g_at_lo[(size_t)B_ * S_ * HID];
__device__ __nv_bfloat16 g_Wc_hi[NCAT * HID];
__device__ __nv_bfloat16 g_Wc_lo[NCAT * HID];
__device__ __nv_bfloat16 g_Wo_hi[HID * HID];
__device__ __nv_bfloat16 g_Wo_lo[HID * HID];

// post-rope bf16 hi/lo tensors for attention
__device__ __nv_bfloat16 g_Qh[(size_t)B_ * S_ * HID];
__device__ __nv_bfloat16 g_Ql[(size_t)B_ * S_ * HID];
__device__ __nv_bfloat16 g_Kh[(size_t)B_ * S_ * NKV * HD];
__device__ __nv_bfloat16 g_Kl[(size_t)B_ * S_ * NKV * HD];
__device__ __nv_bfloat16 g_Vth[(size_t)B_ * NKV * HD * S_];  // [b,kvh,d,s]
__device__ __nv_bfloat16 g_Vtl[(size_t)B_ * NKV * HD * S_];

// ---------------------------------------------------------------------------
// helpers
// ---------------------------------------------------------------------------
__device__ __forceinline__ uint32_t smem_u32(const void* p) {
    uint32_t a;
    asm("{ .reg .u64 t; cvta.to.shared.u64 t, %1; cvt.u32.u64 %0, t; }" : "=r"(a) : "l"(p));
    return a;
}
#define LDSM_X4(r0, r1, r2, r3, addr) \
    asm volatile("ldmatrix.sync.aligned.m8n8.x4.shared.b16 {%0,%1,%2,%3}, [%4];" \
        : "=r"(r0), "=r"(r1), "=r"(r2), "=r"(r3) : "r"(addr))
#define CP_A16(dst, src) \
    asm volatile("cp.async.cg.shared.global [%0], [%1], 16;" :: "r"(dst), "l"(src))
#define CP_COMMIT() asm volatile("cp.async.commit_group;" ::: "memory")
#define CP_WAIT0()  asm volatile("cp.async.wait_group 0;" ::: "memory")
#define CP_WAIT1()  asm volatile("cp.async.wait_group 1;" ::: "memory")
#define CP_WAIT2()  asm volatile("cp.async.wait_group 2;" ::: "memory")

__device__ __forceinline__ void mma_bf16(float* d, const uint32_t* a,
                                         uint32_t b0, uint32_t b1) {
    asm volatile(
        "mma.sync.aligned.m16n8k16.row.col.f32.bf16.bf16.f32 "
        "{%0,%1,%2,%3}, {%4,%5,%6,%7}, {%8,%9}, {%0,%1,%2,%3};"
        : "+f"(d[0]), "+f"(d[1]), "+f"(d[2]), "+f"(d[3])
        : "r"(a[0]), "r"(a[1]), "r"(a[2]), "r"(a[3]), "r"(b0), "r"(b1));
}

__device__ __forceinline__ void split2(float x, float y, uint32_t& h, uint32_t& l) {
    __nv_bfloat162 hh = __floats2bfloat162_rn(x, y);
    float rx = x - __bfloat162float(hh.x);
    float ry = y - __bfloat162float(hh.y);
    __nv_bfloat162 ll = __floats2bfloat162_rn(rx, ry);
    h = *reinterpret_cast<uint32_t*>(&hh);
    l = *reinterpret_cast<uint32_t*>(&ll);
}

// ---------------------------------------------------------------------------
// Weight prep: transpose + hi/lo split.  z=0:Wq z=1:Wk z=2:Wv z=3:Wo.
// ---------------------------------------------------------------------------
__global__ void prep_weights_kernel(const float* __restrict__ Wq,
                                    const float* __restrict__ Wk,
                                    const float* __restrict__ Wv,
                                    const float* __restrict__ Wo) {
    __shared__ float t[32][33];
    int z = blockIdx.z;
    const float* W;
    __nv_bfloat16 *hi, *lo;
    int N, rowoff;
    if (z == 0)      { W = Wq; N = HID; rowoff = 0;    hi = g_Wc_hi; lo = g_Wc_lo; }
    else if (z == 1) { W = Wk; N = 256; rowoff = 1024; hi = g_Wc_hi; lo = g_Wc_lo; }
    else if (z == 2) { W = Wv; N = 256; rowoff = 1280; hi = g_Wc_hi; lo = g_Wc_lo; }
    else             { W = Wo; N = HID; rowoff = 0;    hi = g_Wo_hi; lo = g_Wo_lo; }

    int n0 = blockIdx.x * 32, k0 = blockIdx.y * 32;
    if (n0 >= N) return;
    int x = threadIdx.x, y = threadIdx.y;
    #pragma unroll
    for (int yy = y; yy < 32; yy += 8)
        t[yy][x] = W[(size_t)(k0 + yy) * N + n0 + x];
    __syncthreads();
    #pragma unroll
    for (int yy = y; yy < 32; yy += 8) {
        float v = t[x][yy];
        __nv_bfloat16 h = __float2bfloat16(v);
        size_t o = (size_t)(rowoff + n0 + yy) * HID + k0 + x;
        hi[o] = h;
        lo[o] = __float2bfloat16(v - __bfloat162float(h));
    }
}

__global__ void split_kernel(const float* __restrict__ in,
                             __nv_bfloat16* __restrict__ hi,
                             __nv_bfloat16* __restrict__ lo, int n) {
    int i = blockIdx.x * blockDim.x + threadIdx.x;
    if (i >= n) return;
    float v = in[i];
    __nv_bfloat16 h = __float2bfloat16(v);
    hi[i] = h;
    lo[i] = __float2bfloat16(v - __bfloat162float(h));
}

// ---------------------------------------------------------------------------
// RoPE table + bias concat
// ---------------------------------------------------------------------------
__global__ void rope_table_kernel(const float* __restrict__ bq,
                                  const float* __restrict__ bk,
                                  const float* __restrict__ bv) {
    int idx = blockIdx.x * blockDim.x + threadIdx.x;
    if (idx < NCAT)
        g_bias[idx] = (idx < 1024) ? bq[idx] : (idx < 1280) ? bk[idx - 1024] : bv[idx - 1280];
    if (idx >= S_ * 32) return;
    int t = idx >> 5, j = idx & 31;
    double inv = exp2(-(double)j * 0.5190512648261507);
    float ang = (float)((double)t * inv);
    float s, c;
    sincosf(ang, &s, &c);
    g_cos[idx] = c;
    g_sin[idx] = s;
}

// ---------------------------------------------------------------------------
// GEMM via mma.sync, 3-stage cp.async, hi|lo packed 128B swizzled rows.
// MODE 0: C = A@W^T + bias (fp32). MODE 1: fused RoPE epilogue.
// ---------------------------------------------------------------------------
#define GEMM_SMEM (3 * 32768)

template <int MODE>
__global__ __launch_bounds__(256, 2) void gemm_mma_kernel(
    const __nv_bfloat16* __restrict__ Ahi, const __nv_bfloat16* __restrict__ Alo,
    const __nv_bfloat16* __restrict__ Whi, const __nv_bfloat16* __restrict__ Wlo,
    const float* __restrict__ bias, float* __restrict__ C, int ldc, int K)
{
    extern __shared__ char smx[];
    const int tid = threadIdx.x, lane = tid & 31, wid = tid >> 5;
    const int wm = wid & 1, wn = wid >> 1;
    const int m0 = blockIdx.y * 128, n0 = blockIdx.x * 128;
    const uint32_t sbase = smem_u32(smx);

    float acc[4][4][4];
    #pragma unroll
    for (int a = 0; a < 4; a++)
        #pragma unroll
        for (int bb = 0; bb < 4; bb++)
            #pragma unroll
            for (int c = 0; c < 4; c++) acc[a][bb][c] = 0.f;

    auto load_stage = [&](int ch, int st) {
        const uint32_t base = sbase + (uint32_t)st * 32768u;
        const int k0 = ch * 32;
        #pragma unroll
        for (int it = 0; it < 4; ++it) {
            int i = it * 256 + tid;
            int row = i >> 3, seg = i & 7;
            uint32_t so = (uint32_t)(row * 128 + ((seg ^ (row & 7)) << 4));
            const __nv_bfloat16* pa = (seg < 4) ? Ahi : Alo;
            const __nv_bfloat16* pw = (seg < 4) ? Whi : Wlo;
            CP_A16(base + so,          pa + (size_t)(m0 + row) * K + k0 + (seg & 3) * 8);
            CP_A16(base + 16384u + so, pw + (size_t)(n0 + row) * K + k0 + (seg & 3) * 8);
        }
    };

    const int NCH = K / 32;
    load_stage(0, 0); CP_COMMIT();
    if (NCH > 1) { load_stage(1, 1); CP_COMMIT(); }
    if (NCH > 2) { load_stage(2, 2); CP_COMMIT(); }

    int st = 0;
    for (int ch = 0; ch < NCH; ++ch) {
        const int rem = NCH - 1 - ch;
        if (rem >= 2) CP_WAIT2(); else if (rem == 1) CP_WAIT1(); else CP_WAIT0();
        __syncthreads();

        const uint32_t sA = sbase + (uint32_t)st * 32768u;
        const uint32_t sW = sA + 16384u;

        #pragma unroll
        for (int ks = 0; ks < 2; ++ks) {
            const int colh = ks * 2 + (lane >> 4);
            const int coll = colh + 4;
            uint32_t ah[4][4], al[4][4], bh[2][4], bl[2][4];
            #pragma unroll
            for (int mi = 0; mi < 4; ++mi) {
                int row = wm * 64 + mi * 16 + (lane & 15);
                uint32_t rb = sA + row * 128;
                LDSM_X4(ah[mi][0], ah[mi][1], ah[mi][2], ah[mi][3], rb + ((colh ^ (row & 7)) << 4));
                LDSM_X4(al[mi][0], al[mi][1], al[mi][2], al[mi][3], rb + ((coll ^ (row & 7)) << 4));
            }
            #pragma unroll
            for (int g = 0; g < 2; ++g) {
                int row = wn * 32 + g * 16 + (lane & 15);
                uint32_t rb = sW + row * 128;
                LDSM_X4(bh[g][0], bh[g][1], bh[g][2], bh[g][3], rb + ((colh ^ (row & 7)) << 4));
                LDSM_X4(bl[g][0], bl[g][1], bl[g][2], bl[g][3], rb + ((coll ^ (row & 7)) << 4));
            }
            #pragma unroll
            for (int mi = 0; mi < 4; ++mi) {
                #pragma unroll
                for (int j = 0; j < 4; ++j) {
                    const int g = j >> 1, p = j & 1;
                    mma_bf16(acc[mi][j], ah[mi], bh[g][p], bh[g][p + 2]);
                    mma_bf16(acc[mi][j], ah[mi], bl[g][p], bl[g][p + 2]);
                    mma_bf16(acc[mi][j], al[mi], bh[g][p], bh[g][p + 2]);
                }
            }
        }
        __syncthreads();
        if (ch + 3 < NCH) { load_stage(ch + 3, st); CP_COMMIT(); }
        st = (st == 2) ? 0 : st + 1;
    }

    // epilogue
    #pragma unroll
    for (int mi = 0; mi < 4; ++mi) {
        const int r = m0 + wm * 64 + mi * 16 + (lane >> 2);
        #pragma unroll
        for (int j = 0; j < 4; ++j) {
            const int col = n0 + wn * 32 + j * 8 + (lane & 3) * 2;
            const float b0 = bias[col], b1 = bias[col + 1];
            float x0 = acc[mi][j][0] + b0, x1 = acc[mi][j][1] + b1;
            float x2 = acc[mi][j][2] + b0, x3 = acc[mi][j][3] + b1;
            if (MODE == 0) {
                *reinterpret_cast<float2*>(C + (size_t)r * ldc + col) = make_float2(x0, x1);
                *reinterpret_cast<float2*>(C + (size_t)(r + 8) * ldc + col) = make_float2(x2, x3);
            } else {
                if (col < 1280) {
                    const int pos0 = r & (S_ - 1), pos1 = (r + 8) & (S_ - 1);
                    const int j0 = col & 31;
                    float2 cc0 = *reinterpret_cast<const float2*>(&g_cos[pos0 * 32 + j0]);
                    float2 ss0 = *reinterpret_cast<const float2*>(&g_sin[pos0 * 32 + j0]);
                    float2 cc1 = *reinterpret_cast<const float2*>(&g_cos[pos1 * 32 + j0]);
                    float2 ss1 = *reinterpret_cast<const float2*>(&g_sin[pos1 * 32 + j0]);
                    float y0 = x0 * cc0.x - x1 * ss0.x;
                    float y1 = x1 * cc0.y + x0 * ss0.y;
                    float y2 = x2 * cc1.x - x3 * ss1.x;
                    float y3 = x3 * cc1.y + x2 * ss1.y;
                    uint32_t hh, ll;
                    if (col < 1024) {
                        uint32_t* oh = reinterpret_cast<uint32_t*>(g_Qh);
                        uint32_t* ol = reinterpret_cast<uint32_t*>(g_Ql);
                        size_t w0 = (size_t)r * 512 + (col >> 1);
                        size_t w1 = (size_t)(r + 8) * 512 + (col >> 1);
                        split2(y0, y1, hh, ll); oh[w0] = hh; ol[w0] = ll;
                        split2(y2, y3, hh, ll); oh[w1] = hh; ol[w1] = ll;
                    } else {
                        uint32_t* oh = reinterpret_cast<uint32_t*>(g_Kh);
                        uint32_t* ol = reinterpret_cast<uint32_t*>(g_Kl);
                        size_t w0 = (size_t)r * 128 + ((col - 1024) >> 1);
                        size_t w1 = (size_t)(r + 8) * 128 + ((col - 1024) >> 1);
                        split2(y0, y1, hh, ll); oh[w0] = hh; ol[w0] = ll;
                        split2(y2, y3, hh, ll); oh[w1] = hh; ol[w1] = ll;
                    }
                } else {
                    *reinterpret_cast<float2*>(&g_qkv[(size_t)r * NCAT + col]) = make_float2(x0, x1);
                    *reinterpret_cast<float2*>(&g_qkv[(size_t)(r + 8) * NCAT + col]) = make_float2(x2, x3);
                }
            }
        }
    }
}

// ---------------------------------------------------------------------------
// V transpose + split
// ---------------------------------------------------------------------------
__global__ void v_transpose_kernel() {
    __shared__ float t[64][65];
    const int s0 = blockIdx.x * 64, kvh = blockIdx.y, b = blockIdx.z;
    const int tid = threadIdx.x;
    #pragma unroll
    for (int it = 0; it < 16; ++it) {
        int i = it * 256 + tid;
        int sl = i >> 6, d = i & 63;
        t[sl][d] = g_qkv[(size_t)(b * S_ + s0 + sl) * NCAT + 1280 + kvh * HD + d];
    }
    __syncthreads();
    #pragma unroll
    for (int it = 0; it < 16; ++it) {
        int i = it * 256 + tid;
        int d = i >> 6, sl = i & 63;
        float v = t[sl][d];
        __nv_bfloat16 h = __float2bfloat16(v);
        size_t o = ((size_t)(b * NKV + kvh) * HD + d) * S_ + s0 + sl;
        g_Vth[o] = h;
        g_Vtl[o] = __float2bfloat16(v - __bfloat162float(h));
    }
}

// ---------------------------------------------------------------------------
// Flash attention, load-balanced: each CTA (pair p, head, batch) processes
// q-blocks {15-p, p} of 128 rows each -> uniform 34 key tiles per CTA,
// grid = 256 CTAs = one balanced wave at 2 CTAs/SM.
// ---------------------------------------------------------------------------
#define AQ_OFF  0                         // 128 rows x 256B = 32768
#define AST_OFF 32768                     // 2 stages x (K 16384 + V 16384)
#define AAM_OFF (32768 + 2 * 32768)       // mask 8192
#define ATTN_SMEM (AAM_OFF + S_ * 4)

__global__ __launch_bounds__(256, 2) void attn_mma_kernel(
    const int* __restrict__ amask,
    __nv_bfloat16* __restrict__ athi, __nv_bfloat16* __restrict__ atlo)
{
    extern __shared__ char sm[];
    const uint32_t sb = smem_u32(sm);
    int* am = reinterpret_cast<int*>(sm + AAM_OFF);

    const int tid = threadIdx.x, lane = tid & 31, w = tid >> 5;
    const int pr = blockIdx.x, h = blockIdx.y, b = blockIdx.z;
    const int kvh = h >> 2;

    // mask row for this batch
    #pragma unroll
    for (int it = 0; it < 8; ++it)
        am[it * 256 + tid] = amask[b * S_ + it * 256 + tid];

    auto prefetch_kv = [&](int kt, int st) {
        const int k0 = kt * 64;
        const uint32_t base = sb + AST_OFF + (uint32_t)st * 32768u;
        const __nv_bfloat16* kh = g_Kh + (size_t)(b * S_ + k0) * (NKV * HD) + kvh * HD;
        const __nv_bfloat16* kl = g_Kl + (size_t)(b * S_ + k0) * (NKV * HD) + kvh * HD;
        const __nv_bfloat16* vh = g_Vth + ((size_t)(b * NKV + kvh) * HD) * S_ + k0;
        const __nv_bfloat16* vl = g_Vtl + ((size_t)(b * NKV + kvh) * HD) * S_ + k0;
        #pragma unroll
        for (int it = 0; it < 4; ++it) {
            int i = it * 256 + tid;
            int row = i >> 4, seg = i & 15;
            uint32_t so = (uint32_t)(row * 256 + ((seg ^ (row & 7)) << 4));
            const __nv_bfloat16* pk = (seg < 8) ? kh : kl;
            const __nv_bfloat16* pv = (seg < 8) ? vh : vl;
            CP_A16(base + so,           pk + (size_t)row * (NKV * HD) + (seg & 7) * 8);
            CP_A16(base + 16384u + so,  pv + (size_t)row * S_ + (seg & 7) * 8);
        }
    };

    for (int half = 0; half < 2; ++half) {
        const int qb = half ? pr : (15 - pr);     // long block first
        const int q0 = qb * 128;
        const int nkt = 2 * qb + 2;

        // Q tile cp.async (hi segs 0-7, lo segs 8-15)
        {
            const __nv_bfloat16* qh = g_Qh + (size_t)(b * S_ + q0) * HID + h * HD;
            const __nv_bfloat16* ql = g_Ql + (size_t)(b * S_ + q0) * HID + h * HD;
            #pragma unroll
            for (int it = 0; it < 8; ++it) {
                int i = it * 256 + tid;
                int row = i >> 4, seg = i & 15;
                uint32_t so = (uint32_t)(row * 256 + ((seg ^ (row & 7)) << 4));
                const __nv_bfloat16* p = (seg < 8) ? qh : ql;
                CP_A16(sb + AQ_OFF + so, p + (size_t)row * HID + (seg & 7) * 8);
            }
            CP_COMMIT();
        }

        prefetch_kv(0, 0); CP_COMMIT();
        if (nkt > 1) { prefetch_kv(1, 1); CP_COMMIT(); CP_WAIT1(); }
        else         { CP_WAIT0(); }
        __syncthreads();

        // preload Q fragments for this q-block
        uint32_t qfh[4][4], qfl[4][4];
        {
            int row = w * 16 + (lane & 15);
            uint32_t rb = sb + AQ_OFF + row * 256;
            #pragma unroll
            for (int ks = 0; ks < 4; ++ks) {
                int colh = ks * 2 + (lane >> 4);
                LDSM_X4(qfh[ks][0], qfh[ks][1], qfh[ks][2], qfh[ks][3], rb + ((colh ^ (row & 7)) << 4));
                LDSM_X4(qfl[ks][0], qfl[ks][1], qfl[ks][2], qfl[ks][3], rb + (((colh + 8) ^ (row & 7)) << 4));
            }
        }

        float acc[8][4];
        #pragma unroll
        for (int nt = 0; nt < 8; ++nt)
            #pragma unroll
            for (int c = 0; c < 4; ++c) acc[nt][c] = 0.f;
        float m0 = -1e30f, m1 = -1e30f, l0 = 0.f, l1 = 0.f;
        const int row0g = q0 + w * 16 + (lane >> 2);
        const int row1g = row0g + 8;

        for (int kt = 0; kt < nkt; ++kt) {
            const int k0 = kt * 64;
            const uint32_t stage = sb + AST_OFF + (uint32_t)(kt & 1) * 32768u;

            // ---- S = Q K^T (3-pass) ----
            float s[8][4];
            #pragma unroll
            for (int nt = 0; nt < 8; ++nt)
                #pragma unroll
                for (int c = 0; c < 4; ++c) s[nt][c] = 0.f;

            #pragma unroll
            for (int ks = 0; ks < 4; ++ks) {
                const int colh = ks * 2 + (lane >> 4);
                uint32_t bh[4][4], bl[4][4];
                #pragma unroll
                for (int g = 0; g < 4; ++g) {
                    int row = g * 16 + (lane & 15);
                    uint32_t rb = stage + row * 256;
                    LDSM_X4(bh[g][0], bh[g][1], bh[g][2], bh[g][3], rb + ((colh ^ (row & 7)) << 4));
                    LDSM_X4(bl[g][0], bl[g][1], bl[g][2], bl[g][3], rb + (((colh + 8) ^ (row & 7)) << 4));
                }
                #pragma unroll
                for (int g = 0; g < 4; ++g) {
                    #pragma unroll
                    for (int p = 0; p < 2; ++p) {
                        int nt = g * 2 + p;
                        mma_bf16(s[nt], qfh[ks], bh[g][p], bh[g][p + 2]);
                        mma_bf16(s[nt], qfh[ks], bl[g][p], bl[g][p + 2]);
                        mma_bf16(s[nt], qfl[ks], bh[g][p], bh[g][p + 2]);
                    }
                }
            }

            // ---- scale + causal + key mask, online softmax ----
            float mt0 = -1e30f, mt1 = -1e30f;
            #pragma unroll
            for (int nt = 0; nt < 8; ++nt) {
                int cl = nt * 8 + (lane & 3) * 2;
                int cg0 = k0 + cl, cg1 = cg0 + 1;
                bool ok0 = am[cg0] != 0, ok1 = am[cg1] != 0;
                s[nt][0] = (ok0 && cg0 <= row0g) ? s[nt][0] * 0.125f : -1e30f;
                s[nt][1] = (ok1 && cg1 <= row0g) ? s[nt][1] * 0.125f : -1e30f;
                s[nt][2] = (ok0 && cg0 <= row1g) ? s[nt][2] * 0.125f : -1e30f;
                s[nt][3] = (ok1 && cg1 <= row1g) ? s[nt][3] * 0.125f : -1e30f;
                mt0 = fmaxf(mt0, fmaxf(s[nt][0], s[nt][1]));
                mt1 = fmaxf(mt1, fmaxf(s[nt][2], s[nt][3]));
            }
            mt0 = fmaxf(mt0, __shfl_xor_sync(0xffffffffu, mt0, 1));
            mt0 = fmaxf(mt0, __shfl_xor_sync(0xffffffffu, mt0, 2));
            mt1 = fmaxf(mt1, __shfl_xor_sync(0xffffffffu, mt1, 1));
            mt1 = fmaxf(mt1, __shfl_xor_sync(0xffffffffu, mt1, 2));

            float mn0 = fmaxf(m0, mt0), mn1 = fmaxf(m1, mt1);
            float corr0 = __expf(m0 - mn0), corr1 = __expf(m1 - mn1);
            float ps0 = 0.f, ps1 = 0.f;
            uint32_t pah[4][4], pal[4][4];
            #pragma unroll
            for (int nt = 0; nt < 8; ++nt) {
                float p0 = __expf(s[nt][0] - mn0);
                float p1 = __expf(s[nt][1] - mn0);
                float p2 = __expf(s[nt][2] - mn1);
                float p3 = __expf(s[nt][3] - mn1);
                ps0 += p0 + p1;
                ps1 += p2 + p3;
                int t = nt >> 1, q = nt & 1;
                split2(p0, p1, pah[t][q * 2 + 0], pal[t][q * 2 + 0]);
                split2(p2, p3, pah[t][q * 2 + 1], pal[t][q * 2 + 1]);
            }
            ps0 += __shfl_xor_sync(0xffffffffu, ps0, 1);
            ps0 += __shfl_xor_sync(0xffffffffu, ps0, 2);
            ps1 += __shfl_xor_sync(0xffffffffu, ps1, 1);
            ps1 += __shfl_xor_sync(0xffffffffu, ps1, 2);
            l0 = l0 * corr0 + ps0;
            l1 = l1 * corr1 + ps1;
            m0 = mn0; m1 = mn1;
            #pragma unroll
            for (int nt = 0; nt < 8; ++nt) {
                acc[nt][0] *= corr0; acc[nt][1] *= corr0;
                acc[nt][2] *= corr1; acc[nt][3] *= corr1;
            }

            // ---- O += P V (3-pass) ----
            const uint32_t vstage = stage + 16384u;
            #pragma unroll
            for (int ks = 0; ks < 4; ++ks) {
                const int colh = ks * 2 + (lane >> 4);
                uint32_t vh[4][4], vl[4][4];
                #pragma unroll
                for (int g = 0; g < 4; ++g) {
                    int row = g * 16 + (lane & 15);
                    uint32_t rb = vstage + row * 256;
                    LDSM_X4(vh[g][0], vh[g][1], vh[g][2], vh[g][3], rb + ((colh ^ (row & 7)) << 4));
                    LDSM_X4(vl[g][0], vl[g][1], vl[g][2], vl[g][3], rb + (((colh + 8) ^ (row & 7)) << 4));
                }
                #pragma unroll
                for (int g = 0; g < 4; ++g) {
                    #pragma unroll
                    for (int p = 0; p < 2; ++p) {
                        int nt = g * 2 + p;
                        mma_bf16(acc[nt], pah[ks], vh[g][p], vh[g][p + 2]);
                        mma_bf16(acc[nt], pah[ks], vl[g][p], vl[g][p + 2]);
                        mma_bf16(acc[nt], pal[ks], vh[g][p], vh[g][p + 2]);
                    }
                }
            }

            __syncthreads();
            if (kt + 1 < nkt) {
                if (kt + 2 < nkt) { prefetch_kv(kt + 2, kt & 1); CP_COMMIT(); CP_WAIT1(); }
                else              { CP_WAIT0(); }
                __syncthreads();
            }
        }

        // ---- epilogue for this q-block ----
        float inv0 = 1.f / l0, inv1 = 1.f / l1;
        size_t r0o = (size_t)(b * S_ + row0g) * HID + h * HD;
        size_t r1o = r0o + (size_t)8 * HID;
        #pragma unroll
        for (int nt = 0; nt < 8; ++nt) {
            int d = nt * 8 + (lane & 3) * 2;
            uint32_t hh, ll;
            split2(acc[nt][0] * inv0, acc[nt][1] * inv0, hh, ll);
            *reinterpret_cast<uint32_t*>(athi + r0o + d) = hh;
            *reinterpret_cast<uint32_t*>(atlo + r0o + d) = ll;
            split2(acc[nt][2] * inv1, acc[nt][3] * inv1, hh, ll);
            *reinterpret_cast<uint32_t*>(athi + r1o + d) = hh;
            *reinterpret_cast<uint32_t*>(atlo + r1o + d) = ll;
        }
        __syncthreads();   // smem (Q, stages) safe to reuse for next half
    }
}

// ---------------------------------------------------------------------------
// kernel_launch
// ---------------------------------------------------------------------------
extern "C" void kernel_launch(void* const* d_in, const int* in_sizes, int n_in,
                              void* d_out, int out_size)
{
    const float* hs    = (const float*)d_in[0];
    const int*   amask = (const int*)  d_in[1];
    const float* Wq    = (const float*)d_in[2];
    const float* bq    = (const float*)d_in[3];
    const float* Wk    = (const float*)d_in[4];
    const float* bk    = (const float*)d_in[5];
    const float* Wv    = (const float*)d_in[6];
    const float* bv    = (const float*)d_in[7];
    const float* Wo    = (const float*)d_in[8];
    const float* bo    = (const float*)d_in[9];
    float* out = (float*)d_out;

    float *qkvp, *biasp;
    cudaGetSymbolAddress((void**)&qkvp, g_qkv);
    cudaGetSymbolAddress((void**)&biasp, g_bias);
    __nv_bfloat16 *hshi, *hslo, *athi, *atlo, *wch, *wcl, *woh, *wol;
    cudaGetSymbolAddress((void**)&hshi, g_hs_hi);
    cudaGetSymbolAddress((void**)&hslo, g_hs_lo);
    cudaGetSymbolAddress((void**)&athi, g_at_hi);
    cudaGetSymbolAddress((void**)&atlo, g_at_lo);
    cudaGetSymbolAddress((void**)&wch, g_Wc_hi);
    cudaGetSymbolAddress((void**)&wcl, g_Wc_lo);
    cudaGetSymbolAddress((void**)&woh, g_Wo_hi);
    cudaGetSymbolAddress((void**)&wol, g_Wo_lo);

    cudaFuncSetAttribute(gemm_mma_kernel<0>,
                         cudaFuncAttributeMaxDynamicSharedMemorySize, GEMM_SMEM);
    cudaFuncSetAttribute(gemm_mma_kernel<1>,
                         cudaFuncAttributeMaxDynamicSharedMemorySize, GEMM_SMEM);
    cudaFuncSetAttribute(attn_mma_kernel,
                         cudaFuncAttributeMaxDynamicSharedMemorySize, ATTN_SMEM);

    const int M = B_ * S_;
    const int nhs = M * HID;

    prep_weights_kernel<<<dim3(32, 32, 4), dim3(32, 8)>>>(Wq, Wk, Wv, Wo);
    split_kernel<<<(nhs + 255) / 256, 256>>>(hs, hshi, hslo, nhs);
    rope_table_kernel<<<(S_ * 32 + 255) / 256, 256>>>(bq, bk, bv);

    // fused QKV projection + RoPE + bf16 split (Q,K) / fp32 (V)
    gemm_mma_kernel<1><<<dim3(NCAT / 128, M / 128), 256, GEMM_SMEM>>>(
        hshi, hslo, wch, wcl, biasp, qkvp, NCAT, HID);

    // V transpose -> bf16 hi/lo
    v_transpose_kernel<<<dim3(S_ / 64, NKV, B_), 256>>>();

    // attention: balanced pairs (qb = p and 15-p), 256 CTAs
    attn_mma_kernel<<<dim3(8, NH, B_), 256, ATTN_SMEM>>>(amask, athi, atlo);

    // output projection
    gemm_mma_kernel<0><<<dim3(HID / 128, M / 128), 256, GEMM_SMEM>>>(
        athi, atlo, woh, wol, bo, out, HID, HID);
}

// round 9
// speedup vs baseline: 6.9121x; 2.1950x over previous
#include <cuda_runtime.h>
#include <cuda_fp16.h>
#include <cstdint>
#include <math.h>

#define B_    2
#define S_    2048
#define HID   1024
#define NH    16
#define NKV   4
#define HD    64
#define NCAT  1536            // 1024 (Q) + 256 (K) + 256 (V)

// ---------------------------------------------------------------------------
// Scratch (device globals)
// ---------------------------------------------------------------------------
__device__ float g_qkv[(size_t)B_ * S_ * NCAT];      // V fp32 staging
__device__ float g_cos[S_ * 32];
__device__ float g_sin[S_ * 32];
__device__ float g_bias[NCAT];

__device__ __half g_hs[(size_t)B_ * S_ * HID];       // hidden states fp16
__device__ __half g_at[(size_t)B_ * S_ * HID];       // attention out fp16
__device__ __half g_Wc[NCAT * HID];                  // [1536,1024] K-major rows
__device__ __half g_Wo[HID * HID];
__device__ __half g_Q[(size_t)B_ * S_ * HID];        // post-rope Q fp16
__device__ __half g_K[(size_t)B_ * S_ * NKV * HD];   // post-rope K fp16
__device__ __half g_Vt[(size_t)B_ * NKV * HD * S_];  // [b,kvh,d,s] fp16

// ---------------------------------------------------------------------------
// helpers
// ---------------------------------------------------------------------------
__device__ __forceinline__ uint32_t smem_u32(const void* p) {
    uint32_t a;
    asm("{ .reg .u64 t; cvta.to.shared.u64 t, %1; cvt.u32.u64 %0, t; }" : "=r"(a) : "l"(p));
    return a;
}
#define LDSM_X4(r0, r1, r2, r3, addr) \
    asm volatile("ldmatrix.sync.aligned.m8n8.x4.shared.b16 {%0,%1,%2,%3}, [%4];" \
        : "=r"(r0), "=r"(r1), "=r"(r2), "=r"(r3) : "r"(addr))
#define CP_A16(dst, src) \
    asm volatile("cp.async.cg.shared.global [%0], [%1], 16;" :: "r"(dst), "l"(src))
#define CP_COMMIT() asm volatile("cp.async.commit_group;" ::: "memory")
#define CP_WAIT0()  asm volatile("cp.async.wait_group 0;" ::: "memory")
#define CP_WAIT1()  asm volatile("cp.async.wait_group 1;" ::: "memory")
#define CP_WAIT2()  asm volatile("cp.async.wait_group 2;" ::: "memory")

__device__ __forceinline__ void mma_f16(float* d, const uint32_t* a,
                                        uint32_t b0, uint32_t b1) {
    asm volatile(
        "mma.sync.aligned.m16n8k16.row.col.f32.f16.f16.f32 "
        "{%0,%1,%2,%3}, {%4,%5,%6,%7}, {%8,%9}, {%0,%1,%2,%3};"
        : "+f"(d[0]), "+f"(d[1]), "+f"(d[2]), "+f"(d[3])
        : "r"(a[0]), "r"(a[1]), "r"(a[2]), "r"(a[3]), "r"(b0), "r"(b1));
}
__device__ __forceinline__ uint32_t pack2h(float x, float y) {
    __half2 h = __floats2half2_rn(x, y);
    return *reinterpret_cast<uint32_t*>(&h);
}
__device__ __forceinline__ float fexp2(float x) {
    float y;
    asm("ex2.approx.f32 %0, %1;" : "=f"(y) : "f"(x));
    return y;
}

// ---------------------------------------------------------------------------
// Weight prep: transpose to [N,K] fp16.  z=0:Wq z=1:Wk z=2:Wv z=3:Wo.
// ---------------------------------------------------------------------------
__global__ void prep_weights_kernel(const float* __restrict__ Wq,
                                    const float* __restrict__ Wk,
                                    const float* __restrict__ Wv,
                                    const float* __restrict__ Wo) {
    __shared__ float t[32][33];
    int z = blockIdx.z;
    const float* W;
    __half* dst;
    int N, rowoff;
    if (z == 0)      { W = Wq; N = HID; rowoff = 0;    dst = g_Wc; }
    else if (z == 1) { W = Wk; N = 256; rowoff = 1024; dst = g_Wc; }
    else if (z == 2) { W = Wv; N = 256; rowoff = 1280; dst = g_Wc; }
    else             { W = Wo; N = HID; rowoff = 0;    dst = g_Wo; }

    int n0 = blockIdx.x * 32, k0 = blockIdx.y * 32;
    if (n0 >= N) return;
    int x = threadIdx.x, y = threadIdx.y;
    #pragma unroll
    for (int yy = y; yy < 32; yy += 8)
        t[yy][x] = W[(size_t)(k0 + yy) * N + n0 + x];
    __syncthreads();
    #pragma unroll
    for (int yy = y; yy < 32; yy += 8)
        dst[(size_t)(rowoff + n0 + yy) * HID + k0 + x] = __float2half(t[x][yy]);
}

__global__ void cvt_kernel(const float* __restrict__ in, __half* __restrict__ o, int n) {
    int i = (blockIdx.x * blockDim.x + threadIdx.x) * 2;
    if (i >= n) return;
    float2 v = *reinterpret_cast<const float2*>(in + i);
    *reinterpret_cast<uint32_t*>(o + i) = pack2h(v.x, v.y);
}

// ---------------------------------------------------------------------------
// RoPE table + bias concat
// ---------------------------------------------------------------------------
__global__ void rope_table_kernel(const float* __restrict__ bq,
                                  const float* __restrict__ bk,
                                  const float* __restrict__ bv) {
    int idx = blockIdx.x * blockDim.x + threadIdx.x;
    if (idx < NCAT)
        g_bias[idx] = (idx < 1024) ? bq[idx] : (idx < 1280) ? bk[idx - 1024] : bv[idx - 1280];
    if (idx >= S_ * 32) return;
    int t = idx >> 5, j = idx & 31;
    double inv = exp2(-(double)j * 0.5190512648261507);
    float ang = (float)((double)t * inv);
    float s, c;
    sincosf(ang, &s, &c);
    g_cos[idx] = c;
    g_sin[idx] = s;
}

// ---------------------------------------------------------------------------
// GEMM via fp16 mma.sync single-pass, 3-stage cp.async, 80B-pitch rows.
// MODE 0: C = A@W^T + bias (fp32).  MODE 1: fused RoPE epilogue.
// ---------------------------------------------------------------------------
#define GEMM_SMEM (3 * 20480)

template <int MODE>
__global__ __launch_bounds__(256, 2) void gemm_mma_kernel(
    const __half* __restrict__ Ap, const __half* __restrict__ Wp,
    const float* __restrict__ bias, float* __restrict__ C, int ldc, int K)
{
    extern __shared__ char smx[];
    const int tid = threadIdx.x, lane = tid & 31, wid = tid >> 5;
    const int wm = wid & 1, wn = wid >> 1;
    const int m0 = blockIdx.y * 128, n0 = blockIdx.x * 128;
    const uint32_t sbase = smem_u32(smx);

    float acc[4][4][4];
    #pragma unroll
    for (int a = 0; a < 4; a++)
        #pragma unroll
        for (int bb = 0; bb < 4; bb++)
            #pragma unroll
            for (int c = 0; c < 4; c++) acc[a][bb][c] = 0.f;

    // stage: A 128 rows x 80B @ +0, W 128 rows x 80B @ +10240
    auto load_stage = [&](int ch, int st) {
        const uint32_t base = sbase + (uint32_t)st * 20480u;
        const int k0 = ch * 32;
        #pragma unroll
        for (int it = 0; it < 4; ++it) {
            int i = it * 256 + tid;            // 0..1023
            int mat = i >> 9;
            int row = (i >> 2) & 127;
            int seg = i & 3;
            uint32_t dst = base + (uint32_t)mat * 10240u + (uint32_t)(row * 80 + seg * 16);
            const __half* p = mat ? (Wp + (size_t)(n0 + row) * K)
                                  : (Ap + (size_t)(m0 + row) * K);
            CP_A16(dst, p + k0 + seg * 8);
        }
    };

    const int NCH = K / 32;
    load_stage(0, 0); CP_COMMIT();
    if (NCH > 1) { load_stage(1, 1); CP_COMMIT(); }
    if (NCH > 2) { load_stage(2, 2); CP_COMMIT(); }

    int st = 0;
    for (int ch = 0; ch < NCH; ++ch) {
        const int rem = NCH - 1 - ch;
        if (rem >= 2) CP_WAIT2(); else if (rem == 1) CP_WAIT1(); else CP_WAIT0();
        __syncthreads();

        const uint32_t sA = sbase + (uint32_t)st * 20480u;
        const uint32_t sW = sA + 10240u;

        #pragma unroll
        for (int ks = 0; ks < 2; ++ks) {
            const uint32_t coff = (uint32_t)(ks * 32 + ((lane >> 4) << 4));
            uint32_t a[4][4], bfr[2][4];
            #pragma unroll
            for (int mi = 0; mi < 4; ++mi) {
                uint32_t ro = (uint32_t)(wm * 64 + mi * 16 + (lane & 15)) * 80 + coff;
                LDSM_X4(a[mi][0], a[mi][1], a[mi][2], a[mi][3], sA + ro);
            }
            #pragma unroll
            for (int g = 0; g < 2; ++g) {
                uint32_t ro = (uint32_t)(wn * 32 + g * 16 + (lane & 15)) * 80 + coff;
                LDSM_X4(bfr[g][0], bfr[g][1], bfr[g][2], bfr[g][3], sW + ro);
            }
            #pragma unroll
            for (int mi = 0; mi < 4; ++mi) {
                #pragma unroll
                for (int j = 0; j < 4; ++j) {
                    const int g = j >> 1, p = j & 1;
                    mma_f16(acc[mi][j], a[mi], bfr[g][p], bfr[g][p + 2]);
                }
            }
        }
        __syncthreads();
        if (ch + 3 < NCH) { load_stage(ch + 3, st); CP_COMMIT(); }
        st = (st == 2) ? 0 : st + 1;
    }

    // epilogue
    #pragma unroll
    for (int mi = 0; mi < 4; ++mi) {
        const int r = m0 + wm * 64 + mi * 16 + (lane >> 2);
        #pragma unroll
        for (int j = 0; j < 4; ++j) {
            const int col = n0 + wn * 32 + j * 8 + (lane & 3) * 2;
            const float b0 = bias[col], b1 = bias[col + 1];
            float x0 = acc[mi][j][0] + b0, x1 = acc[mi][j][1] + b1;
            float x2 = acc[mi][j][2] + b0, x3 = acc[mi][j][3] + b1;
            if (MODE == 0) {
                *reinterpret_cast<float2*>(C + (size_t)r * ldc + col) = make_float2(x0, x1);
                *reinterpret_cast<float2*>(C + (size_t)(r + 8) * ldc + col) = make_float2(x2, x3);
            } else {
                if (col < 1280) {
                    const int pos0 = r & (S_ - 1), pos1 = (r + 8) & (S_ - 1);
                    const int j0 = col & 31;
                    float2 cc0 = *reinterpret_cast<const float2*>(&g_cos[pos0 * 32 + j0]);
                    float2 ss0 = *reinterpret_cast<const float2*>(&g_sin[pos0 * 32 + j0]);
                    float2 cc1 = *reinterpret_cast<const float2*>(&g_cos[pos1 * 32 + j0]);
                    float2 ss1 = *reinterpret_cast<const float2*>(&g_sin[pos1 * 32 + j0]);
                    float y0 = x0 * cc0.x - x1 * ss0.x;
                    float y1 = x1 * cc0.y + x0 * ss0.y;
                    float y2 = x2 * cc1.x - x3 * ss1.x;
                    float y3 = x3 * cc1.y + x2 * ss1.y;
                    if (col < 1024) {
                        uint32_t* o = reinterpret_cast<uint32_t*>(g_Q);
                        o[(size_t)r * 512 + (col >> 1)]       = pack2h(y0, y1);
                        o[(size_t)(r + 8) * 512 + (col >> 1)] = pack2h(y2, y3);
                    } else {
                        uint32_t* o = reinterpret_cast<uint32_t*>(g_K);
                        o[(size_t)r * 128 + ((col - 1024) >> 1)]       = pack2h(y0, y1);
                        o[(size_t)(r + 8) * 128 + ((col - 1024) >> 1)] = pack2h(y2, y3);
                    }
                } else {
                    *reinterpret_cast<float2*>(&g_qkv[(size_t)r * NCAT + col]) = make_float2(x0, x1);
                    *reinterpret_cast<float2*>(&g_qkv[(size_t)(r + 8) * NCAT + col]) = make_float2(x2, x3);
                }
            }
        }
    }
}

// ---------------------------------------------------------------------------
// V transpose: g_qkv V cols (fp32) -> Vt[b][kvh][d][s] fp16
// ---------------------------------------------------------------------------
__global__ void v_transpose_kernel() {
    __shared__ float t[64][65];
    const int s0 = blockIdx.x * 64, kvh = blockIdx.y, b = blockIdx.z;
    const int tid = threadIdx.x;
    #pragma unroll
    for (int it = 0; it < 16; ++it) {
        int i = it * 256 + tid;
        int sl = i >> 6, d = i & 63;
        t[sl][d] = g_qkv[(size_t)(b * S_ + s0 + sl) * NCAT + 1280 + kvh * HD + d];
    }
    __syncthreads();
    #pragma unroll
    for (int it = 0; it < 16; ++it) {
        int i = it * 256 + tid;
        int d = i >> 6, sl = i & 63;
        g_Vt[((size_t)(b * NKV + kvh) * HD + d) * S_ + s0 + sl] = __float2half(t[sl][d]);
    }
}

// ---------------------------------------------------------------------------
// Flash attention, fp16 single-pass, load-balanced q-block pairs {15-p, p}.
// 8 warps, 144B-pitch tiles, 2-stage cp.async K/V pipeline, mask fast path.
// ---------------------------------------------------------------------------
#define AQ_OFF  0                                  // 128 x 144 = 18432
#define AST_OFF 18432                              // 2 stages x (K 9216 + V 9216)
#define AOK_OFF (18432 + 2 * 18432)                // 55296: 32 tile-ok flags
#define AAM_OFF (AOK_OFF + 128)                    // mask 8192
#define ATTN_SMEM (AAM_OFF + S_ * 4)

__global__ __launch_bounds__(256, 2) void attn_mma_kernel(
    const int* __restrict__ amask, __half* __restrict__ atout)
{
    extern __shared__ char sm[];
    const uint32_t sb = smem_u32(sm);
    int* am  = reinterpret_cast<int*>(sm + AAM_OFF);
    int* amok = reinterpret_cast<int*>(sm + AOK_OFF);

    const int tid = threadIdx.x, lane = tid & 31, w = tid >> 5;
    const int pr = blockIdx.x, h = blockIdx.y, b = blockIdx.z;
    const int kvh = h >> 2;
    const float SC2 = 0.125f * 1.44269504f;        // scale * log2(e)

    // mask + per-tile all-valid flags
    #pragma unroll
    for (int it = 0; it < 8; ++it)
        am[it * 256 + tid] = amask[b * S_ + it * 256 + tid];
    __syncthreads();
    if (tid < 32) {
        int ok = 1;
        for (int j = 0; j < 64; ++j) ok &= (am[tid * 64 + j] != 0);
        amok[tid] = ok;
    }

    auto prefetch_kv = [&](int kt, int st) {
        const int k0 = kt * 64;
        const uint32_t base = sb + AST_OFF + (uint32_t)st * 18432u;
        const __half* kp = g_K + (size_t)(b * S_ + k0) * (NKV * HD) + kvh * HD;
        const __half* vp = g_Vt + ((size_t)(b * NKV + kvh) * HD) * S_ + k0;
        #pragma unroll
        for (int it = 0; it < 4; ++it) {
            int i = it * 256 + tid;                // 0..1023
            int mat = i >> 9;
            int row = (i >> 3) & 63;
            int seg = i & 7;
            uint32_t dst = base + (uint32_t)mat * 9216u + (uint32_t)(row * 144 + seg * 16);
            const __half* p = mat ? (vp + (size_t)row * S_) : (kp + (size_t)row * (NKV * HD));
            CP_A16(dst, p + seg * 8);
        }
    };

    for (int half = 0; half < 2; ++half) {
        const int qb = half ? pr : (15 - pr);      // long block first
        const int q0 = qb * 128;
        const int nkt = 2 * qb + 2;

        // Q tile cp.async: 128 rows x 8 segs
        {
            const __half* qp = g_Q + (size_t)(b * S_ + q0) * HID + h * HD;
            #pragma unroll
            for (int it = 0; it < 4; ++it) {
                int i = it * 256 + tid;
                int row = i >> 3, seg = i & 7;
                CP_A16(sb + AQ_OFF + (uint32_t)(row * 144 + seg * 16),
                       qp + (size_t)row * HID + seg * 8);
            }
            CP_COMMIT();
        }

        prefetch_kv(0, 0); CP_COMMIT();
        if (nkt > 1) { prefetch_kv(1, 1); CP_COMMIT(); CP_WAIT1(); }
        else         { CP_WAIT0(); }
        __syncthreads();

        // preload Q fragments
        uint32_t qf[4][4];
        {
            uint32_t rb = sb + AQ_OFF + (uint32_t)(w * 16 + (lane & 15)) * 144;
            #pragma unroll
            for (int ks = 0; ks < 4; ++ks)
                LDSM_X4(qf[ks][0], qf[ks][1], qf[ks][2], qf[ks][3],
                        rb + (uint32_t)(ks * 32 + ((lane >> 4) << 4)));
        }

        float acc[8][4];
        #pragma unroll
        for (int nt = 0; nt < 8; ++nt)
            #pragma unroll
            for (int c = 0; c < 4; ++c) acc[nt][c] = 0.f;
        float m0 = -1e30f, m1 = -1e30f, l0 = 0.f, l1 = 0.f;
        const int row0g = q0 + w * 16 + (lane >> 2);
        const int row1g = row0g + 8;

        for (int kt = 0; kt < nkt; ++kt) {
            const int k0 = kt * 64;
            const uint32_t stage = sb + AST_OFF + (uint32_t)(kt & 1) * 18432u;

            // ---- S = Q K^T (single fp16 pass) ----
            float s[8][4];
            #pragma unroll
            for (int nt = 0; nt < 8; ++nt)
                #pragma unroll
                for (int c = 0; c < 4; ++c) s[nt][c] = 0.f;

            #pragma unroll
            for (int ks = 0; ks < 4; ++ks) {
                const uint32_t coff = (uint32_t)(ks * 32 + ((lane >> 4) << 4));
                uint32_t kf[4][4];
                #pragma unroll
                for (int g = 0; g < 4; ++g)
                    LDSM_X4(kf[g][0], kf[g][1], kf[g][2], kf[g][3],
                            stage + (uint32_t)(g * 16 + (lane & 15)) * 144 + coff);
                #pragma unroll
                for (int g = 0; g < 4; ++g)
                    #pragma unroll
                    for (int p = 0; p < 2; ++p)
                        mma_f16(s[g * 2 + p], qf[ks], kf[g][p], kf[g][p + 2]);
            }

            // ---- scale (+ masking unless fast path), online softmax ----
            const bool fast = (k0 + 63 <= q0 + w * 16) && amok[k0 >> 6];
            #pragma unroll
            for (int nt = 0; nt < 8; ++nt)
                #pragma unroll
                for (int c = 0; c < 4; ++c) s[nt][c] *= SC2;
            if (!fast) {
                #pragma unroll
                for (int nt = 0; nt < 8; ++nt) {
                    int cl = nt * 8 + (lane & 3) * 2;
                    int cg0 = k0 + cl, cg1 = cg0 + 1;
                    bool ok0 = am[cg0] != 0, ok1 = am[cg1] != 0;
                    if (!(ok0 && cg0 <= row0g)) s[nt][0] = -1e30f;
                    if (!(ok1 && cg1 <= row0g)) s[nt][1] = -1e30f;
                    if (!(ok0 && cg0 <= row1g)) s[nt][2] = -1e30f;
                    if (!(ok1 && cg1 <= row1g)) s[nt][3] = -1e30f;
                }
            }

            float mt0 = -1e30f, mt1 = -1e30f;
            #pragma unroll
            for (int nt = 0; nt < 8; ++nt) {
                mt0 = fmaxf(mt0, fmaxf(s[nt][0], s[nt][1]));
                mt1 = fmaxf(mt1, fmaxf(s[nt][2], s[nt][3]));
            }
            mt0 = fmaxf(mt0, __shfl_xor_sync(0xffffffffu, mt0, 1));
            mt0 = fmaxf(mt0, __shfl_xor_sync(0xffffffffu, mt0, 2));
            mt1 = fmaxf(mt1, __shfl_xor_sync(0xffffffffu, mt1, 1));
            mt1 = fmaxf(mt1, __shfl_xor_sync(0xffffffffu, mt1, 2));

            float mn0 = fmaxf(m0, mt0), mn1 = fmaxf(m1, mt1);
            float corr0 = fexp2(m0 - mn0), corr1 = fexp2(m1 - mn1);
            float ps0 = 0.f, ps1 = 0.f;
            uint32_t pa[4][4];
            #pragma unroll
            for (int nt = 0; nt < 8; ++nt) {
                float p0 = fexp2(s[nt][0] - mn0);
                float p1 = fexp2(s[nt][1] - mn0);
                float p2 = fexp2(s[nt][2] - mn1);
                float p3 = fexp2(s[nt][3] - mn1);
                ps0 += p0 + p1;
                ps1 += p2 + p3;
                int t = nt >> 1, q = nt & 1;
                pa[t][q * 2 + 0] = pack2h(p0, p1);
                pa[t][q * 2 + 1] = pack2h(p2, p3);
            }
            ps0 += __shfl_xor_sync(0xffffffffu, ps0, 1);
            ps0 += __shfl_xor_sync(0xffffffffu, ps0, 2);
            ps1 += __shfl_xor_sync(0xffffffffu, ps1, 1);
            ps1 += __shfl_xor_sync(0xffffffffu, ps1, 2);
            l0 = l0 * corr0 + ps0;
            l1 = l1 * corr1 + ps1;
            m0 = mn0; m1 = mn1;
            #pragma unroll
            for (int nt = 0; nt < 8; ++nt) {
                acc[nt][0] *= corr0; acc[nt][1] *= corr0;
                acc[nt][2] *= corr1; acc[nt][3] *= corr1;
            }

            // ---- O += P V (single fp16 pass) ----
            const uint32_t vstage = stage + 9216u;
            #pragma unroll
            for (int ks = 0; ks < 4; ++ks) {
                const uint32_t coff = (uint32_t)(ks * 32 + ((lane >> 4) << 4));
                uint32_t vf[4][4];
                #pragma unroll
                for (int g = 0; g < 4; ++g)
                    LDSM_X4(vf[g][0], vf[g][1], vf[g][2], vf[g][3],
                            vstage + (uint32_t)(g * 16 + (lane & 15)) * 144 + coff);
                #pragma unroll
                for (int g = 0; g < 4; ++g)
                    #pragma unroll
                    for (int p = 0; p < 2; ++p)
                        mma_f16(acc[g * 2 + p], pa[ks], vf[g][p], vf[g][p + 2]);
            }

            __syncthreads();
            if (kt + 1 < nkt) {
                if (kt + 2 < nkt) { prefetch_kv(kt + 2, kt & 1); CP_COMMIT(); CP_WAIT1(); }
                else              { CP_WAIT0(); }
                __syncthreads();
            }
        }

        // ---- epilogue: fp16 out ----
        float inv0 = 1.f / l0, inv1 = 1.f / l1;
        size_t r0o = (size_t)(b * S_ + row0g) * HID + h * HD;
        size_t r1o = r0o + (size_t)8 * HID;
        uint32_t* o = reinterpret_cast<uint32_t*>(atout);
        #pragma unroll
        for (int nt = 0; nt < 8; ++nt) {
            int d = nt * 8 + (lane & 3) * 2;
            o[(r0o + d) >> 1] = pack2h(acc[nt][0] * inv0, acc[nt][1] * inv0);
            o[(r1o + d) >> 1] = pack2h(acc[nt][2] * inv1, acc[nt][3] * inv1);
        }
        __syncthreads();   // smem reuse for next half
    }
}

// ---------------------------------------------------------------------------
// kernel_launch
// ---------------------------------------------------------------------------
extern "C" void kernel_launch(void* const* d_in, const int* in_sizes, int n_in,
                              void* d_out, int out_size)
{
    const float* hs    = (const float*)d_in[0];
    const int*   amask = (const int*)  d_in[1];
    const float* Wq    = (const float*)d_in[2];
    const float* bq    = (const float*)d_in[3];
    const float* Wk    = (const float*)d_in[4];
    const float* bk    = (const float*)d_in[5];
    const float* Wv    = (const float*)d_in[6];
    const float* bv    = (const float*)d_in[7];
    const float* Wo    = (const float*)d_in[8];
    const float* bo    = (const float*)d_in[9];
    float* out = (float*)d_out;

    float *qkvp, *biasp;
    cudaGetSymbolAddress((void**)&qkvp, g_qkv);
    cudaGetSymbolAddress((void**)&biasp, g_bias);
    __half *hsp, *atp, *wcp, *wop;
    cudaGetSymbolAddress((void**)&hsp, g_hs);
    cudaGetSymbolAddress((void**)&atp, g_at);
    cudaGetSymbolAddress((void**)&wcp, g_Wc);
    cudaGetSymbolAddress((void**)&wop, g_Wo);

    cudaFuncSetAttribute(gemm_mma_kernel<0>,
                         cudaFuncAttributeMaxDynamicSharedMemorySize, GEMM_SMEM);
    cudaFuncSetAttribute(gemm_mma_kernel<1>,
                         cudaFuncAttributeMaxDynamicSharedMemorySize, GEMM_SMEM);
    cudaFuncSetAttribute(attn_mma_kernel,
                         cudaFuncAttributeMaxDynamicSharedMemorySize, ATTN_SMEM);

    const int M = B_ * S_;
    const int nhs = M * HID;

    prep_weights_kernel<<<dim3(32, 32, 4), dim3(32, 8)>>>(Wq, Wk, Wv, Wo);
    cvt_kernel<<<(nhs / 2 + 255) / 256, 256>>>(hs, hsp, nhs);
    rope_table_kernel<<<(S_ * 32 + 255) / 256, 256>>>(bq, bk, bv);

    // fused QKV projection + RoPE + fp16 conversion (Q,K) / fp32 (V)
    gemm_mma_kernel<1><<<dim3(NCAT / 128, M / 128), 256, GEMM_SMEM>>>(
        hsp, wcp, biasp, qkvp, NCAT, HID);

    // V transpose -> fp16
    v_transpose_kernel<<<dim3(S_ / 64, NKV, B_), 256>>>();

    // attention (profiled launch)
    attn_mma_kernel<<<dim3(8, NH, B_), 256, ATTN_SMEM>>>(amask, atp);

    // output projection
    gemm_mma_kernel<0><<<dim3(HID / 128, M / 128), 256, GEMM_SMEM>>>(
        atp, wop, bo, out, HID, HID);
}

// round 11
// speedup vs baseline: 8.0025x; 1.1577x over previous
#include <cuda_runtime.h>
#include <cuda_fp16.h>
#include <cstdint>
#include <math.h>

#define B_    2
#define S_    2048
#define HID   1024
#define NH    16
#define NKV   4
#define HD    64
#define NCAT  1536            // 1024 (Q) + 256 (K) + 256 (V)

// ---------------------------------------------------------------------------
// Scratch (device globals)
// ---------------------------------------------------------------------------
__device__ float g_qkv[(size_t)B_ * S_ * NCAT];      // V fp32 staging
__device__ float g_cos[S_ * 32];
__device__ float g_sin[S_ * 32];
__device__ float g_bias[NCAT];

__device__ __half g_hs[(size_t)B_ * S_ * HID];
__device__ __half g_at[(size_t)B_ * S_ * HID];
__device__ __half g_Wc[NCAT * HID];                  // [1536,1024] K-major rows
__device__ __half g_Wo[HID * HID];
__device__ __half g_Q[(size_t)B_ * S_ * HID];        // post-rope Q fp16 (pre-scaled)
__device__ __half g_K[(size_t)B_ * S_ * NKV * HD];   // post-rope K fp16
__device__ __half g_Vt[(size_t)B_ * NKV * HD * S_];  // [b,kvh,d,s] fp16

// ---------------------------------------------------------------------------
// helpers
// ---------------------------------------------------------------------------
__device__ __forceinline__ uint32_t smem_u32(const void* p) {
    uint32_t a;
    asm("{ .reg .u64 t; cvta.to.shared.u64 t, %1; cvt.u32.u64 %0, t; }" : "=r"(a) : "l"(p));
    return a;
}
#define LDSM_X4(r0, r1, r2, r3, addr) \
    asm volatile("ldmatrix.sync.aligned.m8n8.x4.shared.b16 {%0,%1,%2,%3}, [%4];" \
        : "=r"(r0), "=r"(r1), "=r"(r2), "=r"(r3) : "r"(addr))
#define CP_A16(dst, src) \
    asm volatile("cp.async.cg.shared.global [%0], [%1], 16;" :: "r"(dst), "l"(src))
#define CP_COMMIT() asm volatile("cp.async.commit_group;" ::: "memory")
#define CP_WAIT0()  asm volatile("cp.async.wait_group 0;" ::: "memory")
#define CP_WAIT1()  asm volatile("cp.async.wait_group 1;" ::: "memory")

__device__ __forceinline__ void mma_f16(float* d, const uint32_t* a,
                                        uint32_t b0, uint32_t b1) {
    asm volatile(
        "mma.sync.aligned.m16n8k16.row.col.f32.f16.f16.f32 "
        "{%0,%1,%2,%3}, {%4,%5,%6,%7}, {%8,%9}, {%0,%1,%2,%3};"
        : "+f"(d[0]), "+f"(d[1]), "+f"(d[2]), "+f"(d[3])
        : "r"(a[0]), "r"(a[1]), "r"(a[2]), "r"(a[3]), "r"(b0), "r"(b1));
}
__device__ __forceinline__ uint32_t pack2h(float x, float y) {
    __half2 h = __floats2half2_rn(x, y);
    return *reinterpret_cast<uint32_t*>(&h);
}
__device__ __forceinline__ float fexp2(float x) {
    float y;
    asm("ex2.approx.f32 %0, %1;" : "=f"(y) : "f"(x));
    return y;
}
__device__ __forceinline__ uint32_t hexp2x2(uint32_t x) {
    uint32_t y;
    asm("ex2.approx.f16x2 %0, %1;" : "=r"(y) : "r"(x));
    return y;
}

// ---------------------------------------------------------------------------
// Weight prep: transpose to [N,K] fp16.  z=0:Wq z=1:Wk z=2:Wv z=3:Wo.
// ---------------------------------------------------------------------------
__global__ void prep_weights_kernel(const float* __restrict__ Wq,
                                    const float* __restrict__ Wk,
                                    const float* __restrict__ Wv,
                                    const float* __restrict__ Wo) {
    __shared__ float t[32][33];
    int z = blockIdx.z;
    const float* W;
    __half* dst;
    int N, rowoff;
    if (z == 0)      { W = Wq; N = HID; rowoff = 0;    dst = g_Wc; }
    else if (z == 1) { W = Wk; N = 256; rowoff = 1024; dst = g_Wc; }
    else if (z == 2) { W = Wv; N = 256; rowoff = 1280; dst = g_Wc; }
    else             { W = Wo; N = HID; rowoff = 0;    dst = g_Wo; }

    int n0 = blockIdx.x * 32, k0 = blockIdx.y * 32;
    if (n0 >= N) return;
    int x = threadIdx.x, y = threadIdx.y;
    #pragma unroll
    for (int yy = y; yy < 32; yy += 8)
        t[yy][x] = W[(size_t)(k0 + yy) * N + n0 + x];
    __syncthreads();
    #pragma unroll
    for (int yy = y; yy < 32; yy += 8)
        dst[(size_t)(rowoff + n0 + yy) * HID + k0 + x] = __float2half(t[x][yy]);
}

__global__ void cvt_kernel(const float* __restrict__ in, __half* __restrict__ o, int n) {
    int i = (blockIdx.x * blockDim.x + threadIdx.x) * 2;
    if (i >= n) return;
    float2 v = *reinterpret_cast<const float2*>(in + i);
    *reinterpret_cast<uint32_t*>(o + i) = pack2h(v.x, v.y);
}

// ---------------------------------------------------------------------------
// RoPE table + bias concat
// ---------------------------------------------------------------------------
__global__ void rope_table_kernel(const float* __restrict__ bq,
                                  const float* __restrict__ bk,
                                  const float* __restrict__ bv) {
    int idx = blockIdx.x * blockDim.x + threadIdx.x;
    if (idx < NCAT)
        g_bias[idx] = (idx < 1024) ? bq[idx] : (idx < 1280) ? bk[idx - 1024] : bv[idx - 1280];
    if (idx >= S_ * 32) return;
    int t = idx >> 5, j = idx & 31;
    double inv = exp2(-(double)j * 0.5190512648261507);
    float ang = (float)((double)t * inv);
    float s, c;
    sincosf(ang, &s, &c);
    g_cos[idx] = c;
    g_sin[idx] = s;
}

// ---------------------------------------------------------------------------
// GEMM fp16 mma.sync: BK=64 chunks, 3-stage ring, ONE sync per chunk.
// 128B swizzled rows. MODE 0: fp32 C + bias. MODE 1: fused RoPE epilogue,
// Q additionally pre-scaled by 0.125*log2(e).
// ---------------------------------------------------------------------------
#define GEMM_SMEM (3 * 32768)

template <int MODE>
__global__ __launch_bounds__(256, 2) void gemm_mma_kernel(
    const __half* __restrict__ Ap, const __half* __restrict__ Wp,
    const float* __restrict__ bias, float* __restrict__ C, int ldc, int K)
{
    extern __shared__ char smx[];
    const int tid = threadIdx.x, lane = tid & 31, wid = tid >> 5;
    const int wm = wid & 1, wn = wid >> 1;
    const int m0 = blockIdx.y * 128, n0 = blockIdx.x * 128;
    const uint32_t sbase = smem_u32(smx);

    float acc[4][4][4];
    #pragma unroll
    for (int a = 0; a < 4; a++)
        #pragma unroll
        for (int bb = 0; bb < 4; bb++)
            #pragma unroll
            for (int c = 0; c < 4; c++) acc[a][bb][c] = 0.f;

    // stage: A 128 rows x 128B @ +0, W @ +16384; BK=64
    auto load_stage = [&](int ch, int st) {
        const uint32_t base = sbase + (uint32_t)st * 32768u;
        const int k0 = ch * 64;
        #pragma unroll
        for (int it = 0; it < 8; ++it) {
            int i = it * 256 + tid;            // 0..2047
            int mat = i >> 10;
            int row = (i >> 3) & 127;
            int seg = i & 7;
            uint32_t dst = base + (uint32_t)mat * 16384u
                         + (uint32_t)(row * 128 + (((seg ^ (row & 7))) << 4));
            const __half* p = mat ? (Wp + (size_t)(n0 + row) * K)
                                  : (Ap + (size_t)(m0 + row) * K);
            CP_A16(dst, p + k0 + seg * 8);
        }
    };

    const int NCH = K / 64;                    // 16
    load_stage(0, 0); CP_COMMIT();
    if (NCH > 1) { load_stage(1, 1); CP_COMMIT(); }

    int stc = 0;
    for (int ch = 0; ch < NCH; ++ch) {
        if (ch + 1 < NCH) CP_WAIT1(); else CP_WAIT0();
        __syncthreads();
        if (ch + 2 < NCH) { load_stage(ch + 2, (stc + 2) % 3); CP_COMMIT(); }

        const uint32_t sA = sbase + (uint32_t)stc * 32768u;
        const uint32_t sW = sA + 16384u;

        #pragma unroll
        for (int ks = 0; ks < 4; ++ks) {
            const int colh = ks * 2 + (lane >> 4);
            uint32_t a[4][4], bfr[2][4];
            #pragma unroll
            for (int mi = 0; mi < 4; ++mi) {
                int row = wm * 64 + mi * 16 + (lane & 15);
                LDSM_X4(a[mi][0], a[mi][1], a[mi][2], a[mi][3],
                        sA + (uint32_t)(row * 128 + ((colh ^ (row & 7)) << 4)));
            }
            #pragma unroll
            for (int g = 0; g < 2; ++g) {
                int row = wn * 32 + g * 16 + (lane & 15);
                LDSM_X4(bfr[g][0], bfr[g][1], bfr[g][2], bfr[g][3],
                        sW + (uint32_t)(row * 128 + ((colh ^ (row & 7)) << 4)));
            }
            #pragma unroll
            for (int mi = 0; mi < 4; ++mi) {
                #pragma unroll
                for (int j = 0; j < 4; ++j) {
                    const int g = j >> 1, p = j & 1;
                    mma_f16(acc[mi][j], a[mi], bfr[g][p], bfr[g][p + 2]);
                }
            }
        }
        stc = (stc == 2) ? 0 : stc + 1;
    }

    // epilogue
    const float SC2 = 0.125f * 1.44269504f;    // folded into Q only
    #pragma unroll
    for (int mi = 0; mi < 4; ++mi) {
        const int r = m0 + wm * 64 + mi * 16 + (lane >> 2);
        #pragma unroll
        for (int j = 0; j < 4; ++j) {
            const int col = n0 + wn * 32 + j * 8 + (lane & 3) * 2;
            const float b0 = bias[col], b1 = bias[col + 1];
            float x0 = acc[mi][j][0] + b0, x1 = acc[mi][j][1] + b1;
            float x2 = acc[mi][j][2] + b0, x3 = acc[mi][j][3] + b1;
            if (MODE == 0) {
                *reinterpret_cast<float2*>(C + (size_t)r * ldc + col) = make_float2(x0, x1);
                *reinterpret_cast<float2*>(C + (size_t)(r + 8) * ldc + col) = make_float2(x2, x3);
            } else {
                if (col < 1280) {
                    const int pos0 = r & (S_ - 1), pos1 = (r + 8) & (S_ - 1);
                    const int j0 = col & 31;
                    float2 cc0 = *reinterpret_cast<const float2*>(&g_cos[pos0 * 32 + j0]);
                    float2 ss0 = *reinterpret_cast<const float2*>(&g_sin[pos0 * 32 + j0]);
                    float2 cc1 = *reinterpret_cast<const float2*>(&g_cos[pos1 * 32 + j0]);
                    float2 ss1 = *reinterpret_cast<const float2*>(&g_sin[pos1 * 32 + j0]);
                    float y0 = x0 * cc0.x - x1 * ss0.x;
                    float y1 = x1 * cc0.y + x0 * ss0.y;
                    float y2 = x2 * cc1.x - x3 * ss1.x;
                    float y3 = x3 * cc1.y + x2 * ss1.y;
                    if (col < 1024) {
                        y0 *= SC2; y1 *= SC2; y2 *= SC2; y3 *= SC2;
                        uint32_t* o = reinterpret_cast<uint32_t*>(g_Q);
                        o[(size_t)r * 512 + (col >> 1)]       = pack2h(y0, y1);
                        o[(size_t)(r + 8) * 512 + (col >> 1)] = pack2h(y2, y3);
                    } else {
                        uint32_t* o = reinterpret_cast<uint32_t*>(g_K);
                        o[(size_t)r * 128 + ((col - 1024) >> 1)]       = pack2h(y0, y1);
                        o[(size_t)(r + 8) * 128 + ((col - 1024) >> 1)] = pack2h(y2, y3);
                    }
                } else {
                    *reinterpret_cast<float2*>(&g_qkv[(size_t)r * NCAT + col]) = make_float2(x0, x1);
                    *reinterpret_cast<float2*>(&g_qkv[(size_t)(r + 8) * NCAT + col]) = make_float2(x2, x3);
                }
            }
        }
    }
}

// ---------------------------------------------------------------------------
// V transpose: g_qkv V cols (fp32) -> Vt[b][kvh][d][s] fp16
// ---------------------------------------------------------------------------
__global__ void v_transpose_kernel() {
    __shared__ float t[64][65];
    const int s0 = blockIdx.x * 64, kvh = blockIdx.y, b = blockIdx.z;
    const int tid = threadIdx.x;
    #pragma unroll
    for (int it = 0; it < 16; ++it) {
        int i = it * 256 + tid;
        int sl = i >> 6, d = i & 63;
        t[sl][d] = g_qkv[(size_t)(b * S_ + s0 + sl) * NCAT + 1280 + kvh * HD + d];
    }
    __syncthreads();
    #pragma unroll
    for (int it = 0; it < 16; ++it) {
        int i = it * 256 + tid;
        int d = i >> 6, sl = i & 63;
        g_Vt[((size_t)(b * NKV + kvh) * HD + d) * S_ + s0 + sl] = __float2half(t[sl][d]);
    }
}

// ---------------------------------------------------------------------------
// Flash attention fp16: load-balanced q-block pairs {15-p, p}, 8 warps,
// 3-stage K/V ring w/ ONE sync per tile, ex2.f16x2 softmax, ones-MMA row sums.
// Q is pre-scaled by 0.125*log2(e) so scores are ready for exp2.
// ---------------------------------------------------------------------------
#define AQ_OFF  0                                  // 128 x 144 = 18432
#define AST_OFF 18432                              // 3 stages x (K 9216 + V 9216)
#define AOK_OFF (AST_OFF + 3 * 18432)              // 32 tile-ok flags
#define AAM_OFF (AOK_OFF + 128)                    // mask 8192
#define ATTN_SMEM (AAM_OFF + S_ * 4)

__global__ __launch_bounds__(256, 2) void attn_mma_kernel(
    const int* __restrict__ amask, __half* __restrict__ atout)
{
    extern __shared__ char sm[];
    const uint32_t sb = smem_u32(sm);
    int* am  = reinterpret_cast<int*>(sm + AAM_OFF);
    int* amok = reinterpret_cast<int*>(sm + AOK_OFF);

    const int tid = threadIdx.x, lane = tid & 31, w = tid >> 5;
    const int pr = blockIdx.x, h = blockIdx.y, b = blockIdx.z;
    const int kvh = h >> 2;
    const uint32_t ONES = 0x3C003C00u;

    // mask + per-tile all-valid flags
    #pragma unroll
    for (int it = 0; it < 8; ++it)
        am[it * 256 + tid] = amask[b * S_ + it * 256 + tid];
    __syncthreads();
    if (tid < 32) {
        int ok = 1;
        for (int j = 0; j < 64; ++j) ok &= (am[tid * 64 + j] != 0);
        amok[tid] = ok;
    }

    auto prefetch_kv = [&](int kt, int st) {
        const int k0 = kt * 64;
        const uint32_t base = sb + AST_OFF + (uint32_t)st * 18432u;
        const __half* kp = g_K + (size_t)(b * S_ + k0) * (NKV * HD) + kvh * HD;
        const __half* vp = g_Vt + ((size_t)(b * NKV + kvh) * HD) * S_ + k0;
        #pragma unroll
        for (int it = 0; it < 4; ++it) {
            int i = it * 256 + tid;
            int mat = i >> 9;
            int row = (i >> 3) & 63;
            int seg = i & 7;
            uint32_t dst = base + (uint32_t)mat * 9216u + (uint32_t)(row * 144 + seg * 16);
            const __half* p = mat ? (vp + (size_t)row * S_) : (kp + (size_t)row * (NKV * HD));
            CP_A16(dst, p + seg * 8);
        }
    };

    for (int half = 0; half < 2; ++half) {
        const int qb = half ? pr : (15 - pr);      // long block first
        const int q0 = qb * 128;
        const int nkt = 2 * qb + 2;                // >= 2

        // Q tile cp.async (group shared with kv0)
        {
            const __half* qp = g_Q + (size_t)(b * S_ + q0) * HID + h * HD;
            #pragma unroll
            for (int it = 0; it < 4; ++it) {
                int i = it * 256 + tid;
                int row = i >> 3, seg = i & 7;
                CP_A16(sb + AQ_OFF + (uint32_t)(row * 144 + seg * 16),
                       qp + (size_t)row * HID + seg * 8);
            }
        }
        prefetch_kv(0, 0); CP_COMMIT();            // group0 = Q + kv0
        prefetch_kv(1, 1); CP_COMMIT();            // group1 = kv1 (nkt >= 2 always)

        CP_WAIT1();                                // Q + kv0 ready
        __syncthreads();

        // preload Q fragments
        uint32_t qf[4][4];
        {
            uint32_t rb = sb + AQ_OFF + (uint32_t)(w * 16 + (lane & 15)) * 144;
            #pragma unroll
            for (int ks = 0; ks < 4; ++ks)
                LDSM_X4(qf[ks][0], qf[ks][1], qf[ks][2], qf[ks][3],
                        rb + (uint32_t)(ks * 32 + ((lane >> 4) << 4)));
        }

        float acc[8][4];
        #pragma unroll
        for (int nt = 0; nt < 8; ++nt)
            #pragma unroll
            for (int c = 0; c < 4; ++c) acc[nt][c] = 0.f;
        float m0 = -1e30f, m1 = -1e30f, l0 = 0.f, l1 = 0.f;
        const int row0g = q0 + w * 16 + (lane >> 2);
        const int row1g = row0g + 8;

        int stc = 0;
        for (int kt = 0; kt < nkt; ++kt) {
            if (kt > 0) {
                if (kt + 1 < nkt) CP_WAIT1(); else CP_WAIT0();
                __syncthreads();
            }
            if (kt + 2 < nkt) { prefetch_kv(kt + 2, (stc + 2) % 3); CP_COMMIT(); }

            const int k0 = kt * 64;
            const uint32_t stage = sb + AST_OFF + (uint32_t)stc * 18432u;

            // ---- S = Q K^T (pre-scaled) ----
            float s[8][4];
            #pragma unroll
            for (int nt = 0; nt < 8; ++nt)
                #pragma unroll
                for (int c = 0; c < 4; ++c) s[nt][c] = 0.f;

            #pragma unroll
            for (int ks = 0; ks < 4; ++ks) {
                const uint32_t coff = (uint32_t)(ks * 32 + ((lane >> 4) << 4));
                uint32_t kf[4][4];
                #pragma unroll
                for (int g = 0; g < 4; ++g)
                    LDSM_X4(kf[g][0], kf[g][1], kf[g][2], kf[g][3],
                            stage + (uint32_t)(g * 16 + (lane & 15)) * 144 + coff);
                #pragma unroll
                for (int g = 0; g < 4; ++g)
                    #pragma unroll
                    for (int p = 0; p < 2; ++p)
                        mma_f16(s[g * 2 + p], qf[ks], kf[g][p], kf[g][p + 2]);
            }

            // ---- masking (skipped on fully-causal, fully-valid tiles) ----
            const bool fast = (k0 + 63 <= q0 + w * 16) && amok[k0 >> 6];
            if (!fast) {
                #pragma unroll
                for (int nt = 0; nt < 8; ++nt) {
                    int cl = nt * 8 + (lane & 3) * 2;
                    int cg0 = k0 + cl, cg1 = cg0 + 1;
                    bool ok0 = am[cg0] != 0, ok1 = am[cg1] != 0;
                    if (!(ok0 && cg0 <= row0g)) s[nt][0] = -1e30f;
                    if (!(ok1 && cg1 <= row0g)) s[nt][1] = -1e30f;
                    if (!(ok0 && cg0 <= row1g)) s[nt][2] = -1e30f;
                    if (!(ok1 && cg1 <= row1g)) s[nt][3] = -1e30f;
                }
            }

            // ---- online softmax (log2 domain) ----
            float mt0 = -1e30f, mt1 = -1e30f;
            #pragma unroll
            for (int nt = 0; nt < 8; ++nt) {
                mt0 = fmaxf(mt0, fmaxf(s[nt][0], s[nt][1]));
                mt1 = fmaxf(mt1, fmaxf(s[nt][2], s[nt][3]));
            }
            mt0 = fmaxf(mt0, __shfl_xor_sync(0xffffffffu, mt0, 1));
            mt0 = fmaxf(mt0, __shfl_xor_sync(0xffffffffu, mt0, 2));
            mt1 = fmaxf(mt1, __shfl_xor_sync(0xffffffffu, mt1, 1));
            mt1 = fmaxf(mt1, __shfl_xor_sync(0xffffffffu, mt1, 2));

            float mn0 = fmaxf(m0, mt0), mn1 = fmaxf(m1, mt1);
            float corr0 = fexp2(m0 - mn0), corr1 = fexp2(m1 - mn1);

            // P = exp2(s - mn) directly in packed fp16
            uint32_t pa[4][4];
            #pragma unroll
            for (int nt = 0; nt < 8; ++nt) {
                int t = nt >> 1, q = nt & 1;
                pa[t][q * 2 + 0] = hexp2x2(pack2h(s[nt][0] - mn0, s[nt][1] - mn0));
                pa[t][q * 2 + 1] = hexp2x2(pack2h(s[nt][2] - mn1, s[nt][3] - mn1));
            }
            // row sums via ones-matrix MMA (fp32, no shuffles)
            float sum4[4] = {0.f, 0.f, 0.f, 0.f};
            #pragma unroll
            for (int ks = 0; ks < 4; ++ks)
                mma_f16(sum4, pa[ks], ONES, ONES);

            l0 = l0 * corr0 + sum4[0];
            l1 = l1 * corr1 + sum4[2];
            m0 = mn0; m1 = mn1;
            #pragma unroll
            for (int nt = 0; nt < 8; ++nt) {
                acc[nt][0] *= corr0; acc[nt][1] *= corr0;
                acc[nt][2] *= corr1; acc[nt][3] *= corr1;
            }

            // ---- O += P V ----
            const uint32_t vstage = stage + 9216u;
            #pragma unroll
            for (int ks = 0; ks < 4; ++ks) {
                const uint32_t coff = (uint32_t)(ks * 32 + ((lane >> 4) << 4));
                uint32_t vf[4][4];
                #pragma unroll
                for (int g = 0; g < 4; ++g)
                    LDSM_X4(vf[g][0], vf[g][1], vf[g][2], vf[g][3],
                            vstage + (uint32_t)(g * 16 + (lane & 15)) * 144 + coff);
                #pragma unroll
                for (int g = 0; g < 4; ++g)
                    #pragma unroll
                    for (int p = 0; p < 2; ++p)
                        mma_f16(acc[g * 2 + p], pa[ks], vf[g][p], vf[g][p + 2]);
            }

            stc = (stc == 2) ? 0 : stc + 1;
        }

        // ---- epilogue: fp16 out ----
        float inv0 = 1.f / l0, inv1 = 1.f / l1;
        size_t r0o = (size_t)(b * S_ + row0g) * HID + h * HD;
        size_t r1o = r0o + (size_t)8 * HID;
        uint32_t* o = reinterpret_cast<uint32_t*>(atout);
        #pragma unroll
        for (int nt = 0; nt < 8; ++nt) {
            int d = nt * 8 + (lane & 3) * 2;
            o[(r0o + d) >> 1] = pack2h(acc[nt][0] * inv0, acc[nt][1] * inv0);
            o[(r1o + d) >> 1] = pack2h(acc[nt][2] * inv1, acc[nt][3] * inv1);
        }
        __syncthreads();   // drain before Q/stage reuse in next half
    }
}

// ---------------------------------------------------------------------------
// kernel_launch
// ---------------------------------------------------------------------------
extern "C" void kernel_launch(void* const* d_in, const int* in_sizes, int n_in,
                              void* d_out, int out_size)
{
    const float* hs    = (const float*)d_in[0];
    const int*   amask = (const int*)  d_in[1];
    const float* Wq    = (const float*)d_in[2];
    const float* bq    = (const float*)d_in[3];
    const float* Wk    = (const float*)d_in[4];
    const float* bk    = (const float*)d_in[5];
    const float* Wv    = (const float*)d_in[6];
    const float* bv    = (const float*)d_in[7];
    const float* Wo    = (const float*)d_in[8];
    const float* bo    = (const float*)d_in[9];
    float* out = (float*)d_out;

    float *qkvp, *biasp;
    cudaGetSymbolAddress((void**)&qkvp, g_qkv);
    cudaGetSymbolAddress((void**)&biasp, g_bias);
    __half *hsp, *atp, *wcp, *wop;
    cudaGetSymbolAddress((void**)&hsp, g_hs);
    cudaGetSymbolAddress((void**)&atp, g_at);
    cudaGetSymbolAddress((void**)&wcp, g_Wc);
    cudaGetSymbolAddress((void**)&wop, g_Wo);

    cudaFuncSetAttribute(gemm_mma_kernel<0>,
                         cudaFuncAttributeMaxDynamicSharedMemorySize, GEMM_SMEM);
    cudaFuncSetAttribute(gemm_mma_kernel<1>,
                         cudaFuncAttributeMaxDynamicSharedMemorySize, GEMM_SMEM);
    cudaFuncSetAttribute(attn_mma_kernel,
                         cudaFuncAttributeMaxDynamicSharedMemorySize, ATTN_SMEM);

    const int M = B_ * S_;
    const int nhs = M * HID;

    prep_weights_kernel<<<dim3(32, 32, 4), dim3(32, 8)>>>(Wq, Wk, Wv, Wo);
    cvt_kernel<<<(nhs / 2 + 255) / 256, 256>>>(hs, hsp, nhs);
    rope_table_kernel<<<(S_ * 32 + 255) / 256, 256>>>(bq, bk, bv);

    // fused QKV projection + RoPE + fp16 (Q pre-scaled) / fp32 V
    gemm_mma_kernel<1><<<dim3(NCAT / 128, M / 128), 256, GEMM_SMEM>>>(
        hsp, wcp, biasp, qkvp, NCAT, HID);

    // V transpose -> fp16
    v_transpose_kernel<<<dim3(S_ / 64, NKV, B_), 256>>>();

    // attention (profiled launch)
    attn_mma_kernel<<<dim3(8, NH, B_), 256, ATTN_SMEM>>>(amask, atp);

    // output projection
    gemm_mma_kernel<0><<<dim3(HID / 128, M / 128), 256, GEMM_SMEM>>>(
        atp, wop, bo, out, HID, HID);
}

// round 12
// speedup vs baseline: 8.0138x; 1.0014x over previous
#include <cuda_runtime.h>
#include <cuda_fp16.h>
#include <cstdint>
#include <math.h>

#define B_    2
#define S_    2048
#define HID   1024
#define NH    16
#define NKV   4
#define HD    64
#define NCAT  1536            // 1024 (Q) + 256 (K) + 256 (V)

// ---------------------------------------------------------------------------
// Scratch (device globals)
// ---------------------------------------------------------------------------
__device__ float g_qkv[(size_t)B_ * S_ * NCAT];      // V fp32 staging
__device__ float g_cos[S_ * 32];
__device__ float g_sin[S_ * 32];
__device__ float g_bias[NCAT];

__device__ __half g_hs[(size_t)B_ * S_ * HID];
__device__ __half g_at[(size_t)B_ * S_ * HID];
__device__ __half g_Wc[NCAT * HID];                  // [1536,1024] K-major rows
__device__ __half g_Wo[HID * HID];
__device__ __half g_Q[(size_t)B_ * S_ * HID];        // post-rope Q fp16 (pre-scaled)
__device__ __half g_K[(size_t)B_ * S_ * NKV * HD];   // post-rope K fp16
__device__ __half g_Vt[(size_t)B_ * NKV * HD * S_];  // [b,kvh,d,s] fp16

// ---------------------------------------------------------------------------
// helpers
// ---------------------------------------------------------------------------
__device__ __forceinline__ uint32_t smem_u32(const void* p) {
    uint32_t a;
    asm("{ .reg .u64 t; cvta.to.shared.u64 t, %1; cvt.u32.u64 %0, t; }" : "=r"(a) : "l"(p));
    return a;
}
#define LDSM_X4(r0, r1, r2, r3, addr) \
    asm volatile("ldmatrix.sync.aligned.m8n8.x4.shared.b16 {%0,%1,%2,%3}, [%4];" \
        : "=r"(r0), "=r"(r1), "=r"(r2), "=r"(r3) : "r"(addr))
#define CP_A16(dst, src) \
    asm volatile("cp.async.cg.shared.global [%0], [%1], 16;" :: "r"(dst), "l"(src))
#define CP_COMMIT() asm volatile("cp.async.commit_group;" ::: "memory")
#define CP_WAIT0()  asm volatile("cp.async.wait_group 0;" ::: "memory")
#define CP_WAIT1()  asm volatile("cp.async.wait_group 1;" ::: "memory")

__device__ __forceinline__ void mma_f16(float* d, const uint32_t* a,
                                        uint32_t b0, uint32_t b1) {
    asm volatile(
        "mma.sync.aligned.m16n8k16.row.col.f32.f16.f16.f32 "
        "{%0,%1,%2,%3}, {%4,%5,%6,%7}, {%8,%9}, {%0,%1,%2,%3};"
        : "+f"(d[0]), "+f"(d[1]), "+f"(d[2]), "+f"(d[3])
        : "r"(a[0]), "r"(a[1]), "r"(a[2]), "r"(a[3]), "r"(b0), "r"(b1));
}
__device__ __forceinline__ uint32_t pack2h(float x, float y) {
    __half2 h = __floats2half2_rn(x, y);
    return *reinterpret_cast<uint32_t*>(&h);
}
__device__ __forceinline__ float fexp2(float x) {
    float y;
    asm("ex2.approx.f32 %0, %1;" : "=f"(y) : "f"(x));
    return y;
}
__device__ __forceinline__ uint32_t hexp2x2(uint32_t x) {
    uint32_t y;
    asm("ex2.approx.f16x2 %0, %1;" : "=r"(y) : "r"(x));
    return y;
}

// ---------------------------------------------------------------------------
// Weight prep: transpose to [N,K] fp16.  z=0:Wq z=1:Wk z=2:Wv z=3:Wo.
// ---------------------------------------------------------------------------
__global__ void prep_weights_kernel(const float* __restrict__ Wq,
                                    const float* __restrict__ Wk,
                                    const float* __restrict__ Wv,
                                    const float* __restrict__ Wo) {
    __shared__ float t[32][33];
    int z = blockIdx.z;
    const float* W;
    __half* dst;
    int N, rowoff;
    if (z == 0)      { W = Wq; N = HID; rowoff = 0;    dst = g_Wc; }
    else if (z == 1) { W = Wk; N = 256; rowoff = 1024; dst = g_Wc; }
    else if (z == 2) { W = Wv; N = 256; rowoff = 1280; dst = g_Wc; }
    else             { W = Wo; N = HID; rowoff = 0;    dst = g_Wo; }

    int n0 = blockIdx.x * 32, k0 = blockIdx.y * 32;
    if (n0 >= N) return;
    int x = threadIdx.x, y = threadIdx.y;
    #pragma unroll
    for (int yy = y; yy < 32; yy += 8)
        t[yy][x] = W[(size_t)(k0 + yy) * N + n0 + x];
    __syncthreads();
    #pragma unroll
    for (int yy = y; yy < 32; yy += 8)
        dst[(size_t)(rowoff + n0 + yy) * HID + k0 + x] = __float2half(t[x][yy]);
}

__global__ void cvt_kernel(const float* __restrict__ in, __half* __restrict__ o, int n) {
    int i = (blockIdx.x * blockDim.x + threadIdx.x) * 2;
    if (i >= n) return;
    float2 v = *reinterpret_cast<const float2*>(in + i);
    *reinterpret_cast<uint32_t*>(o + i) = pack2h(v.x, v.y);
}

// ---------------------------------------------------------------------------
// RoPE table + bias concat
// ---------------------------------------------------------------------------
__global__ void rope_table_kernel(const float* __restrict__ bq,
                                  const float* __restrict__ bk,
                                  const float* __restrict__ bv) {
    int idx = blockIdx.x * blockDim.x + threadIdx.x;
    if (idx < NCAT)
        g_bias[idx] = (idx < 1024) ? bq[idx] : (idx < 1280) ? bk[idx - 1024] : bv[idx - 1280];
    if (idx >= S_ * 32) return;
    int t = idx >> 5, j = idx & 31;
    double inv = exp2(-(double)j * 0.5190512648261507);
    float ang = (float)((double)t * inv);
    float s, c;
    sincosf(ang, &s, &c);
    g_cos[idx] = c;
    g_sin[idx] = s;
}

// ---------------------------------------------------------------------------
// GEMM fp16 mma.sync: BK=64 chunks, 3-stage ring, ONE sync per chunk.
// 128B swizzled rows. MODE 0: fp32 C + bias. MODE 1: fused RoPE epilogue,
// Q additionally pre-scaled by 0.125*log2(e).
// ---------------------------------------------------------------------------
#define GEMM_SMEM (3 * 32768)

template <int MODE>
__global__ __launch_bounds__(256, 2) void gemm_mma_kernel(
    const __half* __restrict__ Ap, const __half* __restrict__ Wp,
    const float* __restrict__ bias, float* __restrict__ C, int ldc, int K)
{
    extern __shared__ char smx[];
    const int tid = threadIdx.x, lane = tid & 31, wid = tid >> 5;
    const int wm = wid & 1, wn = wid >> 1;
    const int m0 = blockIdx.y * 128, n0 = blockIdx.x * 128;
    const uint32_t sbase = smem_u32(smx);

    float acc[4][4][4];
    #pragma unroll
    for (int a = 0; a < 4; a++)
        #pragma unroll
        for (int bb = 0; bb < 4; bb++)
            #pragma unroll
            for (int c = 0; c < 4; c++) acc[a][bb][c] = 0.f;

    // stage: A 128 rows x 128B @ +0, W @ +16384; BK=64
    auto load_stage = [&](int ch, int st) {
        const uint32_t base = sbase + (uint32_t)st * 32768u;
        const int k0 = ch * 64;
        #pragma unroll
        for (int it = 0; it < 8; ++it) {
            int i = it * 256 + tid;            // 0..2047
            int mat = i >> 10;
            int row = (i >> 3) & 127;
            int seg = i & 7;
            uint32_t dst = base + (uint32_t)mat * 16384u
                         + (uint32_t)(row * 128 + (((seg ^ (row & 7))) << 4));
            const __half* p = mat ? (Wp + (size_t)(n0 + row) * K)
                                  : (Ap + (size_t)(m0 + row) * K);
            CP_A16(dst, p + k0 + seg * 8);
        }
    };

    const int NCH = K / 64;                    // 16
    load_stage(0, 0); CP_COMMIT();
    if (NCH > 1) { load_stage(1, 1); CP_COMMIT(); }

    int stc = 0;
    for (int ch = 0; ch < NCH; ++ch) {
        if (ch + 1 < NCH) CP_WAIT1(); else CP_WAIT0();
        __syncthreads();
        if (ch + 2 < NCH) { load_stage(ch + 2, (stc + 2) % 3); CP_COMMIT(); }

        const uint32_t sA = sbase + (uint32_t)stc * 32768u;
        const uint32_t sW = sA + 16384u;

        #pragma unroll
        for (int ks = 0; ks < 4; ++ks) {
            const int colh = ks * 2 + (lane >> 4);
            uint32_t a[4][4], bfr[2][4];
            #pragma unroll
            for (int mi = 0; mi < 4; ++mi) {
                int row = wm * 64 + mi * 16 + (lane & 15);
                LDSM_X4(a[mi][0], a[mi][1], a[mi][2], a[mi][3],
                        sA + (uint32_t)(row * 128 + ((colh ^ (row & 7)) << 4)));
            }
            #pragma unroll
            for (int g = 0; g < 2; ++g) {
                int row = wn * 32 + g * 16 + (lane & 15);
                LDSM_X4(bfr[g][0], bfr[g][1], bfr[g][2], bfr[g][3],
                        sW + (uint32_t)(row * 128 + ((colh ^ (row & 7)) << 4)));
            }
            #pragma unroll
            for (int mi = 0; mi < 4; ++mi) {
                #pragma unroll
                for (int j = 0; j < 4; ++j) {
                    const int g = j >> 1, p = j & 1;
                    mma_f16(acc[mi][j], a[mi], bfr[g][p], bfr[g][p + 2]);
                }
            }
        }
        stc = (stc == 2) ? 0 : stc + 1;
    }

    // epilogue
    const float SC2 = 0.125f * 1.44269504f;    // folded into Q only
    #pragma unroll
    for (int mi = 0; mi < 4; ++mi) {
        const int r = m0 + wm * 64 + mi * 16 + (lane >> 2);
        #pragma unroll
        for (int j = 0; j < 4; ++j) {
            const int col = n0 + wn * 32 + j * 8 + (lane & 3) * 2;
            const float b0 = bias[col], b1 = bias[col + 1];
            float x0 = acc[mi][j][0] + b0, x1 = acc[mi][j][1] + b1;
            float x2 = acc[mi][j][2] + b0, x3 = acc[mi][j][3] + b1;
            if (MODE == 0) {
                *reinterpret_cast<float2*>(C + (size_t)r * ldc + col) = make_float2(x0, x1);
                *reinterpret_cast<float2*>(C + (size_t)(r + 8) * ldc + col) = make_float2(x2, x3);
            } else {
                if (col < 1280) {
                    const int pos0 = r & (S_ - 1), pos1 = (r + 8) & (S_ - 1);
                    const int j0 = col & 31;
                    float2 cc0 = *reinterpret_cast<const float2*>(&g_cos[pos0 * 32 + j0]);
                    float2 ss0 = *reinterpret_cast<const float2*>(&g_sin[pos0 * 32 + j0]);
                    float2 cc1 = *reinterpret_cast<const float2*>(&g_cos[pos1 * 32 + j0]);
                    float2 ss1 = *reinterpret_cast<const float2*>(&g_sin[pos1 * 32 + j0]);
                    float y0 = x0 * cc0.x - x1 * ss0.x;
                    float y1 = x1 * cc0.y + x0 * ss0.y;
                    float y2 = x2 * cc1.x - x3 * ss1.x;
                    float y3 = x3 * cc1.y + x2 * ss1.y;
                    if (col < 1024) {
                        y0 *= SC2; y1 *= SC2; y2 *= SC2; y3 *= SC2;
                        uint32_t* o = reinterpret_cast<uint32_t*>(g_Q);
                        o[(size_t)r * 512 + (col >> 1)]       = pack2h(y0, y1);
                        o[(size_t)(r + 8) * 512 + (col >> 1)] = pack2h(y2, y3);
                    } else {
                        uint32_t* o = reinterpret_cast<uint32_t*>(g_K);
                        o[(size_t)r * 128 + ((col - 1024) >> 1)]       = pack2h(y0, y1);
                        o[(size_t)(r + 8) * 128 + ((col - 1024) >> 1)] = pack2h(y2, y3);
                    }
                } else {
                    *reinterpret_cast<float2*>(&g_qkv[(size_t)r * NCAT + col]) = make_float2(x0, x1);
                    *reinterpret_cast<float2*>(&g_qkv[(size_t)(r + 8) * NCAT + col]) = make_float2(x2, x3);
                }
            }
        }
    }
}

// ---------------------------------------------------------------------------
// V transpose: g_qkv V cols (fp32) -> Vt[b][kvh][d][s] fp16
// ---------------------------------------------------------------------------
__global__ void v_transpose_kernel() {
    __shared__ float t[64][65];
    const int s0 = blockIdx.x * 64, kvh = blockIdx.y, b = blockIdx.z;
    const int tid = threadIdx.x;
    #pragma unroll
    for (int it = 0; it < 16; ++it) {
        int i = it * 256 + tid;
        int sl = i >> 6, d = i & 63;
        t[sl][d] = g_qkv[(size_t)(b * S_ + s0 + sl) * NCAT + 1280 + kvh * HD + d];
    }
    __syncthreads();
    #pragma unroll
    for (int it = 0; it < 16; ++it) {
        int i = it * 256 + tid;
        int d = i >> 6, sl = i & 63;
        g_Vt[((size_t)(b * NKV + kvh) * HD + d) * S_ + s0 + sl] = __float2half(t[sl][d]);
    }
}

// ---------------------------------------------------------------------------
// Flash attention fp16: load-balanced q-block pairs {15-p, p}, 8 warps,
// 3-stage K/V ring w/ ONE sync per tile, ex2.f16x2 softmax, ones-MMA row sums.
// Q is pre-scaled by 0.125*log2(e) so scores are ready for exp2.
// ---------------------------------------------------------------------------
#define AQ_OFF  0                                  // 128 x 144 = 18432
#define AST_OFF 18432                              // 3 stages x (K 9216 + V 9216)
#define AOK_OFF (AST_OFF + 3 * 18432)              // 32 tile-ok flags
#define AAM_OFF (AOK_OFF + 128)                    // mask 8192
#define ATTN_SMEM (AAM_OFF + S_ * 4)

__global__ __launch_bounds__(256, 2) void attn_mma_kernel(
    const int* __restrict__ amask, __half* __restrict__ atout)
{
    extern __shared__ char sm[];
    const uint32_t sb = smem_u32(sm);
    int* am  = reinterpret_cast<int*>(sm + AAM_OFF);
    int* amok = reinterpret_cast<int*>(sm + AOK_OFF);

    const int tid = threadIdx.x, lane = tid & 31, w = tid >> 5;
    const int pr = blockIdx.x, h = blockIdx.y, b = blockIdx.z;
    const int kvh = h >> 2;
    const uint32_t ONES = 0x3C003C00u;

    // mask + per-tile all-valid flags
    #pragma unroll
    for (int it = 0; it < 8; ++it)
        am[it * 256 + tid] = amask[b * S_ + it * 256 + tid];
    __syncthreads();
    if (tid < 32) {
        int ok = 1;
        for (int j = 0; j < 64; ++j) ok &= (am[tid * 64 + j] != 0);
        amok[tid] = ok;
    }

    auto prefetch_kv = [&](int kt, int st) {
        const int k0 = kt * 64;
        const uint32_t base = sb + AST_OFF + (uint32_t)st * 18432u;
        const __half* kp = g_K + (size_t)(b * S_ + k0) * (NKV * HD) + kvh * HD;
        const __half* vp = g_Vt + ((size_t)(b * NKV + kvh) * HD) * S_ + k0;
        #pragma unroll
        for (int it = 0; it < 4; ++it) {
            int i = it * 256 + tid;
            int mat = i >> 9;
            int row = (i >> 3) & 63;
            int seg = i & 7;
            uint32_t dst = base + (uint32_t)mat * 9216u + (uint32_t)(row * 144 + seg * 16);
            const __half* p = mat ? (vp + (size_t)row * S_) : (kp + (size_t)row * (NKV * HD));
            CP_A16(dst, p + seg * 8);
        }
    };

    for (int half = 0; half < 2; ++half) {
        const int qb = half ? pr : (15 - pr);      // long block first
        const int q0 = qb * 128;
        const int nkt = 2 * qb + 2;                // >= 2

        // Q tile cp.async (group shared with kv0)
        {
            const __half* qp = g_Q + (size_t)(b * S_ + q0) * HID + h * HD;
            #pragma unroll
            for (int it = 0; it < 4; ++it) {
                int i = it * 256 + tid;
                int row = i >> 3, seg = i & 7;
                CP_A16(sb + AQ_OFF + (uint32_t)(row * 144 + seg * 16),
                       qp + (size_t)row * HID + seg * 8);
            }
        }
        prefetch_kv(0, 0); CP_COMMIT();            // group0 = Q + kv0
        prefetch_kv(1, 1); CP_COMMIT();            // group1 = kv1 (nkt >= 2 always)

        CP_WAIT1();                                // Q + kv0 ready
        __syncthreads();

        // preload Q fragments
        uint32_t qf[4][4];
        {
            uint32_t rb = sb + AQ_OFF + (uint32_t)(w * 16 + (lane & 15)) * 144;
            #pragma unroll
            for (int ks = 0; ks < 4; ++ks)
                LDSM_X4(qf[ks][0], qf[ks][1], qf[ks][2], qf[ks][3],
                        rb + (uint32_t)(ks * 32 + ((lane >> 4) << 4)));
        }

        float acc[8][4];
        #pragma unroll
        for (int nt = 0; nt < 8; ++nt)
            #pragma unroll
            for (int c = 0; c < 4; ++c) acc[nt][c] = 0.f;
        float m0 = -1e30f, m1 = -1e30f, l0 = 0.f, l1 = 0.f;
        const int row0g = q0 + w * 16 + (lane >> 2);
        const int row1g = row0g + 8;

        int stc = 0;
        for (int kt = 0; kt < nkt; ++kt) {
            if (kt > 0) {
                if (kt + 1 < nkt) CP_WAIT1(); else CP_WAIT0();
                __syncthreads();
            }
            if (kt + 2 < nkt) { prefetch_kv(kt + 2, (stc + 2) % 3); CP_COMMIT(); }

            const int k0 = kt * 64;
            const uint32_t stage = sb + AST_OFF + (uint32_t)stc * 18432u;

            // ---- S = Q K^T (pre-scaled) ----
            float s[8][4];
            #pragma unroll
            for (int nt = 0; nt < 8; ++nt)
                #pragma unroll
                for (int c = 0; c < 4; ++c) s[nt][c] = 0.f;

            #pragma unroll
            for (int ks = 0; ks < 4; ++ks) {
                const uint32_t coff = (uint32_t)(ks * 32 + ((lane >> 4) << 4));
                uint32_t kf[4][4];
                #pragma unroll
                for (int g = 0; g < 4; ++g)
                    LDSM_X4(kf[g][0], kf[g][1], kf[g][2], kf[g][3],
                            stage + (uint32_t)(g * 16 + (lane & 15)) * 144 + coff);
                #pragma unroll
                for (int g = 0; g < 4; ++g)
                    #pragma unroll
                    for (int p = 0; p < 2; ++p)
                        mma_f16(s[g * 2 + p], qf[ks], kf[g][p], kf[g][p + 2]);
            }

            // ---- masking (skipped on fully-causal, fully-valid tiles) ----
            const bool fast = (k0 + 63 <= q0 + w * 16) && amok[k0 >> 6];
            if (!fast) {
                #pragma unroll
                for (int nt = 0; nt < 8; ++nt) {
                    int cl = nt * 8 + (lane & 3) * 2;
                    int cg0 = k0 + cl, cg1 = cg0 + 1;
                    bool ok0 = am[cg0] != 0, ok1 = am[cg1] != 0;
                    if (!(ok0 && cg0 <= row0g)) s[nt][0] = -1e30f;
                    if (!(ok1 && cg1 <= row0g)) s[nt][1] = -1e30f;
                    if (!(ok0 && cg0 <= row1g)) s[nt][2] = -1e30f;
                    if (!(ok1 && cg1 <= row1g)) s[nt][3] = -1e30f;
                }
            }

            // ---- online softmax (log2 domain) ----
            float mt0 = -1e30f, mt1 = -1e30f;
            #pragma unroll
            for (int nt = 0; nt < 8; ++nt) {
                mt0 = fmaxf(mt0, fmaxf(s[nt][0], s[nt][1]));
                mt1 = fmaxf(mt1, fmaxf(s[nt][2], s[nt][3]));
            }
            mt0 = fmaxf(mt0, __shfl_xor_sync(0xffffffffu, mt0, 1));
            mt0 = fmaxf(mt0, __shfl_xor_sync(0xffffffffu, mt0, 2));
            mt1 = fmaxf(mt1, __shfl_xor_sync(0xffffffffu, mt1, 1));
            mt1 = fmaxf(mt1, __shfl_xor_sync(0xffffffffu, mt1, 2));

            float mn0 = fmaxf(m0, mt0), mn1 = fmaxf(m1, mt1);
            float corr0 = fexp2(m0 - mn0), corr1 = fexp2(m1 - mn1);

            // P = exp2(s - mn) directly in packed fp16
            uint32_t pa[4][4];
            #pragma unroll
            for (int nt = 0; nt < 8; ++nt) {
                int t = nt >> 1, q = nt & 1;
                pa[t][q * 2 + 0] = hexp2x2(pack2h(s[nt][0] - mn0, s[nt][1] - mn0));
                pa[t][q * 2 + 1] = hexp2x2(pack2h(s[nt][2] - mn1, s[nt][3] - mn1));
            }
            // row sums via ones-matrix MMA (fp32, no shuffles)
            float sum4[4] = {0.f, 0.f, 0.f, 0.f};
            #pragma unroll
            for (int ks = 0; ks < 4; ++ks)
                mma_f16(sum4, pa[ks], ONES, ONES);

            l0 = l0 * corr0 + sum4[0];
            l1 = l1 * corr1 + sum4[2];
            m0 = mn0; m1 = mn1;
            #pragma unroll
            for (int nt = 0; nt < 8; ++nt) {
                acc[nt][0] *= corr0; acc[nt][1] *= corr0;
                acc[nt][2] *= corr1; acc[nt][3] *= corr1;
            }

            // ---- O += P V ----
            const uint32_t vstage = stage + 9216u;
            #pragma unroll
            for (int ks = 0; ks < 4; ++ks) {
                const uint32_t coff = (uint32_t)(ks * 32 + ((lane >> 4) << 4));
                uint32_t vf[4][4];
                #pragma unroll
                for (int g = 0; g < 4; ++g)
                    LDSM_X4(vf[g][0], vf[g][1], vf[g][2], vf[g][3],
                            vstage + (uint32_t)(g * 16 + (lane & 15)) * 144 + coff);
                #pragma unroll
                for (int g = 0; g < 4; ++g)
                    #pragma unroll
                    for (int p = 0; p < 2; ++p)
                        mma_f16(acc[g * 2 + p], pa[ks], vf[g][p], vf[g][p + 2]);
            }

            stc = (stc == 2) ? 0 : stc + 1;
        }

        // ---- epilogue: fp16 out ----
        float inv0 = 1.f / l0, inv1 = 1.f / l1;
        size_t r0o = (size_t)(b * S_ + row0g) * HID + h * HD;
        size_t r1o = r0o + (size_t)8 * HID;
        uint32_t* o = reinterpret_cast<uint32_t*>(atout);
        #pragma unroll
        for (int nt = 0; nt < 8; ++nt) {
            int d = nt * 8 + (lane & 3) * 2;
            o[(r0o + d) >> 1] = pack2h(acc[nt][0] * inv0, acc[nt][1] * inv0);
            o[(r1o + d) >> 1] = pack2h(acc[nt][2] * inv1, acc[nt][3] * inv1);
        }
        __syncthreads();   // drain before Q/stage reuse in next half
    }
}

// ---------------------------------------------------------------------------
// kernel_launch
// ---------------------------------------------------------------------------
extern "C" void kernel_launch(void* const* d_in, const int* in_sizes, int n_in,
                              void* d_out, int out_size)
{
    const float* hs    = (const float*)d_in[0];
    const int*   amask = (const int*)  d_in[1];
    const float* Wq    = (const float*)d_in[2];
    const float* bq    = (const float*)d_in[3];
    const float* Wk    = (const float*)d_in[4];
    const float* bk    = (const float*)d_in[5];
    const float* Wv    = (const float*)d_in[6];
    const float* bv    = (const float*)d_in[7];
    const float* Wo    = (const float*)d_in[8];
    const float* bo    = (const float*)d_in[9];
    float* out = (float*)d_out;

    float *qkvp, *biasp;
    cudaGetSymbolAddress((void**)&qkvp, g_qkv);
    cudaGetSymbolAddress((void**)&biasp, g_bias);
    __half *hsp, *atp, *wcp, *wop;
    cudaGetSymbolAddress((void**)&hsp, g_hs);
    cudaGetSymbolAddress((void**)&atp, g_at);
    cudaGetSymbolAddress((void**)&wcp, g_Wc);
    cudaGetSymbolAddress((void**)&wop, g_Wo);

    cudaFuncSetAttribute(gemm_mma_kernel<0>,
                         cudaFuncAttributeMaxDynamicSharedMemorySize, GEMM_SMEM);
    cudaFuncSetAttribute(gemm_mma_kernel<1>,
                         cudaFuncAttributeMaxDynamicSharedMemorySize, GEMM_SMEM);
    cudaFuncSetAttribute(attn_mma_kernel,
                         cudaFuncAttributeMaxDynamicSharedMemorySize, ATTN_SMEM);

    const int M = B_ * S_;
    const int nhs = M * HID;

    prep_weights_kernel<<<dim3(32, 32, 4), dim3(32, 8)>>>(Wq, Wk, Wv, Wo);
    cvt_kernel<<<(nhs / 2 + 255) / 256, 256>>>(hs, hsp, nhs);
    rope_table_kernel<<<(S_ * 32 + 255) / 256, 256>>>(bq, bk, bv);

    // fused QKV projection + RoPE + fp16 (Q pre-scaled) / fp32 V
    gemm_mma_kernel<1><<<dim3(NCAT / 128, M / 128), 256, GEMM_SMEM>>>(
        hsp, wcp, biasp, qkvp, NCAT, HID);

    // V transpose -> fp16
    v_transpose_kernel<<<dim3(S_ / 64, NKV, B_), 256>>>();

    // attention (profiled launch)
    attn_mma_kernel<<<dim3(8, NH, B_), 256, ATTN_SMEM>>>(amask, atp);

    // output projection
    gemm_mma_kernel<0><<<dim3(HID / 128, M / 128), 256, GEMM_SMEM>>>(
        atp, wop, bo, out, HID, HID);
}

// round 13
// speedup vs baseline: 8.2981x; 1.0355x over previous
#include <cuda_runtime.h>
#include <cuda_fp16.h>
#include <cstdint>
#include <math.h>

#define B_    2
#define S_    2048
#define HID   1024
#define NH    16
#define NKV   4
#define HD    64
#define NCAT  1536            // 1024 (Q) + 256 (K) + 256 (V)

// ---------------------------------------------------------------------------
// Scratch (device globals)
// ---------------------------------------------------------------------------
__device__ float g_cos[S_ * 32];
__device__ float g_sin[S_ * 32];
__device__ float g_bias[NCAT];

__device__ __half g_hs[(size_t)B_ * S_ * HID];
__device__ __half g_at[(size_t)B_ * S_ * HID];
__device__ __half g_Wc[NCAT * HID];                  // [1536,1024] K-major rows
__device__ __half g_Wo[HID * HID];
__device__ __half g_Q[(size_t)B_ * S_ * HID];        // post-rope Q fp16 (pre-scaled)
__device__ __half g_K[(size_t)B_ * S_ * NKV * HD];   // post-rope K fp16
__device__ __half g_Vt[(size_t)B_ * NKV * HD * S_];  // [b,kvh,d,s] fp16

// ---------------------------------------------------------------------------
// helpers
// ---------------------------------------------------------------------------
__device__ __forceinline__ uint32_t smem_u32(const void* p) {
    uint32_t a;
    asm("{ .reg .u64 t; cvta.to.shared.u64 t, %1; cvt.u32.u64 %0, t; }" : "=r"(a) : "l"(p));
    return a;
}
#define LDSM_X4(r0, r1, r2, r3, addr) \
    asm volatile("ldmatrix.sync.aligned.m8n8.x4.shared.b16 {%0,%1,%2,%3}, [%4];" \
        : "=r"(r0), "=r"(r1), "=r"(r2), "=r"(r3) : "r"(addr))
#define CP_A16(dst, src) \
    asm volatile("cp.async.cg.shared.global [%0], [%1], 16;" :: "r"(dst), "l"(src))
#define CP_COMMIT() asm volatile("cp.async.commit_group;" ::: "memory")
#define CP_WAIT0()  asm volatile("cp.async.wait_group 0;" ::: "memory")
#define CP_WAIT1()  asm volatile("cp.async.wait_group 1;" ::: "memory")

__device__ __forceinline__ void mma_f16(float* d, const uint32_t* a,
                                        uint32_t b0, uint32_t b1) {
    asm volatile(
        "mma.sync.aligned.m16n8k16.row.col.f32.f16.f16.f32 "
        "{%0,%1,%2,%3}, {%4,%5,%6,%7}, {%8,%9}, {%0,%1,%2,%3};"
        : "+f"(d[0]), "+f"(d[1]), "+f"(d[2]), "+f"(d[3])
        : "r"(a[0]), "r"(a[1]), "r"(a[2]), "r"(a[3]), "r"(b0), "r"(b1));
}
__device__ __forceinline__ uint32_t pack2h(float x, float y) {
    __half2 h = __floats2half2_rn(x, y);
    return *reinterpret_cast<uint32_t*>(&h);
}
__device__ __forceinline__ float fexp2(float x) {
    float y;
    asm("ex2.approx.f32 %0, %1;" : "=f"(y) : "f"(x));
    return y;
}
__device__ __forceinline__ uint32_t hexp2x2(uint32_t x) {
    uint32_t y;
    asm("ex2.approx.f16x2 %0, %1;" : "=r"(y) : "r"(x));
    return y;
}

// ---------------------------------------------------------------------------
// Prep: z=0..3 weight transpose to [N,K] fp16; z=4 rope table + bias concat.
// ---------------------------------------------------------------------------
__global__ void prep_kernel(const float* __restrict__ Wq,
                            const float* __restrict__ Wk,
                            const float* __restrict__ Wv,
                            const float* __restrict__ Wo,
                            const float* __restrict__ bq,
                            const float* __restrict__ bk,
                            const float* __restrict__ bv) {
    int z = blockIdx.z;
    int tid = threadIdx.y * 32 + threadIdx.x;
    if (z == 4) {
        int idx = (blockIdx.y * 32 + blockIdx.x) * 256 + tid;   // 0..262143
        if (idx < NCAT)
            g_bias[idx] = (idx < 1024) ? bq[idx] : (idx < 1280) ? bk[idx - 1024] : bv[idx - 1280];
        if (idx >= S_ * 32) return;
        int t = idx >> 5, j = idx & 31;
        double inv = exp2(-(double)j * 0.5190512648261507);
        float ang = (float)((double)t * inv);
        float s, c;
        sincosf(ang, &s, &c);
        g_cos[idx] = c;
        g_sin[idx] = s;
        return;
    }

    __shared__ float t[32][33];
    const float* W;
    __half* dst;
    int N, rowoff;
    if (z == 0)      { W = Wq; N = HID; rowoff = 0;    dst = g_Wc; }
    else if (z == 1) { W = Wk; N = 256; rowoff = 1024; dst = g_Wc; }
    else if (z == 2) { W = Wv; N = 256; rowoff = 1280; dst = g_Wc; }
    else             { W = Wo; N = HID; rowoff = 0;    dst = g_Wo; }

    int n0 = blockIdx.x * 32, k0 = blockIdx.y * 32;
    if (n0 >= N) return;
    int x = threadIdx.x, y = threadIdx.y;
    #pragma unroll
    for (int yy = y; yy < 32; yy += 8)
        t[yy][x] = W[(size_t)(k0 + yy) * N + n0 + x];
    __syncthreads();
    #pragma unroll
    for (int yy = y; yy < 32; yy += 8)
        dst[(size_t)(rowoff + n0 + yy) * HID + k0 + x] = __float2half(t[x][yy]);
}

__global__ void cvt_kernel(const float* __restrict__ in, __half* __restrict__ o, int n) {
    int i = (blockIdx.x * blockDim.x + threadIdx.x) * 2;
    if (i >= n) return;
    float2 v = *reinterpret_cast<const float2*>(in + i);
    *reinterpret_cast<uint32_t*>(o + i) = pack2h(v.x, v.y);
}

// ---------------------------------------------------------------------------
// GEMM fp16 mma.sync: BK=64 chunks, 3-stage ring, ONE sync per chunk.
// MODE 0: fp32 C + bias. MODE 1: fused RoPE (Q pre-scaled) + V transpose.
// ---------------------------------------------------------------------------
#define GEMM_SMEM (3 * 32768)

template <int MODE>
__global__ __launch_bounds__(256, 2) void gemm_mma_kernel(
    const __half* __restrict__ Ap, const __half* __restrict__ Wp,
    const float* __restrict__ bias, float* __restrict__ C, int ldc, int K)
{
    extern __shared__ char smx[];
    const int tid = threadIdx.x, lane = tid & 31, wid = tid >> 5;
    const int wm = wid & 1, wn = wid >> 1;
    const int m0 = blockIdx.y * 128, n0 = blockIdx.x * 128;
    const uint32_t sbase = smem_u32(smx);

    float acc[4][4][4];
    #pragma unroll
    for (int a = 0; a < 4; a++)
        #pragma unroll
        for (int bb = 0; bb < 4; bb++)
            #pragma unroll
            for (int c = 0; c < 4; c++) acc[a][bb][c] = 0.f;

    auto load_stage = [&](int ch, int st) {
        const uint32_t base = sbase + (uint32_t)st * 32768u;
        const int k0 = ch * 64;
        #pragma unroll
        for (int it = 0; it < 8; ++it) {
            int i = it * 256 + tid;
            int mat = i >> 10;
            int row = (i >> 3) & 127;
            int seg = i & 7;
            uint32_t dst = base + (uint32_t)mat * 16384u
                         + (uint32_t)(row * 128 + (((seg ^ (row & 7))) << 4));
            const __half* p = mat ? (Wp + (size_t)(n0 + row) * K)
                                  : (Ap + (size_t)(m0 + row) * K);
            CP_A16(dst, p + k0 + seg * 8);
        }
    };

    const int NCH = K / 64;
    load_stage(0, 0); CP_COMMIT();
    if (NCH > 1) { load_stage(1, 1); CP_COMMIT(); }

    int stc = 0;
    for (int ch = 0; ch < NCH; ++ch) {
        if (ch + 1 < NCH) CP_WAIT1(); else CP_WAIT0();
        __syncthreads();

        const uint32_t sA = sbase + (uint32_t)stc * 32768u;
        const uint32_t sW = sA + 16384u;

        #pragma unroll
        for (int ks = 0; ks < 4; ++ks) {
            const int colh = ks * 2 + (lane >> 4);
            uint32_t a[4][4], bfr[2][4];
            #pragma unroll
            for (int mi = 0; mi < 4; ++mi) {
                int row = wm * 64 + mi * 16 + (lane & 15);
                LDSM_X4(a[mi][0], a[mi][1], a[mi][2], a[mi][3],
                        sA + (uint32_t)(row * 128 + ((colh ^ (row & 7)) << 4)));
            }
            #pragma unroll
            for (int g = 0; g < 2; ++g) {
                int row = wn * 32 + g * 16 + (lane & 15);
                LDSM_X4(bfr[g][0], bfr[g][1], bfr[g][2], bfr[g][3],
                        sW + (uint32_t)(row * 128 + ((colh ^ (row & 7)) << 4)));
            }
            #pragma unroll
            for (int mi = 0; mi < 4; ++mi) {
                #pragma unroll
                for (int j = 0; j < 4; ++j) {
                    const int g = j >> 1, p = j & 1;
                    mma_f16(acc[mi][j], a[mi], bfr[g][p], bfr[g][p + 2]);
                }
            }
            // issue next-stage loads after the first ks group's work is queued
            if (ks == 0 && ch + 2 < NCH) { load_stage(ch + 2, (stc + 2) % 3); CP_COMMIT(); }
        }
        stc = (stc == 2) ? 0 : stc + 1;
    }

    // epilogue
    const float SC2 = 0.125f * 1.44269504f;    // folded into Q only
    #pragma unroll
    for (int mi = 0; mi < 4; ++mi) {
        const int r = m0 + wm * 64 + mi * 16 + (lane >> 2);
        #pragma unroll
        for (int j = 0; j < 4; ++j) {
            const int col = n0 + wn * 32 + j * 8 + (lane & 3) * 2;
            const float b0 = bias[col], b1 = bias[col + 1];
            float x0 = acc[mi][j][0] + b0, x1 = acc[mi][j][1] + b1;
            float x2 = acc[mi][j][2] + b0, x3 = acc[mi][j][3] + b1;
            if (MODE == 0) {
                *reinterpret_cast<float2*>(C + (size_t)r * ldc + col) = make_float2(x0, x1);
                *reinterpret_cast<float2*>(C + (size_t)(r + 8) * ldc + col) = make_float2(x2, x3);
            } else {
                if (col < 1280) {
                    const int pos0 = r & (S_ - 1), pos1 = (r + 8) & (S_ - 1);
                    const int j0 = col & 31;
                    float2 cc0 = *reinterpret_cast<const float2*>(&g_cos[pos0 * 32 + j0]);
                    float2 ss0 = *reinterpret_cast<const float2*>(&g_sin[pos0 * 32 + j0]);
                    float2 cc1 = *reinterpret_cast<const float2*>(&g_cos[pos1 * 32 + j0]);
                    float2 ss1 = *reinterpret_cast<const float2*>(&g_sin[pos1 * 32 + j0]);
                    float y0 = x0 * cc0.x - x1 * ss0.x;
                    float y1 = x1 * cc0.y + x0 * ss0.y;
                    float y2 = x2 * cc1.x - x3 * ss1.x;
                    float y3 = x3 * cc1.y + x2 * ss1.y;
                    if (col < 1024) {
                        y0 *= SC2; y1 *= SC2; y2 *= SC2; y3 *= SC2;
                        uint32_t* o = reinterpret_cast<uint32_t*>(g_Q);
                        o[(size_t)r * 512 + (col >> 1)]       = pack2h(y0, y1);
                        o[(size_t)(r + 8) * 512 + (col >> 1)] = pack2h(y2, y3);
                    } else {
                        uint32_t* o = reinterpret_cast<uint32_t*>(g_K);
                        o[(size_t)r * 128 + ((col - 1024) >> 1)]       = pack2h(y0, y1);
                        o[(size_t)(r + 8) * 128 + ((col - 1024) >> 1)] = pack2h(y2, y3);
                    }
                } else {
                    // fused V transpose: fp16 to g_Vt[b][kvh][d][s]
                    const int d = col - 1280;              // even, pair (d, d+1)
                    const int kvh = d >> 6, dd = d & 63;
                    const int bb2 = r >> 11, s = r & (S_ - 1);
                    __half* vt = g_Vt + ((size_t)(bb2 * NKV + kvh) * HD + dd) * S_;
                    vt[s]           = __float2half(x0);
                    vt[S_ + s]      = __float2half(x1);
                    vt[s + 8]       = __float2half(x2);
                    vt[S_ + s + 8]  = __float2half(x3);
                }
            }
        }
    }
}

// ---------------------------------------------------------------------------
// Flash attention fp16: load-balanced q-block pairs {15-p, p}, 8 warps,
// 3-stage K/V ring w/ ONE sync per tile, ex2.f16x2 softmax, ones-MMA row sums.
// ---------------------------------------------------------------------------
#define AQ_OFF  0                                  // 128 x 144 = 18432
#define AST_OFF 18432                              // 3 stages x (K 9216 + V 9216)
#define AOK_OFF (AST_OFF + 3 * 18432)              // 32 tile-ok flags
#define AAM_OFF (AOK_OFF + 128)                    // mask 8192
#define ATTN_SMEM (AAM_OFF + S_ * 4)

__global__ __launch_bounds__(256, 2) void attn_mma_kernel(
    const int* __restrict__ amask, __half* __restrict__ atout)
{
    extern __shared__ char sm[];
    const uint32_t sb = smem_u32(sm);
    int* am  = reinterpret_cast<int*>(sm + AAM_OFF);
    int* amok = reinterpret_cast<int*>(sm + AOK_OFF);

    const int tid = threadIdx.x, lane = tid & 31, w = tid >> 5;
    const int pr = blockIdx.x, h = blockIdx.y, b = blockIdx.z;
    const int kvh = h >> 2;
    const uint32_t ONES = 0x3C003C00u;

    #pragma unroll
    for (int it = 0; it < 8; ++it)
        am[it * 256 + tid] = amask[b * S_ + it * 256 + tid];
    __syncthreads();
    if (tid < 32) {
        int ok = 1;
        for (int j = 0; j < 64; ++j) ok &= (am[tid * 64 + j] != 0);
        amok[tid] = ok;
    }

    auto prefetch_kv = [&](int kt, int st) {
        const int k0 = kt * 64;
        const uint32_t base = sb + AST_OFF + (uint32_t)st * 18432u;
        const __half* kp = g_K + (size_t)(b * S_ + k0) * (NKV * HD) + kvh * HD;
        const __half* vp = g_Vt + ((size_t)(b * NKV + kvh) * HD) * S_ + k0;
        #pragma unroll
        for (int it = 0; it < 4; ++it) {
            int i = it * 256 + tid;
            int mat = i >> 9;
            int row = (i >> 3) & 63;
            int seg = i & 7;
            uint32_t dst = base + (uint32_t)mat * 9216u + (uint32_t)(row * 144 + seg * 16);
            const __half* p = mat ? (vp + (size_t)row * S_) : (kp + (size_t)row * (NKV * HD));
            CP_A16(dst, p + seg * 8);
        }
    };

    for (int half = 0; half < 2; ++half) {
        const int qb = half ? pr : (15 - pr);      // long block first
        const int q0 = qb * 128;
        const int nkt = 2 * qb + 2;                // >= 2

        {
            const __half* qp = g_Q + (size_t)(b * S_ + q0) * HID + h * HD;
            #pragma unroll
            for (int it = 0; it < 4; ++it) {
                int i = it * 256 + tid;
                int row = i >> 3, seg = i & 7;
                CP_A16(sb + AQ_OFF + (uint32_t)(row * 144 + seg * 16),
                       qp + (size_t)row * HID + seg * 8);
            }
        }
        prefetch_kv(0, 0); CP_COMMIT();            // group0 = Q + kv0
        prefetch_kv(1, 1); CP_COMMIT();            // group1 = kv1

        CP_WAIT1();
        __syncthreads();

        uint32_t qf[4][4];
        {
            uint32_t rb = sb + AQ_OFF + (uint32_t)(w * 16 + (lane & 15)) * 144;
            #pragma unroll
            for (int ks = 0; ks < 4; ++ks)
                LDSM_X4(qf[ks][0], qf[ks][1], qf[ks][2], qf[ks][3],
                        rb + (uint32_t)(ks * 32 + ((lane >> 4) << 4)));
        }

        float acc[8][4];
        #pragma unroll
        for (int nt = 0; nt < 8; ++nt)
            #pragma unroll
            for (int c = 0; c < 4; ++c) acc[nt][c] = 0.f;
        float m0 = -1e30f, m1 = -1e30f, l0 = 0.f, l1 = 0.f;
        const int row0g = q0 + w * 16 + (lane >> 2);
        const int row1g = row0g + 8;

        int stc = 0;
        for (int kt = 0; kt < nkt; ++kt) {
            if (kt > 0) {
                if (kt + 1 < nkt) CP_WAIT1(); else CP_WAIT0();
                __syncthreads();
            }
            if (kt + 2 < nkt) { prefetch_kv(kt + 2, (stc + 2) % 3); CP_COMMIT(); }

            const int k0 = kt * 64;
            const uint32_t stage = sb + AST_OFF + (uint32_t)stc * 18432u;

            float s[8][4];
            #pragma unroll
            for (int nt = 0; nt < 8; ++nt)
                #pragma unroll
                for (int c = 0; c < 4; ++c) s[nt][c] = 0.f;

            #pragma unroll
            for (int ks = 0; ks < 4; ++ks) {
                const uint32_t coff = (uint32_t)(ks * 32 + ((lane >> 4) << 4));
                uint32_t kf[4][4];
                #pragma unroll
                for (int g = 0; g < 4; ++g)
                    LDSM_X4(kf[g][0], kf[g][1], kf[g][2], kf[g][3],
                            stage + (uint32_t)(g * 16 + (lane & 15)) * 144 + coff);
                #pragma unroll
                for (int g = 0; g < 4; ++g)
                    #pragma unroll
                    for (int p = 0; p < 2; ++p)
                        mma_f16(s[g * 2 + p], qf[ks], kf[g][p], kf[g][p + 2]);
            }

            const bool fast = (k0 + 63 <= q0 + w * 16) && amok[k0 >> 6];
            if (!fast) {
                #pragma unroll
                for (int nt = 0; nt < 8; ++nt) {
                    int cl = nt * 8 + (lane & 3) * 2;
                    int cg0 = k0 + cl, cg1 = cg0 + 1;
                    bool ok0 = am[cg0] != 0, ok1 = am[cg1] != 0;
                    if (!(ok0 && cg0 <= row0g)) s[nt][0] = -1e30f;
                    if (!(ok1 && cg1 <= row0g)) s[nt][1] = -1e30f;
                    if (!(ok0 && cg0 <= row1g)) s[nt][2] = -1e30f;
                    if (!(ok1 && cg1 <= row1g)) s[nt][3] = -1e30f;
                }
            }

            float mt0 = -1e30f, mt1 = -1e30f;
            #pragma unroll
            for (int nt = 0; nt < 8; ++nt) {
                mt0 = fmaxf(mt0, fmaxf(s[nt][0], s[nt][1]));
                mt1 = fmaxf(mt1, fmaxf(s[nt][2], s[nt][3]));
            }
            mt0 = fmaxf(mt0, __shfl_xor_sync(0xffffffffu, mt0, 1));
            mt0 = fmaxf(mt0, __shfl_xor_sync(0xffffffffu, mt0, 2));
            mt1 = fmaxf(mt1, __shfl_xor_sync(0xffffffffu, mt1, 1));
            mt1 = fmaxf(mt1, __shfl_xor_sync(0xffffffffu, mt1, 2));

            float mn0 = fmaxf(m0, mt0), mn1 = fmaxf(m1, mt1);
            float corr0 = fexp2(m0 - mn0), corr1 = fexp2(m1 - mn1);

            uint32_t pa[4][4];
            #pragma unroll
            for (int nt = 0; nt < 8; ++nt) {
                int t = nt >> 1, q = nt & 1;
                pa[t][q * 2 + 0] = hexp2x2(pack2h(s[nt][0] - mn0, s[nt][1] - mn0));
                pa[t][q * 2 + 1] = hexp2x2(pack2h(s[nt][2] - mn1, s[nt][3] - mn1));
            }
            float sum4[4] = {0.f, 0.f, 0.f, 0.f};
            #pragma unroll
            for (int ks = 0; ks < 4; ++ks)
                mma_f16(sum4, pa[ks], ONES, ONES);

            l0 = l0 * corr0 + sum4[0];
            l1 = l1 * corr1 + sum4[2];
            m0 = mn0; m1 = mn1;
            #pragma unroll
            for (int nt = 0; nt < 8; ++nt) {
                acc[nt][0] *= corr0; acc[nt][1] *= corr0;
                acc[nt][2] *= corr1; acc[nt][3] *= corr1;
            }

            const uint32_t vstage = stage + 9216u;
            #pragma unroll
            for (int ks = 0; ks < 4; ++ks) {
                const uint32_t coff = (uint32_t)(ks * 32 + ((lane >> 4) << 4));
                uint32_t vf[4][4];
                #pragma unroll
                for (int g = 0; g < 4; ++g)
                    LDSM_X4(vf[g][0], vf[g][1], vf[g][2], vf[g][3],
                            vstage + (uint32_t)(g * 16 + (lane & 15)) * 144 + coff);
                #pragma unroll
                for (int g = 0; g < 4; ++g)
                    #pragma unroll
                    for (int p = 0; p < 2; ++p)
                        mma_f16(acc[g * 2 + p], pa[ks], vf[g][p], vf[g][p + 2]);
            }

            stc = (stc == 2) ? 0 : stc + 1;
        }

        float inv0 = 1.f / l0, inv1 = 1.f / l1;
        size_t r0o = (size_t)(b * S_ + row0g) * HID + h * HD;
        size_t r1o = r0o + (size_t)8 * HID;
        uint32_t* o = reinterpret_cast<uint32_t*>(atout);
        #pragma unroll
        for (int nt = 0; nt < 8; ++nt) {
            int d = nt * 8 + (lane & 3) * 2;
            o[(r0o + d) >> 1] = pack2h(acc[nt][0] * inv0, acc[nt][1] * inv0);
            o[(r1o + d) >> 1] = pack2h(acc[nt][2] * inv1, acc[nt][3] * inv1);
        }
        __syncthreads();
    }
}

// ---------------------------------------------------------------------------
// kernel_launch
// ---------------------------------------------------------------------------
extern "C" void kernel_launch(void* const* d_in, const int* in_sizes, int n_in,
                              void* d_out, int out_size)
{
    const float* hs    = (const float*)d_in[0];
    const int*   amask = (const int*)  d_in[1];
    const float* Wq    = (const float*)d_in[2];
    const float* bq    = (const float*)d_in[3];
    const float* Wk    = (const float*)d_in[4];
    const float* bk    = (const float*)d_in[5];
    const float* Wv    = (const float*)d_in[6];
    const float* bv    = (const float*)d_in[7];
    const float* Wo    = (const float*)d_in[8];
    const float* bo    = (const float*)d_in[9];
    float* out = (float*)d_out;

    float* biasp;
    cudaGetSymbolAddress((void**)&biasp, g_bias);
    __half *hsp, *atp, *wcp, *wop;
    cudaGetSymbolAddress((void**)&hsp, g_hs);
    cudaGetSymbolAddress((void**)&atp, g_at);
    cudaGetSymbolAddress((void**)&wcp, g_Wc);
    cudaGetSymbolAddress((void**)&wop, g_Wo);

    cudaFuncSetAttribute(gemm_mma_kernel<0>,
                         cudaFuncAttributeMaxDynamicSharedMemorySize, GEMM_SMEM);
    cudaFuncSetAttribute(gemm_mma_kernel<1>,
                         cudaFuncAttributeMaxDynamicSharedMemorySize, GEMM_SMEM);
    cudaFuncSetAttribute(attn_mma_kernel,
                         cudaFuncAttributeMaxDynamicSharedMemorySize, ATTN_SMEM);

    const int M = B_ * S_;
    const int nhs = M * HID;

    // prep (weights z=0..3, rope table + bias z=4) and hs fp16 conversion
    prep_kernel<<<dim3(32, 32, 5), dim3(32, 8)>>>(Wq, Wk, Wv, Wo, bq, bk, bv);
    cvt_kernel<<<(nhs / 2 + 255) / 256, 256>>>(hs, hsp, nhs);

    // fused QKV projection + RoPE + fp16 Q/K + V transpose (all in epilogue)
    gemm_mma_kernel<1><<<dim3(NCAT / 128, M / 128), 256, GEMM_SMEM>>>(
        hsp, wcp, biasp, nullptr, NCAT, HID);

    // attention
    attn_mma_kernel<<<dim3(8, NH, B_), 256, ATTN_SMEM>>>(amask, atp);

    // output projection
    gemm_mma_kernel<0><<<dim3(HID / 128, M / 128), 256, GEMM_SMEM>>>(
        atp, wop, bo, out, HID, HID);
}